// round 5
// baseline (speedup 1.0000x reference)
#include <cuda_runtime.h>
#include <math.h>
#include <stdint.h>

// Problem constants
#define Bc   2
#define Lc   2048
#define Dc   1024
#define Hc   16
#define HDc  64
#define NT   (Bc*Lc)     // 4096 tokens
#define BHc  (Bc*Hc)     // 32 (batch*heads)

// ---------------- scratch (device globals; no allocation allowed) ----------
__device__ float g_Q [BHc*Lc*HDc];   // [bh][l][hd]
__device__ float g_K [BHc*Lc*HDc];
__device__ float g_V [BHc*Lc*HDc];
__device__ float g_G [(size_t)NT*Dc];   // gate, [token][d]
__device__ float g_AO[(size_t)NT*Dc];   // attn out * gate, [token][d]
__device__ int   g_mask[NT];            // 1 = masked (exclude)

// ---------------- tf32 helpers ---------------------------------------------
__device__ __forceinline__ uint32_t f2tf(float x) {
    uint32_t u;
    asm("cvt.rna.tf32.f32 %0, %1;" : "=r"(u) : "f"(x));
    return u;
}
__device__ __forceinline__ float f2tf_f(float x) {
    return __uint_as_float(f2tf(x));
}
__device__ __forceinline__ void mma_tf32(
    float& d0, float& d1, float& d2, float& d3,
    uint32_t a0, uint32_t a1, uint32_t a2, uint32_t a3,
    uint32_t b0, uint32_t b1)
{
    asm volatile(
        "mma.sync.aligned.m16n8k8.row.col.f32.tf32.tf32.f32 "
        "{%0,%1,%2,%3}, {%4,%5,%6,%7}, {%8,%9}, {%0,%1,%2,%3};\n"
        : "+f"(d0), "+f"(d1), "+f"(d2), "+f"(d3)
        : "r"(a0), "r"(a1), "r"(a2), "r"(a3), "r"(b0), "r"(b1));
}

// ---------------- mask decode (robust to bool8 / int32 / float32) ----------
__global__ void mask_decode_kernel(const unsigned char* __restrict__ raw) {
    __shared__ int cnt[4];
    int tid = threadIdx.x;
    if (tid < 4) cnt[tid] = 0;
    __syncthreads();
    for (int i = tid; i < NT; i += blockDim.x)
        if (raw[i]) atomicAdd(&cnt[i & 3], 1);
    __syncthreads();
    int c0 = cnt[0], c1 = cnt[1], c2 = cnt[2], c3 = cnt[3];
    int mode; // 0 = bool8/int8, 1 = int32, 2 = float32
    if (c0 > 0 && c1 == 0 && c2 == 0 && c3 == 0)       mode = 1;
    else if ((c2 > 0 || c3 > 0) && c0 == 0 && c1 == 0) mode = 2;
    else                                               mode = 0;
    for (int i = tid; i < NT; i += blockDim.x) {
        int v;
        if (mode == 0)      v = (raw[i] != 0);
        else if (mode == 1) v = (((const int*)raw)[i] != 0);
        else                v = (((const float*)raw)[i] != 0.0f);
        g_mask[i] = v;
    }
}

// ---------------- TF32 projection GEMM with fused RoPE ---------------------
// Block tile 128(m) x 64(n) == one full head in n. 8 warps, each 32x32.
// Warp n-columns: {base..base+15, base+32..base+47}, base=(warp&1)*16, so the
// RoPE pair (c, c+32) lives in one thread's accumulators (nt and nt+2).
// z=0: Q+rope  z=1: K+rope  z=2: V  (head layout)   z=3: gate sigmoid
#define GPAD 20

__global__ __launch_bounds__(256) void proj_gemm_tc(
    const float* __restrict__ query, const float* __restrict__ key_in,
    const float* __restrict__ value,
    const float* __restrict__ Wq, const float* __restrict__ bq,
    const float* __restrict__ Wk, const float* __restrict__ bk,
    const float* __restrict__ Wv, const float* __restrict__ bv,
    const float* __restrict__ Wg, const float* __restrict__ bg,
    const float* __restrict__ cosb, const float* __restrict__ sinb)
{
    const int z = blockIdx.z;
    const float* A; const float* W; const float* bias;
    if      (z == 0) { A = query;  W = Wq; bias = bq; }
    else if (z == 1) { A = key_in; W = Wk; bias = bk; }
    else if (z == 2) { A = value;  W = Wv; bias = bv; }
    else             { A = query;  W = Wg; bias = bg; }

    const int m0 = blockIdx.y * 128;
    const int n0 = blockIdx.x * 64;

    __shared__ float As[128 * GPAD];   // [m][k]
    __shared__ float Bs[64  * GPAD];   // [n][k]

    const int tid  = threadIdx.x;
    const int warp = tid >> 5;
    const int lane = tid & 31;
    const int q    = lane >> 2;
    const int tq   = lane & 3;
    const int warpM0 = (warp >> 1) * 32;
    const int colbase = (warp & 1) * 16;

    float acc[2][4][4];
    #pragma unroll
    for (int mt = 0; mt < 2; mt++)
        #pragma unroll
        for (int nt = 0; nt < 4; nt++)
            #pragma unroll
            for (int e = 0; e < 4; e++) acc[mt][nt][e] = 0.f;

    for (int k0 = 0; k0 < Dc; k0 += 16) {
        __syncthreads();
        #pragma unroll
        for (int i = 0; i < 2; i++) {
            int f = tid + i * 256;
            int m = f >> 2, kq = f & 3;
            float4 v = *(const float4*)(A + (size_t)(m0 + m) * Dc + k0 + kq * 4);
            v.x = f2tf_f(v.x); v.y = f2tf_f(v.y); v.z = f2tf_f(v.z); v.w = f2tf_f(v.w);
            *(float4*)&As[m * GPAD + kq * 4] = v;
        }
        {
            int n = tid >> 2, kq = tid & 3;
            float4 v = *(const float4*)(W + (size_t)(n0 + n) * Dc + k0 + kq * 4);
            v.x = f2tf_f(v.x); v.y = f2tf_f(v.y); v.z = f2tf_f(v.z); v.w = f2tf_f(v.w);
            *(float4*)&Bs[n * GPAD + kq * 4] = v;
        }
        __syncthreads();

        #pragma unroll
        for (int ks = 0; ks < 16; ks += 8) {
            uint32_t af[2][4];
            #pragma unroll
            for (int mt = 0; mt < 2; mt++) {
                int r = warpM0 + mt * 16 + q;
                af[mt][0] = __float_as_uint(As[r       * GPAD + ks     + tq]);
                af[mt][1] = __float_as_uint(As[(r + 8) * GPAD + ks     + tq]);
                af[mt][2] = __float_as_uint(As[r       * GPAD + ks + 4 + tq]);
                af[mt][3] = __float_as_uint(As[(r + 8) * GPAD + ks + 4 + tq]);
            }
            #pragma unroll
            for (int nt = 0; nt < 4; nt++) {
                int n = colbase + (nt & 1) * 8 + (nt >> 1) * 32 + q;
                uint32_t b0 = __float_as_uint(Bs[n * GPAD + ks     + tq]);
                uint32_t b1 = __float_as_uint(Bs[n * GPAD + ks + 4 + tq]);
                #pragma unroll
                for (int mt = 0; mt < 2; mt++)
                    mma_tf32(acc[mt][nt][0], acc[mt][nt][1], acc[mt][nt][2], acc[mt][nt][3],
                             af[mt][0], af[mt][1], af[mt][2], af[mt][3], b0, b1);
            }
        }
    }

    // epilogue: bias, optional rope (pairs nt <-> nt+2), scatter
    #pragma unroll
    for (int mt = 0; mt < 2; mt++)
        #pragma unroll
        for (int nt = 0; nt < 2; nt++)
            #pragma unroll
            for (int e = 0; e < 4; e++) {
                int row = m0 + warpM0 + mt * 16 + q + ((e >> 1) ? 8 : 0);
                int cl  = colbase + nt * 8 + tq * 2 + (e & 1);   // 0..31
                int l   = row & (Lc - 1);
                float x1 = acc[mt][nt][e]     + bias[n0 + cl];
                float x2 = acc[mt][nt + 2][e] + bias[n0 + cl + 32];
                float y1 = x1, y2 = x2;
                if (z <= 1) {
                    float c1 = cosb[l * 64 + cl],      s1 = sinb[l * 64 + cl];
                    float c2 = cosb[l * 64 + cl + 32], s2 = sinb[l * 64 + cl + 32];
                    y1 = x1 * c1 - x2 * s1;
                    y2 = x2 * c2 + x1 * s2;
                }
                if (z == 3) {
                    g_G[(size_t)row * Dc + n0 + cl]      = 1.f / (1.f + __expf(-y1));
                    g_G[(size_t)row * Dc + n0 + cl + 32] = 1.f / (1.f + __expf(-y2));
                } else {
                    int b = row >> 11, l2 = row & (Lc - 1);
                    int h = n0 >> 6;
                    size_t base = ((size_t)(b * Hc + h) * Lc + l2) * HDc;
                    if (z == 0)      { g_Q[base + cl] = y1; g_Q[base + cl + 32] = y2; }
                    else if (z == 1) { g_K[base + cl] = y1; g_K[base + cl + 32] = y2; }
                    else             { g_V[base + cl] = y1; g_V[base + cl + 32] = y2; }
                }
            }
}

// ---------------- TF32 flash attention + gate fuse -------------------------
// q-tile 128 rows; 8 warps x 16 q-rows x 64 cols.
// Ks2: K[n][k] at n*80 + (k>>2) + (k&3)*20  (16 contiguous floats per (n,tq))
// Vs2: V[k][n] at n*90 + (k>>2) + (k&3)*24  (LDS.64 pairs per (n,tq,s))
#define KSTR 80
#define VSTR2 90
#define PSTR 68
#define AT_K  0
#define AT_V  (64*KSTR)                    // 5120
#define AT_P  (AT_V + 64*VSTR2)            // 10880
#define AT_MK (AT_P + 128*PSTR)            // 19584
#define ATTN_SMEM ((AT_MK + 64) * 4)       // 78592 bytes

__global__ __launch_bounds__(256, 2) void attn_tc_kernel()
{
    extern __shared__ float sm[];
    float* Ks2 = sm + AT_K;
    float* Vs2 = sm + AT_V;
    float* Ps  = sm + AT_P;
    float* mk  = sm + AT_MK;

    const int qt  = blockIdx.x;        // 0..15
    const int bh  = blockIdx.y;        // 0..31
    const int b   = bh >> 4;
    const int h   = bh & 15;
    const int tid = threadIdx.x;
    const int warp = tid >> 5;
    const int lane = tid & 31;
    const int q    = lane >> 2;
    const int tq   = lane & 3;
    const int warpM0 = warp * 16;

    // ---- prologue: Q fragments straight into registers (loop-invariant) ----
    const float* Qg = g_Q + ((size_t)bh * Lc + qt * 128 + warpM0 + q) * 64;
    uint32_t qf[8][4];
    #pragma unroll
    for (int s = 0; s < 8; s++) {
        qf[s][0] = f2tf(Qg[s * 8 + tq]);
        qf[s][1] = f2tf(Qg[512 + s * 8 + tq]);       // row +8
        qf[s][2] = f2tf(Qg[s * 8 + 4 + tq]);
        qf[s][3] = f2tf(Qg[512 + s * 8 + 4 + tq]);
    }

    float O[8][4];
    #pragma unroll
    for (int nt = 0; nt < 8; nt++)
        #pragma unroll
        for (int e = 0; e < 4; e++) O[nt][e] = 0.f;
    float m0r = -1e30f, m1r = -1e30f, l0r = 0.f, l1r = 0.f;

    const int* maskb = g_mask + b * Lc;
    const int vn = tid >> 2, vt2 = tid & 3;          // V-transpose assignment

    for (int kt = 0; kt < 32; kt++) {
        __syncthreads();
        const float* Kg = g_K + ((size_t)bh * Lc + kt * 64) * 64;
        const float* Vg = g_V + ((size_t)bh * Lc + kt * 64) * 64;

        // K tile -> permuted smem
        #pragma unroll
        for (int it = 0; it < 4; it++) {
            int f = tid + it * 256;
            int n = f >> 4, kq = f & 15;
            float4 v = *(const float4*)(Kg + n * 64 + kq * 4);
            float* dst = &Ks2[n * KSTR + kq];
            dst[0]  = f2tf_f(v.x);
            dst[20] = f2tf_f(v.y);
            dst[40] = f2tf_f(v.z);
            dst[60] = f2tf_f(v.w);
        }
        // V tile -> transposed permuted smem (thread owns dim vn, k-mod vt2)
        {
            float vr[16];
            #pragma unroll
            for (int j = 0; j < 16; j++)
                vr[j] = f2tf_f(Vg[(4 * j + vt2) * 64 + vn]);
            float* dst = &Vs2[vn * VSTR2 + vt2 * 24];
            #pragma unroll
            for (int j = 0; j < 8; j++)
                *(float2*)&dst[2 * j] = make_float2(vr[2 * j], vr[2 * j + 1]);
        }
        if (tid < 64) mk[tid] = maskb[kt * 64 + tid] ? -1e30f : 0.f;
        __syncthreads();

        // ---- S = Q . K^T  (Q frags in regs; K B-frags via LDS.128) ----
        float S[8][4];
        #pragma unroll
        for (int nt = 0; nt < 8; nt++)
            #pragma unroll
            for (int e = 0; e < 4; e++) S[nt][e] = 0.f;
        #pragma unroll
        for (int nt = 0; nt < 8; nt++) {
            const float4* kp = (const float4*)&Ks2[(nt * 8 + q) * KSTR + tq * 20];
            float4 k0 = kp[0], k1 = kp[1], k2 = kp[2], k3 = kp[3];
            mma_tf32(S[nt][0], S[nt][1], S[nt][2], S[nt][3],
                     qf[0][0], qf[0][1], qf[0][2], qf[0][3],
                     __float_as_uint(k0.x), __float_as_uint(k0.y));
            mma_tf32(S[nt][0], S[nt][1], S[nt][2], S[nt][3],
                     qf[1][0], qf[1][1], qf[1][2], qf[1][3],
                     __float_as_uint(k0.z), __float_as_uint(k0.w));
            mma_tf32(S[nt][0], S[nt][1], S[nt][2], S[nt][3],
                     qf[2][0], qf[2][1], qf[2][2], qf[2][3],
                     __float_as_uint(k1.x), __float_as_uint(k1.y));
            mma_tf32(S[nt][0], S[nt][1], S[nt][2], S[nt][3],
                     qf[3][0], qf[3][1], qf[3][2], qf[3][3],
                     __float_as_uint(k1.z), __float_as_uint(k1.w));
            mma_tf32(S[nt][0], S[nt][1], S[nt][2], S[nt][3],
                     qf[4][0], qf[4][1], qf[4][2], qf[4][3],
                     __float_as_uint(k2.x), __float_as_uint(k2.y));
            mma_tf32(S[nt][0], S[nt][1], S[nt][2], S[nt][3],
                     qf[5][0], qf[5][1], qf[5][2], qf[5][3],
                     __float_as_uint(k2.z), __float_as_uint(k2.w));
            mma_tf32(S[nt][0], S[nt][1], S[nt][2], S[nt][3],
                     qf[6][0], qf[6][1], qf[6][2], qf[6][3],
                     __float_as_uint(k3.x), __float_as_uint(k3.y));
            mma_tf32(S[nt][0], S[nt][1], S[nt][2], S[nt][3],
                     qf[7][0], qf[7][1], qf[7][2], qf[7][3],
                     __float_as_uint(k3.z), __float_as_uint(k3.w));
        }

        // ---- scale + mask ----
        #pragma unroll
        for (int nt = 0; nt < 8; nt++) {
            float mq0 = mk[nt * 8 + tq * 2];
            float mq1 = mk[nt * 8 + tq * 2 + 1];
            S[nt][0] = S[nt][0] * 0.125f + mq0;
            S[nt][1] = S[nt][1] * 0.125f + mq1;
            S[nt][2] = S[nt][2] * 0.125f + mq0;
            S[nt][3] = S[nt][3] * 0.125f + mq1;
        }

        // ---- online softmax ----
        float rm0 = -1e30f, rm1 = -1e30f;
        #pragma unroll
        for (int nt = 0; nt < 8; nt++) {
            rm0 = fmaxf(rm0, fmaxf(S[nt][0], S[nt][1]));
            rm1 = fmaxf(rm1, fmaxf(S[nt][2], S[nt][3]));
        }
        rm0 = fmaxf(rm0, __shfl_xor_sync(0xffffffffu, rm0, 1));
        rm0 = fmaxf(rm0, __shfl_xor_sync(0xffffffffu, rm0, 2));
        rm1 = fmaxf(rm1, __shfl_xor_sync(0xffffffffu, rm1, 1));
        rm1 = fmaxf(rm1, __shfl_xor_sync(0xffffffffu, rm1, 2));
        float mn0 = fmaxf(m0r, rm0);
        float mn1 = fmaxf(m1r, rm1);

        float rs0 = 0.f, rs1 = 0.f;
        #pragma unroll
        for (int nt = 0; nt < 8; nt++) {
            float p0 = (S[nt][0] < -1e29f) ? 0.f : __expf(S[nt][0] - mn0);
            float p1 = (S[nt][1] < -1e29f) ? 0.f : __expf(S[nt][1] - mn0);
            float p2 = (S[nt][2] < -1e29f) ? 0.f : __expf(S[nt][2] - mn1);
            float p3 = (S[nt][3] < -1e29f) ? 0.f : __expf(S[nt][3] - mn1);
            S[nt][0] = p0; S[nt][1] = p1; S[nt][2] = p2; S[nt][3] = p3;
            rs0 += p0 + p1; rs1 += p2 + p3;
        }
        rs0 += __shfl_xor_sync(0xffffffffu, rs0, 1);
        rs0 += __shfl_xor_sync(0xffffffffu, rs0, 2);
        rs1 += __shfl_xor_sync(0xffffffffu, rs1, 1);
        rs1 += __shfl_xor_sync(0xffffffffu, rs1, 2);

        float alpha0 = __expf(m0r - mn0);
        float alpha1 = __expf(m1r - mn1);
        l0r = l0r * alpha0 + rs0;  m0r = mn0;
        l1r = l1r * alpha1 + rs1;  m1r = mn1;

        // rescale O, stage P
        {
            int r = warpM0 + q;
            #pragma unroll
            for (int nt = 0; nt < 8; nt++) {
                O[nt][0] *= alpha0; O[nt][1] *= alpha0;
                O[nt][2] *= alpha1; O[nt][3] *= alpha1;
                float2 p01 = make_float2(f2tf_f(S[nt][0]), f2tf_f(S[nt][1]));
                float2 p23 = make_float2(f2tf_f(S[nt][2]), f2tf_f(S[nt][3]));
                *(float2*)&Ps[r       * PSTR + nt * 8 + tq * 2] = p01;
                *(float2*)&Ps[(r + 8) * PSTR + nt * 8 + tq * 2] = p23;
            }
        }
        __syncthreads();

        // ---- O += P . V  (V B-frags via LDS.64 from transposed layout) ----
        #pragma unroll
        for (int s = 0; s < 8; s++) {
            int r = warpM0 + q;
            int ks = s * 8;
            uint32_t a0 = __float_as_uint(Ps[r       * PSTR + ks     + tq]);
            uint32_t a1 = __float_as_uint(Ps[(r + 8) * PSTR + ks     + tq]);
            uint32_t a2 = __float_as_uint(Ps[r       * PSTR + ks + 4 + tq]);
            uint32_t a3 = __float_as_uint(Ps[(r + 8) * PSTR + ks + 4 + tq]);
            #pragma unroll
            for (int nt = 0; nt < 8; nt++) {
                float2 vb = *(const float2*)&Vs2[(nt * 8 + q) * VSTR2 + tq * 24 + 2 * s];
                mma_tf32(O[nt][0], O[nt][1], O[nt][2], O[nt][3],
                         a0, a1, a2, a3,
                         __float_as_uint(vb.x), __float_as_uint(vb.y));
            }
        }
    }

    // ---- epilogue: normalize, gate, store token-major ----
    float inv0 = (l0r > 0.f) ? (1.f / l0r) : 0.f;
    float inv1 = (l1r > 0.f) ? (1.f / l1r) : 0.f;
    int r0 = qt * 128 + warpM0 + q;
    size_t tok0 = (size_t)b * Lc + r0;
    size_t tok1 = tok0 + 8;
    #pragma unroll
    for (int nt = 0; nt < 8; nt++) {
        int n = h * 64 + nt * 8 + tq * 2;
        g_AO[tok0 * Dc + n]     = O[nt][0] * inv0 * g_G[tok0 * Dc + n];
        g_AO[tok0 * Dc + n + 1] = O[nt][1] * inv0 * g_G[tok0 * Dc + n + 1];
        g_AO[tok1 * Dc + n]     = O[nt][2] * inv1 * g_G[tok1 * Dc + n];
        g_AO[tok1 * Dc + n + 1] = O[nt][3] * inv1 * g_G[tok1 * Dc + n + 1];
    }
}

// ---------------- TF32 output projection GEMM ------------------------------
__global__ __launch_bounds__(256) void out_gemm_tc(
    const float* __restrict__ Wo, const float* __restrict__ bo,
    float* __restrict__ out)
{
    const int m0 = blockIdx.y * 128;
    const int n0 = blockIdx.x * 64;

    __shared__ float As[128 * GPAD];
    __shared__ float Bs[64  * GPAD];

    const int tid  = threadIdx.x;
    const int warp = tid >> 5;
    const int lane = tid & 31;
    const int q    = lane >> 2;
    const int tq   = lane & 3;
    const int warpM0 = (warp >> 1) * 32;
    const int warpN0 = (warp & 1) * 32;

    float acc[2][4][4];
    #pragma unroll
    for (int mt = 0; mt < 2; mt++)
        #pragma unroll
        for (int nt = 0; nt < 4; nt++)
            #pragma unroll
            for (int e = 0; e < 4; e++) acc[mt][nt][e] = 0.f;

    for (int k0 = 0; k0 < Dc; k0 += 16) {
        __syncthreads();
        #pragma unroll
        for (int i = 0; i < 2; i++) {
            int f = tid + i * 256;
            int m = f >> 2, kq = f & 3;
            float4 v = *(const float4*)(g_AO + (size_t)(m0 + m) * Dc + k0 + kq * 4);
            v.x = f2tf_f(v.x); v.y = f2tf_f(v.y); v.z = f2tf_f(v.z); v.w = f2tf_f(v.w);
            *(float4*)&As[m * GPAD + kq * 4] = v;
        }
        {
            int n = tid >> 2, kq = tid & 3;
            float4 v = *(const float4*)(Wo + (size_t)(n0 + n) * Dc + k0 + kq * 4);
            v.x = f2tf_f(v.x); v.y = f2tf_f(v.y); v.z = f2tf_f(v.z); v.w = f2tf_f(v.w);
            *(float4*)&Bs[n * GPAD + kq * 4] = v;
        }
        __syncthreads();

        #pragma unroll
        for (int ks = 0; ks < 16; ks += 8) {
            uint32_t af[2][4];
            #pragma unroll
            for (int mt = 0; mt < 2; mt++) {
                int r = warpM0 + mt * 16 + q;
                af[mt][0] = __float_as_uint(As[r       * GPAD + ks     + tq]);
                af[mt][1] = __float_as_uint(As[(r + 8) * GPAD + ks     + tq]);
                af[mt][2] = __float_as_uint(As[r       * GPAD + ks + 4 + tq]);
                af[mt][3] = __float_as_uint(As[(r + 8) * GPAD + ks + 4 + tq]);
            }
            #pragma unroll
            for (int nt = 0; nt < 4; nt++) {
                int n = warpN0 + nt * 8 + q;
                uint32_t b0 = __float_as_uint(Bs[n * GPAD + ks     + tq]);
                uint32_t b1 = __float_as_uint(Bs[n * GPAD + ks + 4 + tq]);
                #pragma unroll
                for (int mt = 0; mt < 2; mt++)
                    mma_tf32(acc[mt][nt][0], acc[mt][nt][1], acc[mt][nt][2], acc[mt][nt][3],
                             af[mt][0], af[mt][1], af[mt][2], af[mt][3], b0, b1);
            }
        }
    }

    #pragma unroll
    for (int mt = 0; mt < 2; mt++)
        #pragma unroll
        for (int nt = 0; nt < 4; nt++)
            #pragma unroll
            for (int e = 0; e < 4; e++) {
                int row = m0 + warpM0 + mt * 16 + q + ((e >> 1) ? 8 : 0);
                int col = n0 + warpN0 + nt * 8 + tq * 2 + (e & 1);
                out[(size_t)row * Dc + col] = acc[mt][nt][e] + bo[col];
            }
}

// ---------------- launch ----------------------------------------------------
extern "C" void kernel_launch(void* const* d_in, const int* in_sizes, int n_in,
                              void* d_out, int out_size)
{
    const float* query   = (const float*)d_in[0];
    const float* key_in  = (const float*)d_in[1];
    const float* value   = (const float*)d_in[2];
    const unsigned char* maskraw = (const unsigned char*)d_in[3];
    const float* rope_cos = (const float*)d_in[4];
    const float* rope_sin = (const float*)d_in[5];
    const float* Wq = (const float*)d_in[6];
    const float* bq = (const float*)d_in[7];
    const float* Wk = (const float*)d_in[8];
    const float* bk = (const float*)d_in[9];
    const float* Wv = (const float*)d_in[10];
    const float* bv = (const float*)d_in[11];
    const float* Wg = (const float*)d_in[12];
    const float* bg = (const float*)d_in[13];
    const float* Wo = (const float*)d_in[14];
    const float* bo = (const float*)d_in[15];
    float* out = (float*)d_out;

    (void)in_sizes; (void)n_in; (void)out_size;

    mask_decode_kernel<<<1, 1024>>>(maskraw);

    dim3 pg(Dc / 64, NT / 128, 4);         // (16, 32, 4)
    proj_gemm_tc<<<pg, 256>>>(query, key_in, value,
                              Wq, bq, Wk, bk, Wv, bv, Wg, bg,
                              rope_cos, rope_sin);

    cudaFuncSetAttribute(attn_tc_kernel,
                         cudaFuncAttributeMaxDynamicSharedMemorySize, ATTN_SMEM);
    attn_tc_kernel<<<dim3(Lc / 128, BHc), 256, ATTN_SMEM>>>();

    out_gemm_tc<<<dim3(Dc / 64, NT / 128), 256>>>(Wo, bo, out);
}

// round 6
// speedup vs baseline: 1.1300x; 1.1300x over previous
#include <cuda_runtime.h>
#include <math.h>
#include <stdint.h>

// Problem constants
#define Bc   2
#define Lc   2048
#define Dc   1024
#define Hc   16
#define HDc  64
#define NT   (Bc*Lc)     // 4096 tokens
#define BHc  (Bc*Hc)     // 32 (batch*heads)

// ---------------- scratch (device globals; no allocation allowed) ----------
__device__ float g_Q [BHc*Lc*HDc];   // [bh][l][hd]
__device__ float g_K [BHc*Lc*HDc];
__device__ float g_V [BHc*Lc*HDc];
__device__ float g_G [(size_t)NT*Dc];   // gate, [token][d]
__device__ float g_AO[(size_t)NT*Dc];   // attn out * gate, [token][d]
__device__ int   g_mask[NT];            // 1 = masked (exclude)

// ---------------- tf32 helpers ---------------------------------------------
__device__ __forceinline__ uint32_t f2tf(float x) {
    uint32_t u;
    asm("cvt.rna.tf32.f32 %0, %1;" : "=r"(u) : "f"(x));
    return u;
}
__device__ __forceinline__ float f2tf_f(float x) {
    return __uint_as_float(f2tf(x));
}
__device__ __forceinline__ float4 f2tf4(float4 v) {
    v.x = f2tf_f(v.x); v.y = f2tf_f(v.y); v.z = f2tf_f(v.z); v.w = f2tf_f(v.w);
    return v;
}
__device__ __forceinline__ void mma_tf32(
    float& d0, float& d1, float& d2, float& d3,
    uint32_t a0, uint32_t a1, uint32_t a2, uint32_t a3,
    uint32_t b0, uint32_t b1)
{
    asm volatile(
        "mma.sync.aligned.m16n8k8.row.col.f32.tf32.tf32.f32 "
        "{%0,%1,%2,%3}, {%4,%5,%6,%7}, {%8,%9}, {%0,%1,%2,%3};\n"
        : "+f"(d0), "+f"(d1), "+f"(d2), "+f"(d3)
        : "r"(a0), "r"(a1), "r"(a2), "r"(a3), "r"(b0), "r"(b1));
}

// ---------------- mask decode (robust to bool8 / int32 / float32) ----------
__global__ void mask_decode_kernel(const unsigned char* __restrict__ raw) {
    __shared__ int cnt[4];
    int tid = threadIdx.x;
    if (tid < 4) cnt[tid] = 0;
    __syncthreads();
    for (int i = tid; i < NT; i += blockDim.x)
        if (raw[i]) atomicAdd(&cnt[i & 3], 1);
    __syncthreads();
    int c0 = cnt[0], c1 = cnt[1], c2 = cnt[2], c3 = cnt[3];
    int mode; // 0 = bool8/int8, 1 = int32, 2 = float32
    if (c0 > 0 && c1 == 0 && c2 == 0 && c3 == 0)       mode = 1;
    else if ((c2 > 0 || c3 > 0) && c0 == 0 && c1 == 0) mode = 2;
    else                                               mode = 0;
    for (int i = tid; i < NT; i += blockDim.x) {
        int v;
        if (mode == 0)      v = (raw[i] != 0);
        else if (mode == 1) v = (((const int*)raw)[i] != 0);
        else                v = (((const float*)raw)[i] != 0.0f);
        g_mask[i] = v;
    }
}

// ---------------- TF32 projection GEMM, pipelined, fused RoPE --------------
// Block tile 128(m) x 64(n) == one full head in n. 8 warps, each 32x32.
// k-chunk 32, register-prefetch pipeline: LDG(next) issues before MMA(current).
// Warp n-cols {base..base+15, base+32..base+47} so RoPE pair (c, c+32) stays
// in one thread (nt and nt+2).
#define KC    32
#define GPAD2 36   // [m][k] row stride (floats): 32 + 4 pad, conflict-free

__global__ __launch_bounds__(256) void proj_gemm_tc(
    const float* __restrict__ query, const float* __restrict__ key_in,
    const float* __restrict__ value,
    const float* __restrict__ Wq, const float* __restrict__ bq,
    const float* __restrict__ Wk, const float* __restrict__ bk,
    const float* __restrict__ Wv, const float* __restrict__ bv,
    const float* __restrict__ Wg, const float* __restrict__ bg,
    const float* __restrict__ cosb, const float* __restrict__ sinb)
{
    const int z = blockIdx.z;
    const float* A; const float* W; const float* bias;
    if      (z == 0) { A = query;  W = Wq; bias = bq; }
    else if (z == 1) { A = key_in; W = Wk; bias = bk; }
    else if (z == 2) { A = value;  W = Wv; bias = bv; }
    else             { A = query;  W = Wg; bias = bg; }

    const int m0 = blockIdx.y * 128;
    const int n0 = blockIdx.x * 64;

    __shared__ float As[128 * GPAD2];   // [m][k]
    __shared__ float Bs[64  * GPAD2];   // [n][k]

    const int tid  = threadIdx.x;
    const int warp = tid >> 5;
    const int lane = tid & 31;
    const int q    = lane >> 2;
    const int tq   = lane & 3;
    const int warpM0 = (warp >> 1) * 32;
    const int colbase = (warp & 1) * 16;

    // per-thread tile coords (8 float4 per row of 32 k-floats)
    const int am[4] = { (tid)>>3, (tid+256)>>3, (tid+512)>>3, (tid+768)>>3 };
    const int ak    = (tid & 7) * 4;
    const int bn[2] = { (tid)>>3, (tid+256)>>3 };

    float acc[2][4][4];
    #pragma unroll
    for (int mt = 0; mt < 2; mt++)
        #pragma unroll
        for (int nt = 0; nt < 4; nt++)
            #pragma unroll
            for (int e = 0; e < 4; e++) acc[mt][nt][e] = 0.f;

    // prologue prefetch
    float4 ra[4], rb[2];
    #pragma unroll
    for (int i = 0; i < 4; i++)
        ra[i] = *(const float4*)(A + (size_t)(m0 + am[i]) * Dc + ak);
    #pragma unroll
    for (int i = 0; i < 2; i++)
        rb[i] = *(const float4*)(W + (size_t)(n0 + bn[i]) * Dc + ak);

    for (int k0 = 0; k0 < Dc; k0 += KC) {
        __syncthreads();   // previous MMA done reading smem
        #pragma unroll
        for (int i = 0; i < 4; i++)
            *(float4*)&As[am[i] * GPAD2 + ak] = f2tf4(ra[i]);
        #pragma unroll
        for (int i = 0; i < 2; i++)
            *(float4*)&Bs[bn[i] * GPAD2 + ak] = f2tf4(rb[i]);
        __syncthreads();

        // prefetch next k-chunk; latency hides under the MMA block below
        if (k0 + KC < Dc) {
            #pragma unroll
            for (int i = 0; i < 4; i++)
                ra[i] = *(const float4*)(A + (size_t)(m0 + am[i]) * Dc + k0 + KC + ak);
            #pragma unroll
            for (int i = 0; i < 2; i++)
                rb[i] = *(const float4*)(W + (size_t)(n0 + bn[i]) * Dc + k0 + KC + ak);
        }

        #pragma unroll
        for (int ks = 0; ks < KC; ks += 8) {
            uint32_t af[2][4];
            #pragma unroll
            for (int mt = 0; mt < 2; mt++) {
                int r = warpM0 + mt * 16 + q;
                af[mt][0] = __float_as_uint(As[r       * GPAD2 + ks     + tq]);
                af[mt][1] = __float_as_uint(As[(r + 8) * GPAD2 + ks     + tq]);
                af[mt][2] = __float_as_uint(As[r       * GPAD2 + ks + 4 + tq]);
                af[mt][3] = __float_as_uint(As[(r + 8) * GPAD2 + ks + 4 + tq]);
            }
            #pragma unroll
            for (int nt = 0; nt < 4; nt++) {
                int n = colbase + (nt & 1) * 8 + (nt >> 1) * 32 + q;
                uint32_t b0 = __float_as_uint(Bs[n * GPAD2 + ks     + tq]);
                uint32_t b1 = __float_as_uint(Bs[n * GPAD2 + ks + 4 + tq]);
                #pragma unroll
                for (int mt = 0; mt < 2; mt++)
                    mma_tf32(acc[mt][nt][0], acc[mt][nt][1], acc[mt][nt][2], acc[mt][nt][3],
                             af[mt][0], af[mt][1], af[mt][2], af[mt][3], b0, b1);
            }
        }
    }

    // epilogue: bias, optional rope (pairs nt <-> nt+2), scatter
    #pragma unroll
    for (int mt = 0; mt < 2; mt++)
        #pragma unroll
        for (int nt = 0; nt < 2; nt++)
            #pragma unroll
            for (int e = 0; e < 4; e++) {
                int row = m0 + warpM0 + mt * 16 + q + ((e >> 1) ? 8 : 0);
                int cl  = colbase + nt * 8 + tq * 2 + (e & 1);   // 0..31
                int l   = row & (Lc - 1);
                float x1 = acc[mt][nt][e]     + bias[n0 + cl];
                float x2 = acc[mt][nt + 2][e] + bias[n0 + cl + 32];
                float y1 = x1, y2 = x2;
                if (z <= 1) {
                    float c1 = cosb[l * 64 + cl],      s1 = sinb[l * 64 + cl];
                    float c2 = cosb[l * 64 + cl + 32], s2 = sinb[l * 64 + cl + 32];
                    y1 = x1 * c1 - x2 * s1;
                    y2 = x2 * c2 + x1 * s2;
                }
                if (z == 3) {
                    g_G[(size_t)row * Dc + n0 + cl]      = 1.f / (1.f + __expf(-y1));
                    g_G[(size_t)row * Dc + n0 + cl + 32] = 1.f / (1.f + __expf(-y2));
                } else {
                    int b = row >> 11, l2 = row & (Lc - 1);
                    int h = n0 >> 6;
                    size_t base = ((size_t)(b * Hc + h) * Lc + l2) * HDc;
                    if (z == 0)      { g_Q[base + cl] = y1; g_Q[base + cl + 32] = y2; }
                    else if (z == 1) { g_K[base + cl] = y1; g_K[base + cl + 32] = y2; }
                    else             { g_V[base + cl] = y1; g_V[base + cl + 32] = y2; }
                }
            }
}

// ---------------- TF32 flash attention + gate fuse (unchanged from R5) -----
#define KSTR 80
#define VSTR2 90
#define PSTR 68
#define AT_K  0
#define AT_V  (64*KSTR)                    // 5120
#define AT_P  (AT_V + 64*VSTR2)            // 10880
#define AT_MK (AT_P + 128*PSTR)            // 19584
#define ATTN_SMEM ((AT_MK + 64) * 4)       // 78592 bytes

__global__ __launch_bounds__(256, 2) void attn_tc_kernel()
{
    extern __shared__ float sm[];
    float* Ks2 = sm + AT_K;
    float* Vs2 = sm + AT_V;
    float* Ps  = sm + AT_P;
    float* mk  = sm + AT_MK;

    const int qt  = blockIdx.x;        // 0..15
    const int bh  = blockIdx.y;        // 0..31
    const int b   = bh >> 4;
    const int h   = bh & 15;
    const int tid = threadIdx.x;
    const int warp = tid >> 5;
    const int lane = tid & 31;
    const int q    = lane >> 2;
    const int tq   = lane & 3;
    const int warpM0 = warp * 16;

    const float* Qg = g_Q + ((size_t)bh * Lc + qt * 128 + warpM0 + q) * 64;
    uint32_t qf[8][4];
    #pragma unroll
    for (int s = 0; s < 8; s++) {
        qf[s][0] = f2tf(Qg[s * 8 + tq]);
        qf[s][1] = f2tf(Qg[512 + s * 8 + tq]);
        qf[s][2] = f2tf(Qg[s * 8 + 4 + tq]);
        qf[s][3] = f2tf(Qg[512 + s * 8 + 4 + tq]);
    }

    float O[8][4];
    #pragma unroll
    for (int nt = 0; nt < 8; nt++)
        #pragma unroll
        for (int e = 0; e < 4; e++) O[nt][e] = 0.f;
    float m0r = -1e30f, m1r = -1e30f, l0r = 0.f, l1r = 0.f;

    const int* maskb = g_mask + b * Lc;
    const int vn = tid >> 2, vt2 = tid & 3;

    for (int kt = 0; kt < 32; kt++) {
        __syncthreads();
        const float* Kg = g_K + ((size_t)bh * Lc + kt * 64) * 64;
        const float* Vg = g_V + ((size_t)bh * Lc + kt * 64) * 64;

        #pragma unroll
        for (int it = 0; it < 4; it++) {
            int f = tid + it * 256;
            int n = f >> 4, kq = f & 15;
            float4 v = *(const float4*)(Kg + n * 64 + kq * 4);
            float* dst = &Ks2[n * KSTR + kq];
            dst[0]  = f2tf_f(v.x);
            dst[20] = f2tf_f(v.y);
            dst[40] = f2tf_f(v.z);
            dst[60] = f2tf_f(v.w);
        }
        {
            float vr[16];
            #pragma unroll
            for (int j = 0; j < 16; j++)
                vr[j] = f2tf_f(Vg[(4 * j + vt2) * 64 + vn]);
            float* dst = &Vs2[vn * VSTR2 + vt2 * 24];
            #pragma unroll
            for (int j = 0; j < 8; j++)
                *(float2*)&dst[2 * j] = make_float2(vr[2 * j], vr[2 * j + 1]);
        }
        if (tid < 64) mk[tid] = maskb[kt * 64 + tid] ? -1e30f : 0.f;
        __syncthreads();

        float S[8][4];
        #pragma unroll
        for (int nt = 0; nt < 8; nt++)
            #pragma unroll
            for (int e = 0; e < 4; e++) S[nt][e] = 0.f;
        #pragma unroll
        for (int nt = 0; nt < 8; nt++) {
            const float4* kp = (const float4*)&Ks2[(nt * 8 + q) * KSTR + tq * 20];
            float4 k0 = kp[0], k1 = kp[1], k2 = kp[2], k3 = kp[3];
            mma_tf32(S[nt][0], S[nt][1], S[nt][2], S[nt][3],
                     qf[0][0], qf[0][1], qf[0][2], qf[0][3],
                     __float_as_uint(k0.x), __float_as_uint(k0.y));
            mma_tf32(S[nt][0], S[nt][1], S[nt][2], S[nt][3],
                     qf[1][0], qf[1][1], qf[1][2], qf[1][3],
                     __float_as_uint(k0.z), __float_as_uint(k0.w));
            mma_tf32(S[nt][0], S[nt][1], S[nt][2], S[nt][3],
                     qf[2][0], qf[2][1], qf[2][2], qf[2][3],
                     __float_as_uint(k1.x), __float_as_uint(k1.y));
            mma_tf32(S[nt][0], S[nt][1], S[nt][2], S[nt][3],
                     qf[3][0], qf[3][1], qf[3][2], qf[3][3],
                     __float_as_uint(k1.z), __float_as_uint(k1.w));
            mma_tf32(S[nt][0], S[nt][1], S[nt][2], S[nt][3],
                     qf[4][0], qf[4][1], qf[4][2], qf[4][3],
                     __float_as_uint(k2.x), __float_as_uint(k2.y));
            mma_tf32(S[nt][0], S[nt][1], S[nt][2], S[nt][3],
                     qf[5][0], qf[5][1], qf[5][2], qf[5][3],
                     __float_as_uint(k2.z), __float_as_uint(k2.w));
            mma_tf32(S[nt][0], S[nt][1], S[nt][2], S[nt][3],
                     qf[6][0], qf[6][1], qf[6][2], qf[6][3],
                     __float_as_uint(k3.x), __float_as_uint(k3.y));
            mma_tf32(S[nt][0], S[nt][1], S[nt][2], S[nt][3],
                     qf[7][0], qf[7][1], qf[7][2], qf[7][3],
                     __float_as_uint(k3.z), __float_as_uint(k3.w));
        }

        #pragma unroll
        for (int nt = 0; nt < 8; nt++) {
            float mq0 = mk[nt * 8 + tq * 2];
            float mq1 = mk[nt * 8 + tq * 2 + 1];
            S[nt][0] = S[nt][0] * 0.125f + mq0;
            S[nt][1] = S[nt][1] * 0.125f + mq1;
            S[nt][2] = S[nt][2] * 0.125f + mq0;
            S[nt][3] = S[nt][3] * 0.125f + mq1;
        }

        float rm0 = -1e30f, rm1 = -1e30f;
        #pragma unroll
        for (int nt = 0; nt < 8; nt++) {
            rm0 = fmaxf(rm0, fmaxf(S[nt][0], S[nt][1]));
            rm1 = fmaxf(rm1, fmaxf(S[nt][2], S[nt][3]));
        }
        rm0 = fmaxf(rm0, __shfl_xor_sync(0xffffffffu, rm0, 1));
        rm0 = fmaxf(rm0, __shfl_xor_sync(0xffffffffu, rm0, 2));
        rm1 = fmaxf(rm1, __shfl_xor_sync(0xffffffffu, rm1, 1));
        rm1 = fmaxf(rm1, __shfl_xor_sync(0xffffffffu, rm1, 2));
        float mn0 = fmaxf(m0r, rm0);
        float mn1 = fmaxf(m1r, rm1);

        float rs0 = 0.f, rs1 = 0.f;
        #pragma unroll
        for (int nt = 0; nt < 8; nt++) {
            float p0 = (S[nt][0] < -1e29f) ? 0.f : __expf(S[nt][0] - mn0);
            float p1 = (S[nt][1] < -1e29f) ? 0.f : __expf(S[nt][1] - mn0);
            float p2 = (S[nt][2] < -1e29f) ? 0.f : __expf(S[nt][2] - mn1);
            float p3 = (S[nt][3] < -1e29f) ? 0.f : __expf(S[nt][3] - mn1);
            S[nt][0] = p0; S[nt][1] = p1; S[nt][2] = p2; S[nt][3] = p3;
            rs0 += p0 + p1; rs1 += p2 + p3;
        }
        rs0 += __shfl_xor_sync(0xffffffffu, rs0, 1);
        rs0 += __shfl_xor_sync(0xffffffffu, rs0, 2);
        rs1 += __shfl_xor_sync(0xffffffffu, rs1, 1);
        rs1 += __shfl_xor_sync(0xffffffffu, rs1, 2);

        float alpha0 = __expf(m0r - mn0);
        float alpha1 = __expf(m1r - mn1);
        l0r = l0r * alpha0 + rs0;  m0r = mn0;
        l1r = l1r * alpha1 + rs1;  m1r = mn1;

        {
            int r = warpM0 + q;
            #pragma unroll
            for (int nt = 0; nt < 8; nt++) {
                O[nt][0] *= alpha0; O[nt][1] *= alpha0;
                O[nt][2] *= alpha1; O[nt][3] *= alpha1;
                float2 p01 = make_float2(f2tf_f(S[nt][0]), f2tf_f(S[nt][1]));
                float2 p23 = make_float2(f2tf_f(S[nt][2]), f2tf_f(S[nt][3]));
                *(float2*)&Ps[r       * PSTR + nt * 8 + tq * 2] = p01;
                *(float2*)&Ps[(r + 8) * PSTR + nt * 8 + tq * 2] = p23;
            }
        }
        __syncthreads();

        #pragma unroll
        for (int s = 0; s < 8; s++) {
            int r = warpM0 + q;
            int ks = s * 8;
            uint32_t a0 = __float_as_uint(Ps[r       * PSTR + ks     + tq]);
            uint32_t a1 = __float_as_uint(Ps[(r + 8) * PSTR + ks     + tq]);
            uint32_t a2 = __float_as_uint(Ps[r       * PSTR + ks + 4 + tq]);
            uint32_t a3 = __float_as_uint(Ps[(r + 8) * PSTR + ks + 4 + tq]);
            #pragma unroll
            for (int nt = 0; nt < 8; nt++) {
                float2 vb = *(const float2*)&Vs2[(nt * 8 + q) * VSTR2 + tq * 24 + 2 * s];
                mma_tf32(O[nt][0], O[nt][1], O[nt][2], O[nt][3],
                         a0, a1, a2, a3,
                         __float_as_uint(vb.x), __float_as_uint(vb.y));
            }
        }
    }

    float inv0 = (l0r > 0.f) ? (1.f / l0r) : 0.f;
    float inv1 = (l1r > 0.f) ? (1.f / l1r) : 0.f;
    int r0 = qt * 128 + warpM0 + q;
    size_t tok0 = (size_t)b * Lc + r0;
    size_t tok1 = tok0 + 8;
    #pragma unroll
    for (int nt = 0; nt < 8; nt++) {
        int n = h * 64 + nt * 8 + tq * 2;
        g_AO[tok0 * Dc + n]     = O[nt][0] * inv0 * g_G[tok0 * Dc + n];
        g_AO[tok0 * Dc + n + 1] = O[nt][1] * inv0 * g_G[tok0 * Dc + n + 1];
        g_AO[tok1 * Dc + n]     = O[nt][2] * inv1 * g_G[tok1 * Dc + n];
        g_AO[tok1 * Dc + n + 1] = O[nt][3] * inv1 * g_G[tok1 * Dc + n + 1];
    }
}

// ---------------- TF32 output projection GEMM, pipelined -------------------
__global__ __launch_bounds__(256) void out_gemm_tc(
    const float* __restrict__ Wo, const float* __restrict__ bo,
    float* __restrict__ out)
{
    const int m0 = blockIdx.y * 128;
    const int n0 = blockIdx.x * 64;

    __shared__ float As[128 * GPAD2];
    __shared__ float Bs[64  * GPAD2];

    const int tid  = threadIdx.x;
    const int warp = tid >> 5;
    const int lane = tid & 31;
    const int q    = lane >> 2;
    const int tq   = lane & 3;
    const int warpM0 = (warp >> 1) * 32;
    const int warpN0 = (warp & 1) * 32;

    const int am[4] = { (tid)>>3, (tid+256)>>3, (tid+512)>>3, (tid+768)>>3 };
    const int ak    = (tid & 7) * 4;
    const int bn[2] = { (tid)>>3, (tid+256)>>3 };

    float acc[2][4][4];
    #pragma unroll
    for (int mt = 0; mt < 2; mt++)
        #pragma unroll
        for (int nt = 0; nt < 4; nt++)
            #pragma unroll
            for (int e = 0; e < 4; e++) acc[mt][nt][e] = 0.f;

    float4 ra[4], rb[2];
    #pragma unroll
    for (int i = 0; i < 4; i++)
        ra[i] = *(const float4*)(g_AO + (size_t)(m0 + am[i]) * Dc + ak);
    #pragma unroll
    for (int i = 0; i < 2; i++)
        rb[i] = *(const float4*)(Wo + (size_t)(n0 + bn[i]) * Dc + ak);

    for (int k0 = 0; k0 < Dc; k0 += KC) {
        __syncthreads();
        #pragma unroll
        for (int i = 0; i < 4; i++)
            *(float4*)&As[am[i] * GPAD2 + ak] = f2tf4(ra[i]);
        #pragma unroll
        for (int i = 0; i < 2; i++)
            *(float4*)&Bs[bn[i] * GPAD2 + ak] = f2tf4(rb[i]);
        __syncthreads();

        if (k0 + KC < Dc) {
            #pragma unroll
            for (int i = 0; i < 4; i++)
                ra[i] = *(const float4*)(g_AO + (size_t)(m0 + am[i]) * Dc + k0 + KC + ak);
            #pragma unroll
            for (int i = 0; i < 2; i++)
                rb[i] = *(const float4*)(Wo + (size_t)(n0 + bn[i]) * Dc + k0 + KC + ak);
        }

        #pragma unroll
        for (int ks = 0; ks < KC; ks += 8) {
            uint32_t af[2][4];
            #pragma unroll
            for (int mt = 0; mt < 2; mt++) {
                int r = warpM0 + mt * 16 + q;
                af[mt][0] = __float_as_uint(As[r       * GPAD2 + ks     + tq]);
                af[mt][1] = __float_as_uint(As[(r + 8) * GPAD2 + ks     + tq]);
                af[mt][2] = __float_as_uint(As[r       * GPAD2 + ks + 4 + tq]);
                af[mt][3] = __float_as_uint(As[(r + 8) * GPAD2 + ks + 4 + tq]);
            }
            #pragma unroll
            for (int nt = 0; nt < 4; nt++) {
                int n = warpN0 + nt * 8 + q;
                uint32_t b0 = __float_as_uint(Bs[n * GPAD2 + ks     + tq]);
                uint32_t b1 = __float_as_uint(Bs[n * GPAD2 + ks + 4 + tq]);
                #pragma unroll
                for (int mt = 0; mt < 2; mt++)
                    mma_tf32(acc[mt][nt][0], acc[mt][nt][1], acc[mt][nt][2], acc[mt][nt][3],
                             af[mt][0], af[mt][1], af[mt][2], af[mt][3], b0, b1);
            }
        }
    }

    #pragma unroll
    for (int mt = 0; mt < 2; mt++)
        #pragma unroll
        for (int nt = 0; nt < 4; nt++)
            #pragma unroll
            for (int e = 0; e < 4; e++) {
                int row = m0 + warpM0 + mt * 16 + q + ((e >> 1) ? 8 : 0);
                int col = n0 + warpN0 + nt * 8 + tq * 2 + (e & 1);
                out[(size_t)row * Dc + col] = acc[mt][nt][e] + bo[col];
            }
}

// ---------------- launch ----------------------------------------------------
extern "C" void kernel_launch(void* const* d_in, const int* in_sizes, int n_in,
                              void* d_out, int out_size)
{
    const float* query   = (const float*)d_in[0];
    const float* key_in  = (const float*)d_in[1];
    const float* value   = (const float*)d_in[2];
    const unsigned char* maskraw = (const unsigned char*)d_in[3];
    const float* rope_cos = (const float*)d_in[4];
    const float* rope_sin = (const float*)d_in[5];
    const float* Wq = (const float*)d_in[6];
    const float* bq = (const float*)d_in[7];
    const float* Wk = (const float*)d_in[8];
    const float* bk = (const float*)d_in[9];
    const float* Wv = (const float*)d_in[10];
    const float* bv = (const float*)d_in[11];
    const float* Wg = (const float*)d_in[12];
    const float* bg = (const float*)d_in[13];
    const float* Wo = (const float*)d_in[14];
    const float* bo = (const float*)d_in[15];
    float* out = (float*)d_out;

    (void)in_sizes; (void)n_in; (void)out_size;

    mask_decode_kernel<<<1, 1024>>>(maskraw);

    dim3 pg(Dc / 64, NT / 128, 4);         // (16, 32, 4)
    proj_gemm_tc<<<pg, 256>>>(query, key_in, value,
                              Wq, bq, Wk, bk, Wv, bv, Wg, bg,
                              rope_cos, rope_sin);

    cudaFuncSetAttribute(attn_tc_kernel,
                         cudaFuncAttributeMaxDynamicSharedMemorySize, ATTN_SMEM);
    attn_tc_kernel<<<dim3(Lc / 128, BHc), 256, ATTN_SMEM>>>();

    out_gemm_tc<<<dim3(Dc / 64, NT / 128), 256>>>(Wo, bo, out);
}

// round 7
// speedup vs baseline: 1.1323x; 1.0020x over previous
#include <cuda_runtime.h>
#include <math.h>
#include <stdint.h>

// Problem constants
#define Bc   2
#define Lc   2048
#define Dc   1024
#define Hc   16
#define HDc  64
#define NT   (Bc*Lc)     // 4096 tokens
#define BHc  (Bc*Hc)     // 32 (batch*heads)

// ---------------- scratch (device globals; no allocation allowed) ----------
__device__ float g_Q [BHc*Lc*HDc];   // [bh][l][hd]
__device__ float g_K [BHc*Lc*HDc];
__device__ float g_V [BHc*Lc*HDc];
__device__ float g_G [(size_t)NT*Dc];   // gate, [token][d]
__device__ float g_AO[(size_t)NT*Dc];   // attn out * gate, [token][d]
__device__ int   g_mask[NT];            // 1 = masked (exclude)

// ---------------- tf32 helpers ---------------------------------------------
__device__ __forceinline__ uint32_t f2tf(float x) {
    uint32_t u;
    asm("cvt.rna.tf32.f32 %0, %1;" : "=r"(u) : "f"(x));
    return u;
}
__device__ __forceinline__ float f2tf_f(float x) {
    return __uint_as_float(f2tf(x));
}
__device__ __forceinline__ float4 f2tf4(float4 v) {
    v.x = f2tf_f(v.x); v.y = f2tf_f(v.y); v.z = f2tf_f(v.z); v.w = f2tf_f(v.w);
    return v;
}
__device__ __forceinline__ void mma_tf32(
    float& d0, float& d1, float& d2, float& d3,
    uint32_t a0, uint32_t a1, uint32_t a2, uint32_t a3,
    uint32_t b0, uint32_t b1)
{
    asm volatile(
        "mma.sync.aligned.m16n8k8.row.col.f32.tf32.tf32.f32 "
        "{%0,%1,%2,%3}, {%4,%5,%6,%7}, {%8,%9}, {%0,%1,%2,%3};\n"
        : "+f"(d0), "+f"(d1), "+f"(d2), "+f"(d3)
        : "r"(a0), "r"(a1), "r"(a2), "r"(a3), "r"(b0), "r"(b1));
}

// ---------------- mask decode (robust to bool8 / int32 / float32) ----------
__global__ void mask_decode_kernel(const unsigned char* __restrict__ raw) {
    __shared__ int cnt[4];
    int tid = threadIdx.x;
    if (tid < 4) cnt[tid] = 0;
    __syncthreads();
    for (int i = tid; i < NT; i += blockDim.x)
        if (raw[i]) atomicAdd(&cnt[i & 3], 1);
    __syncthreads();
    int c0 = cnt[0], c1 = cnt[1], c2 = cnt[2], c3 = cnt[3];
    int mode; // 0 = bool8/int8, 1 = int32, 2 = float32
    if (c0 > 0 && c1 == 0 && c2 == 0 && c3 == 0)       mode = 1;
    else if ((c2 > 0 || c3 > 0) && c0 == 0 && c1 == 0) mode = 2;
    else                                               mode = 0;
    for (int i = tid; i < NT; i += blockDim.x) {
        int v;
        if (mode == 0)      v = (raw[i] != 0);
        else if (mode == 1) v = (((const int*)raw)[i] != 0);
        else                v = (((const float*)raw)[i] != 0.0f);
        g_mask[i] = v;
    }
}

// ---------------- TF32 projection GEMM, pipelined, fused RoPE --------------
// Block tile 128(m) x 64(n) == one full head in n. 8 warps, each 32x32.
// k-chunk 32, register-prefetch pipeline: LDG(next) issues before MMA(current).
// Warp n-cols {base..base+15, base+32..base+47} so RoPE pair (c, c+32) stays
// in one thread (nt and nt+2).
#define KC    32
#define GPAD2 36   // [m][k] row stride (floats): 32 + 4 pad, conflict-free

__global__ __launch_bounds__(256) void proj_gemm_tc(
    const float* __restrict__ query, const float* __restrict__ key_in,
    const float* __restrict__ value,
    const float* __restrict__ Wq, const float* __restrict__ bq,
    const float* __restrict__ Wk, const float* __restrict__ bk,
    const float* __restrict__ Wv, const float* __restrict__ bv,
    const float* __restrict__ Wg, const float* __restrict__ bg,
    const float* __restrict__ cosb, const float* __restrict__ sinb)
{
    const int z = blockIdx.z;
    const float* A; const float* W; const float* bias;
    if      (z == 0) { A = query;  W = Wq; bias = bq; }
    else if (z == 1) { A = key_in; W = Wk; bias = bk; }
    else if (z == 2) { A = value;  W = Wv; bias = bv; }
    else             { A = query;  W = Wg; bias = bg; }

    const int m0 = blockIdx.y * 128;
    const int n0 = blockIdx.x * 64;

    __shared__ float As[128 * GPAD2];   // [m][k]
    __shared__ float Bs[64  * GPAD2];   // [n][k]

    const int tid  = threadIdx.x;
    const int warp = tid >> 5;
    const int lane = tid & 31;
    const int q    = lane >> 2;
    const int tq   = lane & 3;
    const int warpM0 = (warp >> 1) * 32;
    const int colbase = (warp & 1) * 16;

    // per-thread tile coords (8 float4 per row of 32 k-floats)
    const int am[4] = { (tid)>>3, (tid+256)>>3, (tid+512)>>3, (tid+768)>>3 };
    const int ak    = (tid & 7) * 4;
    const int bn[2] = { (tid)>>3, (tid+256)>>3 };

    float acc[2][4][4];
    #pragma unroll
    for (int mt = 0; mt < 2; mt++)
        #pragma unroll
        for (int nt = 0; nt < 4; nt++)
            #pragma unroll
            for (int e = 0; e < 4; e++) acc[mt][nt][e] = 0.f;

    // prologue prefetch
    float4 ra[4], rb[2];
    #pragma unroll
    for (int i = 0; i < 4; i++)
        ra[i] = *(const float4*)(A + (size_t)(m0 + am[i]) * Dc + ak);
    #pragma unroll
    for (int i = 0; i < 2; i++)
        rb[i] = *(const float4*)(W + (size_t)(n0 + bn[i]) * Dc + ak);

    for (int k0 = 0; k0 < Dc; k0 += KC) {
        __syncthreads();   // previous MMA done reading smem
        #pragma unroll
        for (int i = 0; i < 4; i++)
            *(float4*)&As[am[i] * GPAD2 + ak] = f2tf4(ra[i]);
        #pragma unroll
        for (int i = 0; i < 2; i++)
            *(float4*)&Bs[bn[i] * GPAD2 + ak] = f2tf4(rb[i]);
        __syncthreads();

        // prefetch next k-chunk; latency hides under the MMA block below
        if (k0 + KC < Dc) {
            #pragma unroll
            for (int i = 0; i < 4; i++)
                ra[i] = *(const float4*)(A + (size_t)(m0 + am[i]) * Dc + k0 + KC + ak);
            #pragma unroll
            for (int i = 0; i < 2; i++)
                rb[i] = *(const float4*)(W + (size_t)(n0 + bn[i]) * Dc + k0 + KC + ak);
        }

        #pragma unroll
        for (int ks = 0; ks < KC; ks += 8) {
            uint32_t af[2][4];
            #pragma unroll
            for (int mt = 0; mt < 2; mt++) {
                int r = warpM0 + mt * 16 + q;
                af[mt][0] = __float_as_uint(As[r       * GPAD2 + ks     + tq]);
                af[mt][1] = __float_as_uint(As[(r + 8) * GPAD2 + ks     + tq]);
                af[mt][2] = __float_as_uint(As[r       * GPAD2 + ks + 4 + tq]);
                af[mt][3] = __float_as_uint(As[(r + 8) * GPAD2 + ks + 4 + tq]);
            }
            #pragma unroll
            for (int nt = 0; nt < 4; nt++) {
                int n = colbase + (nt & 1) * 8 + (nt >> 1) * 32 + q;
                uint32_t b0 = __float_as_uint(Bs[n * GPAD2 + ks     + tq]);
                uint32_t b1 = __float_as_uint(Bs[n * GPAD2 + ks + 4 + tq]);
                #pragma unroll
                for (int mt = 0; mt < 2; mt++)
                    mma_tf32(acc[mt][nt][0], acc[mt][nt][1], acc[mt][nt][2], acc[mt][nt][3],
                             af[mt][0], af[mt][1], af[mt][2], af[mt][3], b0, b1);
            }
        }
    }

    // epilogue: bias, optional rope (pairs nt <-> nt+2), scatter
    #pragma unroll
    for (int mt = 0; mt < 2; mt++)
        #pragma unroll
        for (int nt = 0; nt < 2; nt++)
            #pragma unroll
            for (int e = 0; e < 4; e++) {
                int row = m0 + warpM0 + mt * 16 + q + ((e >> 1) ? 8 : 0);
                int cl  = colbase + nt * 8 + tq * 2 + (e & 1);   // 0..31
                int l   = row & (Lc - 1);
                float x1 = acc[mt][nt][e]     + bias[n0 + cl];
                float x2 = acc[mt][nt + 2][e] + bias[n0 + cl + 32];
                float y1 = x1, y2 = x2;
                if (z <= 1) {
                    float c1 = cosb[l * 64 + cl],      s1 = sinb[l * 64 + cl];
                    float c2 = cosb[l * 64 + cl + 32], s2 = sinb[l * 64 + cl + 32];
                    y1 = x1 * c1 - x2 * s1;
                    y2 = x2 * c2 + x1 * s2;
                }
                if (z == 3) {
                    g_G[(size_t)row * Dc + n0 + cl]      = 1.f / (1.f + __expf(-y1));
                    g_G[(size_t)row * Dc + n0 + cl + 32] = 1.f / (1.f + __expf(-y2));
                } else {
                    int b = row >> 11, l2 = row & (Lc - 1);
                    int h = n0 >> 6;
                    size_t base = ((size_t)(b * Hc + h) * Lc + l2) * HDc;
                    if (z == 0)      { g_Q[base + cl] = y1; g_Q[base + cl + 32] = y2; }
                    else if (z == 1) { g_K[base + cl] = y1; g_K[base + cl + 32] = y2; }
                    else             { g_V[base + cl] = y1; g_V[base + cl + 32] = y2; }
                }
            }
}

// ---------------- TF32 flash attention + gate fuse (unchanged from R5) -----
#define KSTR 80
#define VSTR2 90
#define PSTR 68
#define AT_K  0
#define AT_V  (64*KSTR)                    // 5120
#define AT_P  (AT_V + 64*VSTR2)            // 10880
#define AT_MK (AT_P + 128*PSTR)            // 19584
#define ATTN_SMEM ((AT_MK + 64) * 4)       // 78592 bytes

__global__ __launch_bounds__(256, 2) void attn_tc_kernel()
{
    extern __shared__ float sm[];
    float* Ks2 = sm + AT_K;
    float* Vs2 = sm + AT_V;
    float* Ps  = sm + AT_P;
    float* mk  = sm + AT_MK;

    const int qt  = blockIdx.x;        // 0..15
    const int bh  = blockIdx.y;        // 0..31
    const int b   = bh >> 4;
    const int h   = bh & 15;
    const int tid = threadIdx.x;
    const int warp = tid >> 5;
    const int lane = tid & 31;
    const int q    = lane >> 2;
    const int tq   = lane & 3;
    const int warpM0 = warp * 16;

    const float* Qg = g_Q + ((size_t)bh * Lc + qt * 128 + warpM0 + q) * 64;
    uint32_t qf[8][4];
    #pragma unroll
    for (int s = 0; s < 8; s++) {
        qf[s][0] = f2tf(Qg[s * 8 + tq]);
        qf[s][1] = f2tf(Qg[512 + s * 8 + tq]);
        qf[s][2] = f2tf(Qg[s * 8 + 4 + tq]);
        qf[s][3] = f2tf(Qg[512 + s * 8 + 4 + tq]);
    }

    float O[8][4];
    #pragma unroll
    for (int nt = 0; nt < 8; nt++)
        #pragma unroll
        for (int e = 0; e < 4; e++) O[nt][e] = 0.f;
    float m0r = -1e30f, m1r = -1e30f, l0r = 0.f, l1r = 0.f;

    const int* maskb = g_mask + b * Lc;
    const int vn = tid >> 2, vt2 = tid & 3;

    for (int kt = 0; kt < 32; kt++) {
        __syncthreads();
        const float* Kg = g_K + ((size_t)bh * Lc + kt * 64) * 64;
        const float* Vg = g_V + ((size_t)bh * Lc + kt * 64) * 64;

        #pragma unroll
        for (int it = 0; it < 4; it++) {
            int f = tid + it * 256;
            int n = f >> 4, kq = f & 15;
            float4 v = *(const float4*)(Kg + n * 64 + kq * 4);
            float* dst = &Ks2[n * KSTR + kq];
            dst[0]  = f2tf_f(v.x);
            dst[20] = f2tf_f(v.y);
            dst[40] = f2tf_f(v.z);
            dst[60] = f2tf_f(v.w);
        }
        {
            float vr[16];
            #pragma unroll
            for (int j = 0; j < 16; j++)
                vr[j] = f2tf_f(Vg[(4 * j + vt2) * 64 + vn]);
            float* dst = &Vs2[vn * VSTR2 + vt2 * 24];
            #pragma unroll
            for (int j = 0; j < 8; j++)
                *(float2*)&dst[2 * j] = make_float2(vr[2 * j], vr[2 * j + 1]);
        }
        if (tid < 64) mk[tid] = maskb[kt * 64 + tid] ? -1e30f : 0.f;
        __syncthreads();

        float S[8][4];
        #pragma unroll
        for (int nt = 0; nt < 8; nt++)
            #pragma unroll
            for (int e = 0; e < 4; e++) S[nt][e] = 0.f;
        #pragma unroll
        for (int nt = 0; nt < 8; nt++) {
            const float4* kp = (const float4*)&Ks2[(nt * 8 + q) * KSTR + tq * 20];
            float4 k0 = kp[0], k1 = kp[1], k2 = kp[2], k3 = kp[3];
            mma_tf32(S[nt][0], S[nt][1], S[nt][2], S[nt][3],
                     qf[0][0], qf[0][1], qf[0][2], qf[0][3],
                     __float_as_uint(k0.x), __float_as_uint(k0.y));
            mma_tf32(S[nt][0], S[nt][1], S[nt][2], S[nt][3],
                     qf[1][0], qf[1][1], qf[1][2], qf[1][3],
                     __float_as_uint(k0.z), __float_as_uint(k0.w));
            mma_tf32(S[nt][0], S[nt][1], S[nt][2], S[nt][3],
                     qf[2][0], qf[2][1], qf[2][2], qf[2][3],
                     __float_as_uint(k1.x), __float_as_uint(k1.y));
            mma_tf32(S[nt][0], S[nt][1], S[nt][2], S[nt][3],
                     qf[3][0], qf[3][1], qf[3][2], qf[3][3],
                     __float_as_uint(k1.z), __float_as_uint(k1.w));
            mma_tf32(S[nt][0], S[nt][1], S[nt][2], S[nt][3],
                     qf[4][0], qf[4][1], qf[4][2], qf[4][3],
                     __float_as_uint(k2.x), __float_as_uint(k2.y));
            mma_tf32(S[nt][0], S[nt][1], S[nt][2], S[nt][3],
                     qf[5][0], qf[5][1], qf[5][2], qf[5][3],
                     __float_as_uint(k2.z), __float_as_uint(k2.w));
            mma_tf32(S[nt][0], S[nt][1], S[nt][2], S[nt][3],
                     qf[6][0], qf[6][1], qf[6][2], qf[6][3],
                     __float_as_uint(k3.x), __float_as_uint(k3.y));
            mma_tf32(S[nt][0], S[nt][1], S[nt][2], S[nt][3],
                     qf[7][0], qf[7][1], qf[7][2], qf[7][3],
                     __float_as_uint(k3.z), __float_as_uint(k3.w));
        }

        #pragma unroll
        for (int nt = 0; nt < 8; nt++) {
            float mq0 = mk[nt * 8 + tq * 2];
            float mq1 = mk[nt * 8 + tq * 2 + 1];
            S[nt][0] = S[nt][0] * 0.125f + mq0;
            S[nt][1] = S[nt][1] * 0.125f + mq1;
            S[nt][2] = S[nt][2] * 0.125f + mq0;
            S[nt][3] = S[nt][3] * 0.125f + mq1;
        }

        float rm0 = -1e30f, rm1 = -1e30f;
        #pragma unroll
        for (int nt = 0; nt < 8; nt++) {
            rm0 = fmaxf(rm0, fmaxf(S[nt][0], S[nt][1]));
            rm1 = fmaxf(rm1, fmaxf(S[nt][2], S[nt][3]));
        }
        rm0 = fmaxf(rm0, __shfl_xor_sync(0xffffffffu, rm0, 1));
        rm0 = fmaxf(rm0, __shfl_xor_sync(0xffffffffu, rm0, 2));
        rm1 = fmaxf(rm1, __shfl_xor_sync(0xffffffffu, rm1, 1));
        rm1 = fmaxf(rm1, __shfl_xor_sync(0xffffffffu, rm1, 2));
        float mn0 = fmaxf(m0r, rm0);
        float mn1 = fmaxf(m1r, rm1);

        float rs0 = 0.f, rs1 = 0.f;
        #pragma unroll
        for (int nt = 0; nt < 8; nt++) {
            float p0 = (S[nt][0] < -1e29f) ? 0.f : __expf(S[nt][0] - mn0);
            float p1 = (S[nt][1] < -1e29f) ? 0.f : __expf(S[nt][1] - mn0);
            float p2 = (S[nt][2] < -1e29f) ? 0.f : __expf(S[nt][2] - mn1);
            float p3 = (S[nt][3] < -1e29f) ? 0.f : __expf(S[nt][3] - mn1);
            S[nt][0] = p0; S[nt][1] = p1; S[nt][2] = p2; S[nt][3] = p3;
            rs0 += p0 + p1; rs1 += p2 + p3;
        }
        rs0 += __shfl_xor_sync(0xffffffffu, rs0, 1);
        rs0 += __shfl_xor_sync(0xffffffffu, rs0, 2);
        rs1 += __shfl_xor_sync(0xffffffffu, rs1, 1);
        rs1 += __shfl_xor_sync(0xffffffffu, rs1, 2);

        float alpha0 = __expf(m0r - mn0);
        float alpha1 = __expf(m1r - mn1);
        l0r = l0r * alpha0 + rs0;  m0r = mn0;
        l1r = l1r * alpha1 + rs1;  m1r = mn1;

        {
            int r = warpM0 + q;
            #pragma unroll
            for (int nt = 0; nt < 8; nt++) {
                O[nt][0] *= alpha0; O[nt][1] *= alpha0;
                O[nt][2] *= alpha1; O[nt][3] *= alpha1;
                float2 p01 = make_float2(f2tf_f(S[nt][0]), f2tf_f(S[nt][1]));
                float2 p23 = make_float2(f2tf_f(S[nt][2]), f2tf_f(S[nt][3]));
                *(float2*)&Ps[r       * PSTR + nt * 8 + tq * 2] = p01;
                *(float2*)&Ps[(r + 8) * PSTR + nt * 8 + tq * 2] = p23;
            }
        }
        __syncthreads();

        #pragma unroll
        for (int s = 0; s < 8; s++) {
            int r = warpM0 + q;
            int ks = s * 8;
            uint32_t a0 = __float_as_uint(Ps[r       * PSTR + ks     + tq]);
            uint32_t a1 = __float_as_uint(Ps[(r + 8) * PSTR + ks     + tq]);
            uint32_t a2 = __float_as_uint(Ps[r       * PSTR + ks + 4 + tq]);
            uint32_t a3 = __float_as_uint(Ps[(r + 8) * PSTR + ks + 4 + tq]);
            #pragma unroll
            for (int nt = 0; nt < 8; nt++) {
                float2 vb = *(const float2*)&Vs2[(nt * 8 + q) * VSTR2 + tq * 24 + 2 * s];
                mma_tf32(O[nt][0], O[nt][1], O[nt][2], O[nt][3],
                         a0, a1, a2, a3,
                         __float_as_uint(vb.x), __float_as_uint(vb.y));
            }
        }
    }

    float inv0 = (l0r > 0.f) ? (1.f / l0r) : 0.f;
    float inv1 = (l1r > 0.f) ? (1.f / l1r) : 0.f;
    int r0 = qt * 128 + warpM0 + q;
    size_t tok0 = (size_t)b * Lc + r0;
    size_t tok1 = tok0 + 8;
    #pragma unroll
    for (int nt = 0; nt < 8; nt++) {
        int n = h * 64 + nt * 8 + tq * 2;
        g_AO[tok0 * Dc + n]     = O[nt][0] * inv0 * g_G[tok0 * Dc + n];
        g_AO[tok0 * Dc + n + 1] = O[nt][1] * inv0 * g_G[tok0 * Dc + n + 1];
        g_AO[tok1 * Dc + n]     = O[nt][2] * inv1 * g_G[tok1 * Dc + n];
        g_AO[tok1 * Dc + n + 1] = O[nt][3] * inv1 * g_G[tok1 * Dc + n + 1];
    }
}

// ---------------- TF32 output projection GEMM, pipelined -------------------
__global__ __launch_bounds__(256) void out_gemm_tc(
    const float* __restrict__ Wo, const float* __restrict__ bo,
    float* __restrict__ out)
{
    const int m0 = blockIdx.y * 128;
    const int n0 = blockIdx.x * 64;

    __shared__ float As[128 * GPAD2];
    __shared__ float Bs[64  * GPAD2];

    const int tid  = threadIdx.x;
    const int warp = tid >> 5;
    const int lane = tid & 31;
    const int q    = lane >> 2;
    const int tq   = lane & 3;
    const int warpM0 = (warp >> 1) * 32;
    const int warpN0 = (warp & 1) * 32;

    const int am[4] = { (tid)>>3, (tid+256)>>3, (tid+512)>>3, (tid+768)>>3 };
    const int ak    = (tid & 7) * 4;
    const int bn[2] = { (tid)>>3, (tid+256)>>3 };

    float acc[2][4][4];
    #pragma unroll
    for (int mt = 0; mt < 2; mt++)
        #pragma unroll
        for (int nt = 0; nt < 4; nt++)
            #pragma unroll
            for (int e = 0; e < 4; e++) acc[mt][nt][e] = 0.f;

    float4 ra[4], rb[2];
    #pragma unroll
    for (int i = 0; i < 4; i++)
        ra[i] = *(const float4*)(g_AO + (size_t)(m0 + am[i]) * Dc + ak);
    #pragma unroll
    for (int i = 0; i < 2; i++)
        rb[i] = *(const float4*)(Wo + (size_t)(n0 + bn[i]) * Dc + ak);

    for (int k0 = 0; k0 < Dc; k0 += KC) {
        __syncthreads();
        #pragma unroll
        for (int i = 0; i < 4; i++)
            *(float4*)&As[am[i] * GPAD2 + ak] = f2tf4(ra[i]);
        #pragma unroll
        for (int i = 0; i < 2; i++)
            *(float4*)&Bs[bn[i] * GPAD2 + ak] = f2tf4(rb[i]);
        __syncthreads();

        if (k0 + KC < Dc) {
            #pragma unroll
            for (int i = 0; i < 4; i++)
                ra[i] = *(const float4*)(g_AO + (size_t)(m0 + am[i]) * Dc + k0 + KC + ak);
            #pragma unroll
            for (int i = 0; i < 2; i++)
                rb[i] = *(const float4*)(Wo + (size_t)(n0 + bn[i]) * Dc + k0 + KC + ak);
        }

        #pragma unroll
        for (int ks = 0; ks < KC; ks += 8) {
            uint32_t af[2][4];
            #pragma unroll
            for (int mt = 0; mt < 2; mt++) {
                int r = warpM0 + mt * 16 + q;
                af[mt][0] = __float_as_uint(As[r       * GPAD2 + ks     + tq]);
                af[mt][1] = __float_as_uint(As[(r + 8) * GPAD2 + ks     + tq]);
                af[mt][2] = __float_as_uint(As[r       * GPAD2 + ks + 4 + tq]);
                af[mt][3] = __float_as_uint(As[(r + 8) * GPAD2 + ks + 4 + tq]);
            }
            #pragma unroll
            for (int nt = 0; nt < 4; nt++) {
                int n = warpN0 + nt * 8 + q;
                uint32_t b0 = __float_as_uint(Bs[n * GPAD2 + ks     + tq]);
                uint32_t b1 = __float_as_uint(Bs[n * GPAD2 + ks + 4 + tq]);
                #pragma unroll
                for (int mt = 0; mt < 2; mt++)
                    mma_tf32(acc[mt][nt][0], acc[mt][nt][1], acc[mt][nt][2], acc[mt][nt][3],
                             af[mt][0], af[mt][1], af[mt][2], af[mt][3], b0, b1);
            }
        }
    }

    #pragma unroll
    for (int mt = 0; mt < 2; mt++)
        #pragma unroll
        for (int nt = 0; nt < 4; nt++)
            #pragma unroll
            for (int e = 0; e < 4; e++) {
                int row = m0 + warpM0 + mt * 16 + q + ((e >> 1) ? 8 : 0);
                int col = n0 + warpN0 + nt * 8 + tq * 2 + (e & 1);
                out[(size_t)row * Dc + col] = acc[mt][nt][e] + bo[col];
            }
}

// ---------------- launch ----------------------------------------------------
extern "C" void kernel_launch(void* const* d_in, const int* in_sizes, int n_in,
                              void* d_out, int out_size)
{
    const float* query   = (const float*)d_in[0];
    const float* key_in  = (const float*)d_in[1];
    const float* value   = (const float*)d_in[2];
    const unsigned char* maskraw = (const unsigned char*)d_in[3];
    const float* rope_cos = (const float*)d_in[4];
    const float* rope_sin = (const float*)d_in[5];
    const float* Wq = (const float*)d_in[6];
    const float* bq = (const float*)d_in[7];
    const float* Wk = (const float*)d_in[8];
    const float* bk = (const float*)d_in[9];
    const float* Wv = (const float*)d_in[10];
    const float* bv = (const float*)d_in[11];
    const float* Wg = (const float*)d_in[12];
    const float* bg = (const float*)d_in[13];
    const float* Wo = (const float*)d_in[14];
    const float* bo = (const float*)d_in[15];
    float* out = (float*)d_out;

    (void)in_sizes; (void)n_in; (void)out_size;

    mask_decode_kernel<<<1, 1024>>>(maskraw);

    dim3 pg(Dc / 64, NT / 128, 4);         // (16, 32, 4)
    proj_gemm_tc<<<pg, 256>>>(query, key_in, value,
                              Wq, bq, Wk, bk, Wv, bv, Wg, bg,
                              rope_cos, rope_sin);

    cudaFuncSetAttribute(attn_tc_kernel,
                         cudaFuncAttributeMaxDynamicSharedMemorySize, ATTN_SMEM);
    attn_tc_kernel<<<dim3(Lc / 128, BHc), 256, ATTN_SMEM>>>();

    out_gemm_tc<<<dim3(Dc / 64, NT / 128), 256>>>(Wo, bo, out);
}

// round 8
// speedup vs baseline: 1.6582x; 1.4645x over previous
#include <cuda_runtime.h>
#include <cuda_fp16.h>
#include <math.h>
#include <stdint.h>

#define Bc   2
#define Lc   2048
#define Dc   1024
#define Hc   16
#define HDc  64
#define NT   (Bc*Lc)
#define BHc  (Bc*Hc)

__device__ float g_Q [BHc*Lc*HDc];
__device__ float g_K [BHc*Lc*HDc];
__device__ float g_V [BHc*Lc*HDc];
__device__ float g_G [(size_t)NT*Dc];
__device__ float g_AO[(size_t)NT*Dc];
__device__ int   g_mask[NT];

__device__ __forceinline__ uint32_t packh2(float a, float b) {
    __half2 h = __floats2half2_rn(a, b);
    return *reinterpret_cast<uint32_t*>(&h);
}
__device__ __forceinline__ void mma_f16(
    float* d, uint32_t a0, uint32_t a1, uint32_t a2, uint32_t a3,
    uint32_t b0, uint32_t b1)
{
    asm volatile(
        "mma.sync.aligned.m16n8k16.row.col.f32.f16.f16.f32 "
        "{%0,%1,%2,%3}, {%4,%5,%6,%7}, {%8,%9}, {%0,%1,%2,%3};\n"
        : "+f"(d[0]), "+f"(d[1]), "+f"(d[2]), "+f"(d[3])
        : "r"(a0), "r"(a1), "r"(a2), "r"(a3), "r"(b0), "r"(b1));
}

__global__ void mask_decode_kernel(const unsigned char* __restrict__ raw) {
    __shared__ int cnt[4];
    int tid = threadIdx.x;
    if (tid < 4) cnt[tid] = 0;
    __syncthreads();
    for (int i = tid; i < NT; i += blockDim.x)
        if (raw[i]) atomicAdd(&cnt[i & 3], 1);
    __syncthreads();
    int c0 = cnt[0], c1 = cnt[1], c2 = cnt[2], c3 = cnt[3];
    int mode;
    if (c0 > 0 && c1 == 0 && c2 == 0 && c3 == 0)       mode = 1;
    else if ((c2 > 0 || c3 > 0) && c0 == 0 && c1 == 0) mode = 2;
    else                                               mode = 0;
    for (int i = tid; i < NT; i += blockDim.x) {
        int v;
        if (mode == 0)      v = (raw[i] != 0);
        else if (mode == 1) v = (((const int*)raw)[i] != 0);
        else                v = (((const float*)raw)[i] != 0.0f);
        g_mask[i] = v;
    }
}

// ---- FP16 projection GEMM, pipelined, fused RoPE. 128x64 tile, 8 warps. ----
// smem rows: 16 half2, permuted pos=(idx&3)*4+(idx>>2); LDS.128 covers both
// k16-steps of the 32-float chunk. Conflict-free (granule = r*4+tq).
#define KC 32

__global__ __launch_bounds__(256) void proj_gemm_tc(
    const float* __restrict__ query, const float* __restrict__ key_in,
    const float* __restrict__ value,
    const float* __restrict__ Wq, const float* __restrict__ bq,
    const float* __restrict__ Wk, const float* __restrict__ bk,
    const float* __restrict__ Wv, const float* __restrict__ bv,
    const float* __restrict__ Wg, const float* __restrict__ bg,
    const float* __restrict__ cosb, const float* __restrict__ sinb)
{
    const int z = blockIdx.z;
    const float* A; const float* W; const float* bias;
    if      (z == 0) { A = query;  W = Wq; bias = bq; }
    else if (z == 1) { A = key_in; W = Wk; bias = bk; }
    else if (z == 2) { A = value;  W = Wv; bias = bv; }
    else             { A = query;  W = Wg; bias = bg; }

    const int m0 = blockIdx.y * 128;
    const int n0 = blockIdx.x * 64;

    __shared__ uint32_t As[128 * 16];
    __shared__ uint32_t Bs[64 * 16];

    const int tid  = threadIdx.x;
    const int warp = tid >> 5;
    const int lane = tid & 31;
    const int q    = lane >> 2;
    const int tq   = lane & 3;
    const int warpM0 = (warp >> 1) * 32;
    const int colbase = (warp & 1) * 16;

    float acc[2][4][4];
    #pragma unroll
    for (int mt = 0; mt < 2; mt++)
        #pragma unroll
        for (int nt = 0; nt < 4; nt++)
            #pragma unroll
            for (int e = 0; e < 4; e++) acc[mt][nt][e] = 0.f;

    float4 ra[4], rb[2];
    #pragma unroll
    for (int i = 0; i < 4; i++) {
        int f = tid + i * 256;
        ra[i] = *(const float4*)(A + (size_t)(m0 + (f >> 3)) * Dc + (f & 7) * 4);
    }
    #pragma unroll
    for (int i = 0; i < 2; i++) {
        int f = tid + i * 256;
        rb[i] = *(const float4*)(W + (size_t)(n0 + (f >> 3)) * Dc + (f & 7) * 4);
    }

    for (int k0 = 0; k0 < Dc; k0 += KC) {
        __syncthreads();
        #pragma unroll
        for (int i = 0; i < 4; i++) {
            int f = tid + i * 256;
            int m = f >> 3, c = f & 7;
            int p = (c & 1) * 8 + (c >> 1);
            As[m * 16 + p]     = packh2(ra[i].x, ra[i].y);
            As[m * 16 + p + 4] = packh2(ra[i].z, ra[i].w);
        }
        #pragma unroll
        for (int i = 0; i < 2; i++) {
            int f = tid + i * 256;
            int n = f >> 3, c = f & 7;
            int p = (c & 1) * 8 + (c >> 1);
            Bs[n * 16 + p]     = packh2(rb[i].x, rb[i].y);
            Bs[n * 16 + p + 4] = packh2(rb[i].z, rb[i].w);
        }
        __syncthreads();

        if (k0 + KC < Dc) {
            #pragma unroll
            for (int i = 0; i < 4; i++) {
                int f = tid + i * 256;
                ra[i] = *(const float4*)(A + (size_t)(m0 + (f >> 3)) * Dc + k0 + KC + (f & 7) * 4);
            }
            #pragma unroll
            for (int i = 0; i < 2; i++) {
                int f = tid + i * 256;
                rb[i] = *(const float4*)(W + (size_t)(n0 + (f >> 3)) * Dc + k0 + KC + (f & 7) * 4);
            }
        }

        uint4 Ar[2], Ar8[2];
        #pragma unroll
        for (int mt = 0; mt < 2; mt++) {
            int r = warpM0 + mt * 16 + q;
            Ar[mt]  = *(const uint4*)&As[r * 16 + tq * 4];
            Ar8[mt] = *(const uint4*)&As[(r + 8) * 16 + tq * 4];
        }
        #pragma unroll
        for (int nt = 0; nt < 4; nt++) {
            int n = colbase + (nt & 1) * 8 + (nt >> 1) * 32 + q;
            uint4 Bv = *(const uint4*)&Bs[n * 16 + tq * 4];
            #pragma unroll
            for (int mt = 0; mt < 2; mt++) {
                mma_f16(acc[mt][nt], Ar[mt].x, Ar8[mt].x, Ar[mt].y, Ar8[mt].y, Bv.x, Bv.y);
                mma_f16(acc[mt][nt], Ar[mt].z, Ar8[mt].z, Ar[mt].w, Ar8[mt].w, Bv.z, Bv.w);
            }
        }
    }

    #pragma unroll
    for (int mt = 0; mt < 2; mt++)
        #pragma unroll
        for (int nt = 0; nt < 2; nt++)
            #pragma unroll
            for (int e = 0; e < 4; e++) {
                int row = m0 + warpM0 + mt * 16 + q + ((e >> 1) ? 8 : 0);
                int cl  = colbase + nt * 8 + tq * 2 + (e & 1);
                int l   = row & (Lc - 1);
                float x1 = acc[mt][nt][e]     + bias[n0 + cl];
                float x2 = acc[mt][nt + 2][e] + bias[n0 + cl + 32];
                float y1 = x1, y2 = x2;
                if (z <= 1) {
                    float c1 = cosb[l * 64 + cl],      s1 = sinb[l * 64 + cl];
                    float c2 = cosb[l * 64 + cl + 32], s2 = sinb[l * 64 + cl + 32];
                    y1 = x1 * c1 - x2 * s1;
                    y2 = x2 * c2 + x1 * s2;
                }
                if (z == 3) {
                    g_G[(size_t)row * Dc + n0 + cl]      = 1.f / (1.f + __expf(-y1));
                    g_G[(size_t)row * Dc + n0 + cl + 32] = 1.f / (1.f + __expf(-y2));
                } else {
                    int b = row >> 11;
                    int h = n0 >> 6;
                    size_t base = ((size_t)(b * Hc + h) * Lc + l) * HDc;
                    if (z == 0)      { g_Q[base + cl] = y1; g_Q[base + cl + 32] = y2; }
                    else if (z == 1) { g_K[base + cl] = y1; g_K[base + cl + 32] = y2; }
                    else             { g_V[base + cl] = y1; g_V[base + cl + 32] = y2; }
                }
            }
}

// ---- FP16 flash attention. q-tile 128, 8 warps. P stays in registers. ------
// K/V smem rows: 32 half2, permuted pos=(idx&3)*8+(idx>>2), stride 36 half2.
__global__ __launch_bounds__(256, 2) void attn_tc_kernel()
{
    __shared__ uint32_t Ks[64 * 36];
    __shared__ uint32_t Vs[64 * 36];
    __shared__ float mk[64];

    const int qt  = blockIdx.x;
    const int bh  = blockIdx.y;
    const int b   = bh >> 4;
    const int h   = bh & 15;
    const int tid = threadIdx.x;
    const int warp = tid >> 5;
    const int lane = tid & 31;
    const int q    = lane >> 2;
    const int tq   = lane & 3;

    // Q fragments (loop-invariant)
    const float* Qg = g_Q + ((size_t)bh * Lc + qt * 128 + warp * 16 + q) * 64;
    uint32_t qf[4][4];
    #pragma unroll
    for (int s = 0; s < 4; s++) {
        qf[s][0] = packh2(Qg[16*s + 2*tq],           Qg[16*s + 2*tq + 1]);
        qf[s][1] = packh2(Qg[512 + 16*s + 2*tq],     Qg[512 + 16*s + 2*tq + 1]);
        qf[s][2] = packh2(Qg[16*s + 2*tq + 8],       Qg[16*s + 2*tq + 9]);
        qf[s][3] = packh2(Qg[512 + 16*s + 2*tq + 8], Qg[512 + 16*s + 2*tq + 9]);
    }

    float O[8][4];
    #pragma unroll
    for (int nt = 0; nt < 8; nt++)
        #pragma unroll
        for (int e = 0; e < 4; e++) O[nt][e] = 0.f;
    float m0r = -1e30f, m1r = -1e30f, l0r = 0.f, l1r = 0.f;

    const int* maskb = g_mask + b * Lc;
    const int vn = tid >> 2, vt2 = tid & 3;

    for (int kt = 0; kt < 32; kt++) {
        __syncthreads();
        const float* Kg = g_K + ((size_t)bh * Lc + kt * 64) * 64;
        const float* Vg = g_V + ((size_t)bh * Lc + kt * 64) * 64;

        // K tile: row n (key), pair-permuted half2 over dim
        #pragma unroll
        for (int it = 0; it < 2; it++) {
            int f = tid + it * 256;
            int n = f >> 3, c = f & 7;
            float4 v1 = *(const float4*)(Kg + n * 64 + c * 8);
            float4 v2 = *(const float4*)(Kg + n * 64 + c * 8 + 4);
            uint32_t* dst = &Ks[n * 36 + c];
            dst[0]  = packh2(v1.x, v1.y);
            dst[8]  = packh2(v1.z, v1.w);
            dst[16] = packh2(v2.x, v2.y);
            dst[24] = packh2(v2.z, v2.w);
        }
        // V tile transposed: row = dim, pair-permuted half2 over key
        {
            uint32_t vr[8];
            #pragma unroll
            for (int i = 0; i < 8; i++)
                vr[i] = packh2(Vg[(8*i + 2*vt2) * 64 + vn],
                               Vg[(8*i + 2*vt2 + 1) * 64 + vn]);
            uint32_t* dst = &Vs[vn * 36 + vt2 * 8];
            *(uint4*)dst       = make_uint4(vr[0], vr[1], vr[2], vr[3]);
            *(uint4*)(dst + 4) = make_uint4(vr[4], vr[5], vr[6], vr[7]);
        }
        if (tid < 64) mk[tid] = maskb[kt * 64 + tid] ? -1e30f : 0.f;
        __syncthreads();

        // S = Q.K^T
        float S[8][4];
        #pragma unroll
        for (int nt = 0; nt < 8; nt++)
            #pragma unroll
            for (int e = 0; e < 4; e++) S[nt][e] = 0.f;
        #pragma unroll
        for (int nt = 0; nt < 8; nt++) {
            const uint32_t* kr = &Ks[(nt * 8 + q) * 36 + tq * 8];
            uint4 B1 = *(const uint4*)kr;
            uint4 B2 = *(const uint4*)(kr + 4);
            mma_f16(S[nt], qf[0][0], qf[0][1], qf[0][2], qf[0][3], B1.x, B1.y);
            mma_f16(S[nt], qf[1][0], qf[1][1], qf[1][2], qf[1][3], B1.z, B1.w);
            mma_f16(S[nt], qf[2][0], qf[2][1], qf[2][2], qf[2][3], B2.x, B2.y);
            mma_f16(S[nt], qf[3][0], qf[3][1], qf[3][2], qf[3][3], B2.z, B2.w);
        }

        // scale + mask
        #pragma unroll
        for (int nt = 0; nt < 8; nt++) {
            float mq0 = mk[nt * 8 + tq * 2];
            float mq1 = mk[nt * 8 + tq * 2 + 1];
            S[nt][0] = S[nt][0] * 0.125f + mq0;
            S[nt][1] = S[nt][1] * 0.125f + mq1;
            S[nt][2] = S[nt][2] * 0.125f + mq0;
            S[nt][3] = S[nt][3] * 0.125f + mq1;
        }

        // online softmax (quad owns rows q, q+8)
        float rm0 = -1e30f, rm1 = -1e30f;
        #pragma unroll
        for (int nt = 0; nt < 8; nt++) {
            rm0 = fmaxf(rm0, fmaxf(S[nt][0], S[nt][1]));
            rm1 = fmaxf(rm1, fmaxf(S[nt][2], S[nt][3]));
        }
        rm0 = fmaxf(rm0, __shfl_xor_sync(0xffffffffu, rm0, 1));
        rm0 = fmaxf(rm0, __shfl_xor_sync(0xffffffffu, rm0, 2));
        rm1 = fmaxf(rm1, __shfl_xor_sync(0xffffffffu, rm1, 1));
        rm1 = fmaxf(rm1, __shfl_xor_sync(0xffffffffu, rm1, 2));
        float mn0 = fmaxf(m0r, rm0);
        float mn1 = fmaxf(m1r, rm1);

        float rs0 = 0.f, rs1 = 0.f;
        #pragma unroll
        for (int nt = 0; nt < 8; nt++) {
            float p0 = (S[nt][0] < -1e29f) ? 0.f : __expf(S[nt][0] - mn0);
            float p1 = (S[nt][1] < -1e29f) ? 0.f : __expf(S[nt][1] - mn0);
            float p2 = (S[nt][2] < -1e29f) ? 0.f : __expf(S[nt][2] - mn1);
            float p3 = (S[nt][3] < -1e29f) ? 0.f : __expf(S[nt][3] - mn1);
            S[nt][0] = p0; S[nt][1] = p1; S[nt][2] = p2; S[nt][3] = p3;
            rs0 += p0 + p1; rs1 += p2 + p3;
        }
        rs0 += __shfl_xor_sync(0xffffffffu, rs0, 1);
        rs0 += __shfl_xor_sync(0xffffffffu, rs0, 2);
        rs1 += __shfl_xor_sync(0xffffffffu, rs1, 1);
        rs1 += __shfl_xor_sync(0xffffffffu, rs1, 2);

        float alpha0 = __expf(m0r - mn0);
        float alpha1 = __expf(m1r - mn1);
        l0r = l0r * alpha0 + rs0;  m0r = mn0;
        l1r = l1r * alpha1 + rs1;  m1r = mn1;

        // pack P: C-frag -> PV A-frag, all thread-local
        uint32_t pp[8][2];
        #pragma unroll
        for (int nt = 0; nt < 8; nt++) {
            pp[nt][0] = packh2(S[nt][0], S[nt][1]);
            pp[nt][1] = packh2(S[nt][2], S[nt][3]);
            O[nt][0] *= alpha0; O[nt][1] *= alpha0;
            O[nt][2] *= alpha1; O[nt][3] *= alpha1;
        }

        // O += P.V
        #pragma unroll
        for (int nt = 0; nt < 8; nt++) {
            const uint32_t* vr = &Vs[(nt * 8 + q) * 36 + tq * 8];
            uint4 V1 = *(const uint4*)vr;
            uint4 V2 = *(const uint4*)(vr + 4);
            mma_f16(O[nt], pp[0][0], pp[0][1], pp[1][0], pp[1][1], V1.x, V1.y);
            mma_f16(O[nt], pp[2][0], pp[2][1], pp[3][0], pp[3][1], V1.z, V1.w);
            mma_f16(O[nt], pp[4][0], pp[4][1], pp[5][0], pp[5][1], V2.x, V2.y);
            mma_f16(O[nt], pp[6][0], pp[6][1], pp[7][0], pp[7][1], V2.z, V2.w);
        }
    }

    float inv0 = (l0r > 0.f) ? (1.f / l0r) : 0.f;
    float inv1 = (l1r > 0.f) ? (1.f / l1r) : 0.f;
    int r0 = qt * 128 + warp * 16 + q;
    size_t tok0 = (size_t)b * Lc + r0;
    size_t tok1 = tok0 + 8;
    #pragma unroll
    for (int nt = 0; nt < 8; nt++) {
        int n = h * 64 + nt * 8 + tq * 2;
        g_AO[tok0 * Dc + n]     = O[nt][0] * inv0 * g_G[tok0 * Dc + n];
        g_AO[tok0 * Dc + n + 1] = O[nt][1] * inv0 * g_G[tok0 * Dc + n + 1];
        g_AO[tok1 * Dc + n]     = O[nt][2] * inv1 * g_G[tok1 * Dc + n];
        g_AO[tok1 * Dc + n + 1] = O[nt][3] * inv1 * g_G[tok1 * Dc + n + 1];
    }
}

// ---- FP16 output projection GEMM, pipelined --------------------------------
__global__ __launch_bounds__(256) void out_gemm_tc(
    const float* __restrict__ Wo, const float* __restrict__ bo,
    float* __restrict__ out)
{
    const int m0 = blockIdx.y * 128;
    const int n0 = blockIdx.x * 64;

    __shared__ uint32_t As[128 * 16];
    __shared__ uint32_t Bs[64 * 16];

    const int tid  = threadIdx.x;
    const int warp = tid >> 5;
    const int lane = tid & 31;
    const int q    = lane >> 2;
    const int tq   = lane & 3;
    const int warpM0 = (warp >> 1) * 32;
    const int warpN0 = (warp & 1) * 32;

    float acc[2][4][4];
    #pragma unroll
    for (int mt = 0; mt < 2; mt++)
        #pragma unroll
        for (int nt = 0; nt < 4; nt++)
            #pragma unroll
            for (int e = 0; e < 4; e++) acc[mt][nt][e] = 0.f;

    float4 ra[4], rb[2];
    #pragma unroll
    for (int i = 0; i < 4; i++) {
        int f = tid + i * 256;
        ra[i] = *(const float4*)(g_AO + (size_t)(m0 + (f >> 3)) * Dc + (f & 7) * 4);
    }
    #pragma unroll
    for (int i = 0; i < 2; i++) {
        int f = tid + i * 256;
        rb[i] = *(const float4*)(Wo + (size_t)(n0 + (f >> 3)) * Dc + (f & 7) * 4);
    }

    for (int k0 = 0; k0 < Dc; k0 += KC) {
        __syncthreads();
        #pragma unroll
        for (int i = 0; i < 4; i++) {
            int f = tid + i * 256;
            int m = f >> 3, c = f & 7;
            int p = (c & 1) * 8 + (c >> 1);
            As[m * 16 + p]     = packh2(ra[i].x, ra[i].y);
            As[m * 16 + p + 4] = packh2(ra[i].z, ra[i].w);
        }
        #pragma unroll
        for (int i = 0; i < 2; i++) {
            int f = tid + i * 256;
            int n = f >> 3, c = f & 7;
            int p = (c & 1) * 8 + (c >> 1);
            Bs[n * 16 + p]     = packh2(rb[i].x, rb[i].y);
            Bs[n * 16 + p + 4] = packh2(rb[i].z, rb[i].w);
        }
        __syncthreads();

        if (k0 + KC < Dc) {
            #pragma unroll
            for (int i = 0; i < 4; i++) {
                int f = tid + i * 256;
                ra[i] = *(const float4*)(g_AO + (size_t)(m0 + (f >> 3)) * Dc + k0 + KC + (f & 7) * 4);
            }
            #pragma unroll
            for (int i = 0; i < 2; i++) {
                int f = tid + i * 256;
                rb[i] = *(const float4*)(Wo + (size_t)(n0 + (f >> 3)) * Dc + k0 + KC + (f & 7) * 4);
            }
        }

        uint4 Ar[2], Ar8[2];
        #pragma unroll
        for (int mt = 0; mt < 2; mt++) {
            int r = warpM0 + mt * 16 + q;
            Ar[mt]  = *(const uint4*)&As[r * 16 + tq * 4];
            Ar8[mt] = *(const uint4*)&As[(r + 8) * 16 + tq * 4];
        }
        #pragma unroll
        for (int nt = 0; nt < 4; nt++) {
            int n = warpN0 + nt * 8 + q;
            uint4 Bv = *(const uint4*)&Bs[n * 16 + tq * 4];
            #pragma unroll
            for (int mt = 0; mt < 2; mt++) {
                mma_f16(acc[mt][nt], Ar[mt].x, Ar8[mt].x, Ar[mt].y, Ar8[mt].y, Bv.x, Bv.y);
                mma_f16(acc[mt][nt], Ar[mt].z, Ar8[mt].z, Ar[mt].w, Ar8[mt].w, Bv.z, Bv.w);
            }
        }
    }

    #pragma unroll
    for (int mt = 0; mt < 2; mt++)
        #pragma unroll
        for (int nt = 0; nt < 4; nt++)
            #pragma unroll
            for (int e = 0; e < 4; e++) {
                int row = m0 + warpM0 + mt * 16 + q + ((e >> 1) ? 8 : 0);
                int col = n0 + warpN0 + nt * 8 + tq * 2 + (e & 1);
                out[(size_t)row * Dc + col] = acc[mt][nt][e] + bo[col];
            }
}

// ---- launch -----------------------------------------------------------------
extern "C" void kernel_launch(void* const* d_in, const int* in_sizes, int n_in,
                              void* d_out, int out_size)
{
    const float* query   = (const float*)d_in[0];
    const float* key_in  = (const float*)d_in[1];
    const float* value   = (const float*)d_in[2];
    const unsigned char* maskraw = (const unsigned char*)d_in[3];
    const float* rope_cos = (const float*)d_in[4];
    const float* rope_sin = (const float*)d_in[5];
    const float* Wq = (const float*)d_in[6];
    const float* bq = (const float*)d_in[7];
    const float* Wk = (const float*)d_in[8];
    const float* bk = (const float*)d_in[9];
    const float* Wv = (const float*)d_in[10];
    const float* bv = (const float*)d_in[11];
    const float* Wg = (const float*)d_in[12];
    const float* bg = (const float*)d_in[13];
    const float* Wo = (const float*)d_in[14];
    const float* bo = (const float*)d_in[15];
    float* out = (float*)d_out;

    (void)in_sizes; (void)n_in; (void)out_size;

    mask_decode_kernel<<<1, 1024>>>(maskraw);

    dim3 pg(Dc / 64, NT / 128, 4);
    proj_gemm_tc<<<pg, 256>>>(query, key_in, value,
                              Wq, bq, Wk, bk, Wv, bv, Wg, bg,
                              rope_cos, rope_sin);

    attn_tc_kernel<<<dim3(Lc / 128, BHc), 256>>>();

    out_gemm_tc<<<dim3(Dc / 64, NT / 128), 256>>>(Wo, bo, out);
}

// round 9
// speedup vs baseline: 1.8502x; 1.1158x over previous
#include <cuda_runtime.h>
#include <cuda_fp16.h>
#include <stdint.h>
#include <math.h>

#define Bc   2
#define Lc   2048
#define Dc   1024
#define Hc   16
#define NT   4096
#define BHc  32

// g_H: chunk-permuted half buffer. Segments (uint32 units):
//   [0)            query   4096x512
//   [SEG1)         key     4096x512
//   [SEG2)         value   4096x512
//   [SEGW + w*WS)  weights Wq,Wk,Wv,Wg,Wo each 1024x512
#define SEG1 (4096*512)
#define SEGW (3*4096*512)
#define WS   (1024*512)
__device__ uint32_t g_H[(size_t)(3*4096 + 5*1024)*512];
__device__ uint32_t g_Qh[(size_t)BHc*Lc*32];   // plain half-pair rows of 32
__device__ uint32_t g_Kh[(size_t)BHc*Lc*32];   // attn-permuted rows of 32
__device__ float    g_V [(size_t)BHc*Lc*64];
__device__ float    g_G [(size_t)NT*Dc];
__device__ uint32_t g_AOh[(size_t)NT*512];     // chunk-permuted half
__device__ int      g_mask[NT];

__device__ __forceinline__ uint32_t packh2(float a, float b) {
    __half2 h = __floats2half2_rn(a, b);
    return *reinterpret_cast<uint32_t*>(&h);
}
__device__ __forceinline__ void mma_f16(
    float* d, uint32_t a0, uint32_t a1, uint32_t a2, uint32_t a3,
    uint32_t b0, uint32_t b1)
{
    asm volatile(
        "mma.sync.aligned.m16n8k16.row.col.f32.f16.f16.f32 "
        "{%0,%1,%2,%3}, {%4,%5,%6,%7}, {%8,%9}, {%0,%1,%2,%3};\n"
        : "+f"(d[0]), "+f"(d[1]), "+f"(d[2]), "+f"(d[3])
        : "r"(a0), "r"(a1), "r"(a2), "r"(a3), "r"(b0), "r"(b1));
}
__device__ __forceinline__ void cpa16(uint32_t dst, const void* src) {
    asm volatile("cp.async.ca.shared.global [%0], [%1], 16;"
                 :: "r"(dst), "l"(src) : "memory");
}
#define CPA_COMMIT() asm volatile("cp.async.commit_group;" ::: "memory")
#define CPA_WAIT1()  asm volatile("cp.async.wait_group 1;" ::: "memory")

__global__ void mask_decode_kernel(const unsigned char* __restrict__ raw) {
    __shared__ int cnt[4];
    int tid = threadIdx.x;
    if (tid < 4) cnt[tid] = 0;
    __syncthreads();
    for (int i = tid; i < NT; i += blockDim.x)
        if (raw[i]) atomicAdd(&cnt[i & 3], 1);
    __syncthreads();
    int c0 = cnt[0], c1 = cnt[1], c2 = cnt[2], c3 = cnt[3];
    int mode;
    if (c0 > 0 && c1 == 0 && c2 == 0 && c3 == 0)       mode = 1;
    else if ((c2 > 0 || c3 > 0) && c0 == 0 && c1 == 0) mode = 2;
    else                                               mode = 0;
    for (int i = tid; i < NT; i += blockDim.x) {
        int v;
        if (mode == 0)      v = (raw[i] != 0);
        else if (mode == 1) v = (((const int*)raw)[i] != 0);
        else                v = (((const float*)raw)[i] != 0.0f);
        g_mask[i] = v;
    }
}

// ---- prep: float -> chunk-permuted half (matches GEMM smem layout) ---------
__global__ void prep_half(
    const float* __restrict__ q, const float* __restrict__ k,
    const float* __restrict__ v,
    const float* __restrict__ wq, const float* __restrict__ wk,
    const float* __restrict__ wv, const float* __restrict__ wg,
    const float* __restrict__ wo)
{
    int z = blockIdx.z, row = blockIdx.x, t = threadIdx.x;
    const float* src; size_t off;
    if (z < 3) {
        src = (z == 0) ? q : ((z == 1) ? k : v);
        off = (size_t)z * SEG1;
    } else {
        if (row >= 1024) return;
        src = (z == 3) ? wq : ((z == 4) ? wk : ((z == 5) ? wv : ((z == 6) ? wg : wo)));
        off = (size_t)SEGW + (size_t)(z - 3) * WS;
    }
    float4 val = ((const float4*)src)[(size_t)row * 256 + t];
    int ch = t >> 3, c = t & 7;
    uint32_t* dst = g_H + off + (size_t)row * 512 + ch * 16 + (c & 1) * 8 + (c >> 1);
    dst[0] = packh2(val.x, val.y);
    dst[4] = packh2(val.z, val.w);
}

// ---- FP16 projection GEMM, cp.async double-buffered, fused RoPE ------------
__global__ __launch_bounds__(256) void proj_gemm_tc(
    const float* __restrict__ bq, const float* __restrict__ bk,
    const float* __restrict__ bv, const float* __restrict__ bg,
    const float* __restrict__ cosb, const float* __restrict__ sinb)
{
    const int z = blockIdx.z;
    const uint32_t* Ag  = g_H + ((z == 3) ? 0 : (size_t)z * SEG1);
    const uint32_t* Wgp = g_H + SEGW + (size_t)z * WS;
    const float* bias = (z == 0) ? bq : ((z == 1) ? bk : ((z == 2) ? bv : bg));

    const int m0 = blockIdx.y * 128;
    const int n0 = blockIdx.x * 64;

    __shared__ uint32_t As[2][128 * 16];
    __shared__ uint32_t Bs[2][64 * 16];

    const int tid  = threadIdx.x;
    const int warp = tid >> 5;
    const int lane = tid & 31;
    const int q    = lane >> 2;
    const int tq   = lane & 3;
    const int warpM0 = (warp >> 1) * 32;
    const int colbase = (warp & 1) * 16;

    float acc[2][4][4];
    #pragma unroll
    for (int mt = 0; mt < 2; mt++)
        #pragma unroll
        for (int nt = 0; nt < 4; nt++)
            #pragma unroll
            for (int e = 0; e < 4; e++) acc[mt][nt][e] = 0.f;

    auto copyt = [&](int kc, int buf) {
        uint32_t sA = (uint32_t)__cvta_generic_to_shared(&As[buf][0]);
        uint32_t sB = (uint32_t)__cvta_generic_to_shared(&Bs[buf][0]);
        #pragma unroll
        for (int i = 0; i < 2; i++) {
            int idx = tid + i * 256;
            int m = idx >> 2, u = idx & 3;
            cpa16(sA + (m * 16 + u * 4) * 4,
                  (const uint4*)(Ag + (size_t)(m0 + m) * 512 + kc * 16) + u);
        }
        {
            int n = tid >> 2, u = tid & 3;
            cpa16(sB + (n * 16 + u * 4) * 4,
                  (const uint4*)(Wgp + (size_t)(n0 + n) * 512 + kc * 16) + u);
        }
    };

    copyt(0, 0); CPA_COMMIT();
    copyt(1, 1); CPA_COMMIT();

    for (int it = 0; it < 32; it++) {
        CPA_WAIT1();
        __syncthreads();
        int buf = it & 1;

        uint4 Ar[2], Ar8[2];
        #pragma unroll
        for (int mt = 0; mt < 2; mt++) {
            int r = warpM0 + mt * 16 + q;
            Ar[mt]  = *(const uint4*)&As[buf][r * 16 + tq * 4];
            Ar8[mt] = *(const uint4*)&As[buf][(r + 8) * 16 + tq * 4];
        }
        #pragma unroll
        for (int nt = 0; nt < 4; nt++) {
            int n = colbase + (nt & 1) * 8 + (nt >> 1) * 32 + q;
            uint4 Bv = *(const uint4*)&Bs[buf][n * 16 + tq * 4];
            #pragma unroll
            for (int mt = 0; mt < 2; mt++) {
                mma_f16(acc[mt][nt], Ar[mt].x, Ar8[mt].x, Ar[mt].y, Ar8[mt].y, Bv.x, Bv.y);
                mma_f16(acc[mt][nt], Ar[mt].z, Ar8[mt].z, Ar[mt].w, Ar8[mt].w, Bv.z, Bv.w);
            }
        }
        __syncthreads();
        if (it + 2 < 32) copyt(it + 2, buf);
        CPA_COMMIT();
    }

    // epilogue: bias + rope; pack (cl,cl+1) pairs for half outputs
    const int h = n0 >> 6;
    #pragma unroll
    for (int mt = 0; mt < 2; mt++)
        #pragma unroll
        for (int nt = 0; nt < 2; nt++) {
            int cl0 = colbase + nt * 8 + tq * 2;
            float y1[4], y2[4];
            #pragma unroll
            for (int e = 0; e < 4; e++) {
                int row = m0 + warpM0 + mt * 16 + q + ((e >> 1) ? 8 : 0);
                int l = row & (Lc - 1);
                int cl = cl0 + (e & 1);
                float x1 = acc[mt][nt][e]     + bias[n0 + cl];
                float x2 = acc[mt][nt + 2][e] + bias[n0 + cl + 32];
                if (z <= 1) {
                    float c1 = cosb[l * 64 + cl],      s1 = sinb[l * 64 + cl];
                    float c2 = cosb[l * 64 + cl + 32], s2 = sinb[l * 64 + cl + 32];
                    y1[e] = x1 * c1 - x2 * s1;
                    y2[e] = x2 * c2 + x1 * s2;
                } else { y1[e] = x1; y2[e] = x2; }
            }
            #pragma unroll
            for (int h2 = 0; h2 < 2; h2++) {
                int row = m0 + warpM0 + mt * 16 + q + h2 * 8;
                int b = row >> 11, l = row & (Lc - 1);
                if (z == 3) {
                    size_t rb = (size_t)row * Dc + n0;
                    g_G[rb + cl0]      = 1.f / (1.f + __expf(-y1[2*h2]));
                    g_G[rb + cl0 + 1]  = 1.f / (1.f + __expf(-y1[2*h2+1]));
                    g_G[rb + cl0 + 32] = 1.f / (1.f + __expf(-y2[2*h2]));
                    g_G[rb + cl0 + 33] = 1.f / (1.f + __expf(-y2[2*h2+1]));
                } else if (z == 2) {
                    size_t base = ((size_t)(b * Hc + h) * Lc + l) * 64;
                    g_V[base + cl0]      = y1[2*h2];
                    g_V[base + cl0 + 1]  = y1[2*h2+1];
                    g_V[base + cl0 + 32] = y2[2*h2];
                    g_V[base + cl0 + 33] = y2[2*h2+1];
                } else {
                    size_t drow = ((size_t)(b * Hc + h) * Lc + l) * 32;
                    uint32_t p1 = packh2(y1[2*h2], y1[2*h2+1]);
                    uint32_t p2 = packh2(y2[2*h2], y2[2*h2+1]);
                    int j1 = cl0 >> 1;
                    if (z == 0) {
                        g_Qh[drow + j1]      = p1;
                        g_Qh[drow + j1 + 16] = p2;
                    } else {
                        int pos = (j1 & 3) * 8 + (j1 >> 2);
                        g_Kh[drow + pos]     = p1;
                        g_Kh[drow + pos + 4] = p2;
                    }
                }
            }
        }
}

// ---- FP16 flash attention; K raw-copied, P in registers --------------------
__global__ __launch_bounds__(256, 2) void attn_tc_kernel()
{
    __shared__ uint32_t Ks[64 * 36];
    __shared__ uint32_t Vs[64 * 36];
    __shared__ float mk[64];

    const int qt  = blockIdx.x;
    const int bh  = blockIdx.y;
    const int b   = bh >> 4;
    const int h   = bh & 15;
    const int tid = threadIdx.x;
    const int warp = tid >> 5;
    const int lane = tid & 31;
    const int q    = lane >> 2;
    const int tq   = lane & 3;

    const uint32_t* Qg32 = g_Qh + ((size_t)bh * Lc + qt * 128 + warp * 16 + q) * 32;
    uint32_t qf[4][4];
    #pragma unroll
    for (int s = 0; s < 4; s++) {
        qf[s][0] = Qg32[8*s + tq];
        qf[s][1] = Qg32[256 + 8*s + tq];
        qf[s][2] = Qg32[8*s + tq + 4];
        qf[s][3] = Qg32[256 + 8*s + tq + 4];
    }

    float O[8][4];
    #pragma unroll
    for (int nt = 0; nt < 8; nt++)
        #pragma unroll
        for (int e = 0; e < 4; e++) O[nt][e] = 0.f;
    float m0r = -1e30f, m1r = -1e30f, l0r = 0.f, l1r = 0.f;

    const int* maskb = g_mask + b * Lc;
    const int vn = tid >> 2, vt2 = tid & 3;

    for (int kt = 0; kt < 32; kt++) {
        __syncthreads();
        const uint4* Kg4 = (const uint4*)(g_Kh + ((size_t)bh * Lc + kt * 64) * 32);
        const float* Vg  = g_V + ((size_t)bh * Lc + kt * 64) * 64;

        #pragma unroll
        for (int i2 = 0; i2 < 2; i2++) {
            int f = tid + i2 * 256;
            int n = f >> 3, u = f & 7;
            *(uint4*)&Ks[n * 36 + u * 4] = Kg4[n * 8 + u];
        }
        {
            uint32_t vr[8];
            #pragma unroll
            for (int i = 0; i < 8; i++)
                vr[i] = packh2(Vg[(8*i + 2*vt2) * 64 + vn],
                               Vg[(8*i + 2*vt2 + 1) * 64 + vn]);
            uint32_t* dst = &Vs[vn * 36 + vt2 * 8];
            *(uint4*)dst       = make_uint4(vr[0], vr[1], vr[2], vr[3]);
            *(uint4*)(dst + 4) = make_uint4(vr[4], vr[5], vr[6], vr[7]);
        }
        if (tid < 64) mk[tid] = maskb[kt * 64 + tid] ? -1e30f : 0.f;
        __syncthreads();

        float S[8][4];
        #pragma unroll
        for (int nt = 0; nt < 8; nt++)
            #pragma unroll
            for (int e = 0; e < 4; e++) S[nt][e] = 0.f;
        #pragma unroll
        for (int nt = 0; nt < 8; nt++) {
            const uint32_t* kr = &Ks[(nt * 8 + q) * 36 + tq * 8];
            uint4 B1 = *(const uint4*)kr;
            uint4 B2 = *(const uint4*)(kr + 4);
            mma_f16(S[nt], qf[0][0], qf[0][1], qf[0][2], qf[0][3], B1.x, B1.y);
            mma_f16(S[nt], qf[1][0], qf[1][1], qf[1][2], qf[1][3], B1.z, B1.w);
            mma_f16(S[nt], qf[2][0], qf[2][1], qf[2][2], qf[2][3], B2.x, B2.y);
            mma_f16(S[nt], qf[3][0], qf[3][1], qf[3][2], qf[3][3], B2.z, B2.w);
        }

        #pragma unroll
        for (int nt = 0; nt < 8; nt++) {
            float mq0 = mk[nt * 8 + tq * 2];
            float mq1 = mk[nt * 8 + tq * 2 + 1];
            S[nt][0] = S[nt][0] * 0.125f + mq0;
            S[nt][1] = S[nt][1] * 0.125f + mq1;
            S[nt][2] = S[nt][2] * 0.125f + mq0;
            S[nt][3] = S[nt][3] * 0.125f + mq1;
        }

        float rm0 = -1e30f, rm1 = -1e30f;
        #pragma unroll
        for (int nt = 0; nt < 8; nt++) {
            rm0 = fmaxf(rm0, fmaxf(S[nt][0], S[nt][1]));
            rm1 = fmaxf(rm1, fmaxf(S[nt][2], S[nt][3]));
        }
        rm0 = fmaxf(rm0, __shfl_xor_sync(0xffffffffu, rm0, 1));
        rm0 = fmaxf(rm0, __shfl_xor_sync(0xffffffffu, rm0, 2));
        rm1 = fmaxf(rm1, __shfl_xor_sync(0xffffffffu, rm1, 1));
        rm1 = fmaxf(rm1, __shfl_xor_sync(0xffffffffu, rm1, 2));
        float mn0 = fmaxf(m0r, rm0);
        float mn1 = fmaxf(m1r, rm1);

        float rs0 = 0.f, rs1 = 0.f;
        #pragma unroll
        for (int nt = 0; nt < 8; nt++) {
            float p0 = (S[nt][0] < -1e29f) ? 0.f : __expf(S[nt][0] - mn0);
            float p1 = (S[nt][1] < -1e29f) ? 0.f : __expf(S[nt][1] - mn0);
            float p2 = (S[nt][2] < -1e29f) ? 0.f : __expf(S[nt][2] - mn1);
            float p3 = (S[nt][3] < -1e29f) ? 0.f : __expf(S[nt][3] - mn1);
            S[nt][0] = p0; S[nt][1] = p1; S[nt][2] = p2; S[nt][3] = p3;
            rs0 += p0 + p1; rs1 += p2 + p3;
        }
        rs0 += __shfl_xor_sync(0xffffffffu, rs0, 1);
        rs0 += __shfl_xor_sync(0xffffffffu, rs0, 2);
        rs1 += __shfl_xor_sync(0xffffffffu, rs1, 1);
        rs1 += __shfl_xor_sync(0xffffffffu, rs1, 2);

        float alpha0 = __expf(m0r - mn0);
        float alpha1 = __expf(m1r - mn1);
        l0r = l0r * alpha0 + rs0;  m0r = mn0;
        l1r = l1r * alpha1 + rs1;  m1r = mn1;

        uint32_t pp[8][2];
        #pragma unroll
        for (int nt = 0; nt < 8; nt++) {
            pp[nt][0] = packh2(S[nt][0], S[nt][1]);
            pp[nt][1] = packh2(S[nt][2], S[nt][3]);
            O[nt][0] *= alpha0; O[nt][1] *= alpha0;
            O[nt][2] *= alpha1; O[nt][3] *= alpha1;
        }

        #pragma unroll
        for (int nt = 0; nt < 8; nt++) {
            const uint32_t* vr = &Vs[(nt * 8 + q) * 36 + tq * 8];
            uint4 V1 = *(const uint4*)vr;
            uint4 V2 = *(const uint4*)(vr + 4);
            mma_f16(O[nt], pp[0][0], pp[0][1], pp[1][0], pp[1][1], V1.x, V1.y);
            mma_f16(O[nt], pp[2][0], pp[2][1], pp[3][0], pp[3][1], V1.z, V1.w);
            mma_f16(O[nt], pp[4][0], pp[4][1], pp[5][0], pp[5][1], V2.x, V2.y);
            mma_f16(O[nt], pp[6][0], pp[6][1], pp[7][0], pp[7][1], V2.z, V2.w);
        }
    }

    float inv0 = (l0r > 0.f) ? (1.f / l0r) : 0.f;
    float inv1 = (l1r > 0.f) ? (1.f / l1r) : 0.f;
    int r0 = qt * 128 + warp * 16 + q;
    size_t tok0 = (size_t)b * Lc + r0;
    size_t tok1 = tok0 + 8;
    #pragma unroll
    for (int nt = 0; nt < 8; nt++) {
        int n = h * 64 + nt * 8 + tq * 2;
        float o0 = O[nt][0] * inv0 * g_G[tok0 * Dc + n];
        float o1 = O[nt][1] * inv0 * g_G[tok0 * Dc + n + 1];
        float o2 = O[nt][2] * inv1 * g_G[tok1 * Dc + n];
        float o3 = O[nt][3] * inv1 * g_G[tok1 * Dc + n + 1];
        int J = n >> 1, chnk = J >> 4, jj = J & 15;
        int pos = (jj >> 2) + (jj & 1) * 4 + ((jj >> 1) & 1) * 8;
        g_AOh[tok0 * 512 + chnk * 16 + pos] = packh2(o0, o1);
        g_AOh[tok1 * 512 + chnk * 16 + pos] = packh2(o2, o3);
    }
}

// ---- FP16 output projection GEMM, cp.async double-buffered -----------------
__global__ __launch_bounds__(256) void out_gemm_tc(
    const float* __restrict__ bo, float* __restrict__ out)
{
    const uint32_t* Ag  = g_AOh;
    const uint32_t* Wgp = g_H + SEGW + (size_t)4 * WS;

    const int m0 = blockIdx.y * 128;
    const int n0 = blockIdx.x * 64;

    __shared__ uint32_t As[2][128 * 16];
    __shared__ uint32_t Bs[2][64 * 16];

    const int tid  = threadIdx.x;
    const int warp = tid >> 5;
    const int lane = tid & 31;
    const int q    = lane >> 2;
    const int tq   = lane & 3;
    const int warpM0 = (warp >> 1) * 32;
    const int warpN0 = (warp & 1) * 32;

    float acc[2][4][4];
    #pragma unroll
    for (int mt = 0; mt < 2; mt++)
        #pragma unroll
        for (int nt = 0; nt < 4; nt++)
            #pragma unroll
            for (int e = 0; e < 4; e++) acc[mt][nt][e] = 0.f;

    auto copyt = [&](int kc, int buf) {
        uint32_t sA = (uint32_t)__cvta_generic_to_shared(&As[buf][0]);
        uint32_t sB = (uint32_t)__cvta_generic_to_shared(&Bs[buf][0]);
        #pragma unroll
        for (int i = 0; i < 2; i++) {
            int idx = tid + i * 256;
            int m = idx >> 2, u = idx & 3;
            cpa16(sA + (m * 16 + u * 4) * 4,
                  (const uint4*)(Ag + (size_t)(m0 + m) * 512 + kc * 16) + u);
        }
        {
            int n = tid >> 2, u = tid & 3;
            cpa16(sB + (n * 16 + u * 4) * 4,
                  (const uint4*)(Wgp + (size_t)(n0 + n) * 512 + kc * 16) + u);
        }
    };

    copyt(0, 0); CPA_COMMIT();
    copyt(1, 1); CPA_COMMIT();

    for (int it = 0; it < 32; it++) {
        CPA_WAIT1();
        __syncthreads();
        int buf = it & 1;

        uint4 Ar[2], Ar8[2];
        #pragma unroll
        for (int mt = 0; mt < 2; mt++) {
            int r = warpM0 + mt * 16 + q;
            Ar[mt]  = *(const uint4*)&As[buf][r * 16 + tq * 4];
            Ar8[mt] = *(const uint4*)&As[buf][(r + 8) * 16 + tq * 4];
        }
        #pragma unroll
        for (int nt = 0; nt < 4; nt++) {
            int n = warpN0 + nt * 8 + q;
            uint4 Bv = *(const uint4*)&Bs[buf][n * 16 + tq * 4];
            #pragma unroll
            for (int mt = 0; mt < 2; mt++) {
                mma_f16(acc[mt][nt], Ar[mt].x, Ar8[mt].x, Ar[mt].y, Ar8[mt].y, Bv.x, Bv.y);
                mma_f16(acc[mt][nt], Ar[mt].z, Ar8[mt].z, Ar[mt].w, Ar8[mt].w, Bv.z, Bv.w);
            }
        }
        __syncthreads();
        if (it + 2 < 32) copyt(it + 2, buf);
        CPA_COMMIT();
    }

    #pragma unroll
    for (int mt = 0; mt < 2; mt++)
        #pragma unroll
        for (int nt = 0; nt < 4; nt++)
            #pragma unroll
            for (int e = 0; e < 4; e++) {
                int row = m0 + warpM0 + mt * 16 + q + ((e >> 1) ? 8 : 0);
                int col = n0 + warpN0 + nt * 8 + tq * 2 + (e & 1);
                out[(size_t)row * Dc + col] = acc[mt][nt][e] + bo[col];
            }
}

// ---- launch -----------------------------------------------------------------
extern "C" void kernel_launch(void* const* d_in, const int* in_sizes, int n_in,
                              void* d_out, int out_size)
{
    const float* query   = (const float*)d_in[0];
    const float* key_in  = (const float*)d_in[1];
    const float* value   = (const float*)d_in[2];
    const unsigned char* maskraw = (const unsigned char*)d_in[3];
    const float* rope_cos = (const float*)d_in[4];
    const float* rope_sin = (const float*)d_in[5];
    const float* Wq = (const float*)d_in[6];
    const float* bq = (const float*)d_in[7];
    const float* Wk = (const float*)d_in[8];
    const float* bk = (const float*)d_in[9];
    const float* Wv = (const float*)d_in[10];
    const float* bv = (const float*)d_in[11];
    const float* Wg = (const float*)d_in[12];
    const float* bg = (const float*)d_in[13];
    const float* Wo = (const float*)d_in[14];
    const float* bo = (const float*)d_in[15];
    float* out = (float*)d_out;

    (void)in_sizes; (void)n_in; (void)out_size;

    mask_decode_kernel<<<1, 1024>>>(maskraw);
    prep_half<<<dim3(4096, 1, 8), 256>>>(query, key_in, value, Wq, Wk, Wv, Wg, Wo);
    proj_gemm_tc<<<dim3(16, 32, 4), 256>>>(bq, bk, bv, bg, rope_cos, rope_sin);
    attn_tc_kernel<<<dim3(16, 32), 256>>>();
    out_gemm_tc<<<dim3(16, 32), 256>>>(bo, out);
}

// round 11
// speedup vs baseline: 2.1061x; 1.1383x over previous
#include <cuda_runtime.h>
#include <cuda_fp16.h>
#include <stdint.h>
#include <math.h>

#define Bc   2
#define Lc   2048
#define Dc   1024
#define Hc   16
#define NT   4096
#define BHc  32

#define SEG1 (4096*512)
#define SEGW (3*4096*512)
#define WS   (1024*512)
__device__ uint32_t g_H[(size_t)(3*4096 + 5*1024)*512];
__device__ uint32_t g_Qh[(size_t)BHc*Lc*32];     // plain half-pair rows of 32
__device__ uint32_t g_Kh[(size_t)BHc*Lc*32];     // attn-permuted rows of 32
__device__ __half   g_Vth[(size_t)BHc*32*64*64]; // attn-smem-image half V
__device__ float    g_G [(size_t)NT*Dc];
__device__ uint32_t g_AOh[(size_t)NT*512];       // chunk-permuted half
__device__ int      g_mask[NT];

__device__ __forceinline__ uint32_t packh2(float a, float b) {
    __half2 h = __floats2half2_rn(a, b);
    return *reinterpret_cast<uint32_t*>(&h);
}
__device__ __forceinline__ float ex2f(float x) {
    float y;
    asm("ex2.approx.f32 %0, %1;" : "=f"(y) : "f"(x));
    return y;
}
__device__ __forceinline__ void mma_f16(
    float* d, uint32_t a0, uint32_t a1, uint32_t a2, uint32_t a3,
    uint32_t b0, uint32_t b1)
{
    asm volatile(
        "mma.sync.aligned.m16n8k16.row.col.f32.f16.f16.f32 "
        "{%0,%1,%2,%3}, {%4,%5,%6,%7}, {%8,%9}, {%0,%1,%2,%3};\n"
        : "+f"(d[0]), "+f"(d[1]), "+f"(d[2]), "+f"(d[3])
        : "r"(a0), "r"(a1), "r"(a2), "r"(a3), "r"(b0), "r"(b1));
}
__device__ __forceinline__ void cpa16(uint32_t dst, const void* src) {
    asm volatile("cp.async.ca.shared.global [%0], [%1], 16;"
                 :: "r"(dst), "l"(src) : "memory");
}
#define CPA_COMMIT() asm volatile("cp.async.commit_group;" ::: "memory")
#define CPA_WAIT1()  asm volatile("cp.async.wait_group 1;" ::: "memory")

__global__ void mask_decode_kernel(const unsigned char* __restrict__ raw) {
    __shared__ int cnt[4];
    int tid = threadIdx.x;
    if (tid < 4) cnt[tid] = 0;
    __syncthreads();
    for (int i = tid; i < NT; i += blockDim.x)
        if (raw[i]) atomicAdd(&cnt[i & 3], 1);
    __syncthreads();
    int c0 = cnt[0], c1 = cnt[1], c2 = cnt[2], c3 = cnt[3];
    int mode;
    if (c0 > 0 && c1 == 0 && c2 == 0 && c3 == 0)       mode = 1;
    else if ((c2 > 0 || c3 > 0) && c0 == 0 && c1 == 0) mode = 2;
    else                                               mode = 0;
    for (int i = tid; i < NT; i += blockDim.x) {
        int v;
        if (mode == 0)      v = (raw[i] != 0);
        else if (mode == 1) v = (((const int*)raw)[i] != 0);
        else                v = (((const float*)raw)[i] != 0.0f);
        g_mask[i] = v;
    }
}

__global__ void prep_half(
    const float* __restrict__ q, const float* __restrict__ k,
    const float* __restrict__ v,
    const float* __restrict__ wq, const float* __restrict__ wk,
    const float* __restrict__ wv, const float* __restrict__ wg,
    const float* __restrict__ wo)
{
    int z = blockIdx.z, row = blockIdx.x, t = threadIdx.x;
    const float* src; size_t off;
    if (z < 3) {
        src = (z == 0) ? q : ((z == 1) ? k : v);
        off = (size_t)z * SEG1;
    } else {
        if (row >= 1024) return;
        src = (z == 3) ? wq : ((z == 4) ? wk : ((z == 5) ? wv : ((z == 6) ? wg : wo)));
        off = (size_t)SEGW + (size_t)(z - 3) * WS;
    }
    float4 val = ((const float4*)src)[(size_t)row * 256 + t];
    int ch = t >> 3, c = t & 7;
    uint32_t* dst = g_H + off + (size_t)row * 512 + ch * 16 + (c & 1) * 8 + (c >> 1);
    dst[0] = packh2(val.x, val.y);
    dst[4] = packh2(val.z, val.w);
}

// ---- FP16 projection GEMM, cp.async double-buffered, fused RoPE ------------
__global__ __launch_bounds__(256) void proj_gemm_tc(
    const float* __restrict__ bq, const float* __restrict__ bk,
    const float* __restrict__ bv, const float* __restrict__ bg,
    const float* __restrict__ cosb, const float* __restrict__ sinb)
{
    const int z = blockIdx.z;
    const uint32_t* Ag  = g_H + ((z == 3) ? 0 : (size_t)z * SEG1);
    const uint32_t* Wgp = g_H + SEGW + (size_t)z * WS;
    const float* bias = (z == 0) ? bq : ((z == 1) ? bk : ((z == 2) ? bv : bg));

    const int m0 = blockIdx.y * 128;
    const int n0 = blockIdx.x * 64;

    __shared__ uint32_t As[2][128 * 16];
    __shared__ uint32_t Bs[2][64 * 16];

    const int tid  = threadIdx.x;
    const int warp = tid >> 5;
    const int lane = tid & 31;
    const int q    = lane >> 2;
    const int tq   = lane & 3;
    const int warpM0 = (warp >> 1) * 32;
    const int colbase = (warp & 1) * 16;

    float acc[2][4][4];
    #pragma unroll
    for (int mt = 0; mt < 2; mt++)
        #pragma unroll
        for (int nt = 0; nt < 4; nt++)
            #pragma unroll
            for (int e = 0; e < 4; e++) acc[mt][nt][e] = 0.f;

    auto copyt = [&](int kc, int buf) {
        uint32_t sA = (uint32_t)__cvta_generic_to_shared(&As[buf][0]);
        uint32_t sB = (uint32_t)__cvta_generic_to_shared(&Bs[buf][0]);
        #pragma unroll
        for (int i = 0; i < 2; i++) {
            int idx = tid + i * 256;
            int m = idx >> 2, u = idx & 3;
            cpa16(sA + (m * 16 + u * 4) * 4,
                  (const uint4*)(Ag + (size_t)(m0 + m) * 512 + kc * 16) + u);
        }
        {
            int n = tid >> 2, u = tid & 3;
            cpa16(sB + (n * 16 + u * 4) * 4,
                  (const uint4*)(Wgp + (size_t)(n0 + n) * 512 + kc * 16) + u);
        }
    };

    copyt(0, 0); CPA_COMMIT();
    copyt(1, 1); CPA_COMMIT();

    for (int it = 0; it < 32; it++) {
        CPA_WAIT1();
        __syncthreads();
        int buf = it & 1;

        uint4 Ar[2], Ar8[2];
        #pragma unroll
        for (int mt = 0; mt < 2; mt++) {
            int r = warpM0 + mt * 16 + q;
            Ar[mt]  = *(const uint4*)&As[buf][r * 16 + tq * 4];
            Ar8[mt] = *(const uint4*)&As[buf][(r + 8) * 16 + tq * 4];
        }
        #pragma unroll
        for (int nt = 0; nt < 4; nt++) {
            int n = colbase + (nt & 1) * 8 + (nt >> 1) * 32 + q;
            uint4 Bv = *(const uint4*)&Bs[buf][n * 16 + tq * 4];
            #pragma unroll
            for (int mt = 0; mt < 2; mt++) {
                mma_f16(acc[mt][nt], Ar[mt].x, Ar8[mt].x, Ar[mt].y, Ar8[mt].y, Bv.x, Bv.y);
                mma_f16(acc[mt][nt], Ar[mt].z, Ar8[mt].z, Ar[mt].w, Ar8[mt].w, Bv.z, Bv.w);
            }
        }
        __syncthreads();
        if (it + 2 < 32) copyt(it + 2, buf);
        CPA_COMMIT();
    }

    const int h = n0 >> 6;
    #pragma unroll
    for (int mt = 0; mt < 2; mt++)
        #pragma unroll
        for (int nt = 0; nt < 2; nt++) {
            int cl0 = colbase + nt * 8 + tq * 2;
            float y1[4], y2[4];
            #pragma unroll
            for (int e = 0; e < 4; e++) {
                int row = m0 + warpM0 + mt * 16 + q + ((e >> 1) ? 8 : 0);
                int l = row & (Lc - 1);
                int cl = cl0 + (e & 1);
                float x1 = acc[mt][nt][e]     + bias[n0 + cl];
                float x2 = acc[mt][nt + 2][e] + bias[n0 + cl + 32];
                if (z <= 1) {
                    float c1 = cosb[l * 64 + cl],      s1 = sinb[l * 64 + cl];
                    float c2 = cosb[l * 64 + cl + 32], s2 = sinb[l * 64 + cl + 32];
                    y1[e] = x1 * c1 - x2 * s1;
                    y2[e] = x2 * c2 + x1 * s2;
                } else { y1[e] = x1; y2[e] = x2; }
            }
            #pragma unroll
            for (int h2 = 0; h2 < 2; h2++) {
                int row = m0 + warpM0 + mt * 16 + q + h2 * 8;
                int b = row >> 11, l = row & (Lc - 1);
                if (z == 3) {
                    size_t rb = (size_t)row * Dc + n0;
                    g_G[rb + cl0]      = 1.f / (1.f + __expf(-y1[2*h2]));
                    g_G[rb + cl0 + 1]  = 1.f / (1.f + __expf(-y1[2*h2+1]));
                    g_G[rb + cl0 + 32] = 1.f / (1.f + __expf(-y2[2*h2]));
                    g_G[rb + cl0 + 33] = 1.f / (1.f + __expf(-y2[2*h2+1]));
                } else if (z == 2) {
                    int kt2 = l >> 6, tk = l & 63, jp = tk >> 1;
                    int hoff = ((jp & 3) * 8 + (jp >> 2)) * 2 + (tk & 1);
                    __half* vrow = g_Vth + (((size_t)(b * Hc + h) * 32 + kt2) * 64) * 64;
                    vrow[(size_t)(cl0)      * 64 + hoff] = __float2half(y1[2*h2]);
                    vrow[(size_t)(cl0 + 1)  * 64 + hoff] = __float2half(y1[2*h2+1]);
                    vrow[(size_t)(cl0 + 32) * 64 + hoff] = __float2half(y2[2*h2]);
                    vrow[(size_t)(cl0 + 33) * 64 + hoff] = __float2half(y2[2*h2+1]);
                } else {
                    size_t drow = ((size_t)(b * Hc + h) * Lc + l) * 32;
                    uint32_t p1 = packh2(y1[2*h2], y1[2*h2+1]);
                    uint32_t p2 = packh2(y2[2*h2], y2[2*h2+1]);
                    int j1 = cl0 >> 1;
                    if (z == 0) {
                        g_Qh[drow + j1]      = p1;
                        g_Qh[drow + j1 + 16] = p2;
                    } else {
                        int pos = (j1 & 3) * 8 + (j1 >> 2);
                        g_Kh[drow + pos]     = p1;
                        g_Kh[drow + pos + 4] = p2;
                    }
                }
            }
        }
}

// ---- FP16 flash attention: cp.async double-buffered K/V, exp2 softmax ------
__global__ __launch_bounds__(256, 2) void attn_tc_kernel()
{
    __shared__ uint32_t Ks[2][64 * 36];
    __shared__ uint32_t Vs[2][64 * 36];
    __shared__ float mk[2][64];

    const int qt  = blockIdx.x;
    const int bh  = blockIdx.y;
    const int b   = bh >> 4;
    const int h   = bh & 15;
    const int tid = threadIdx.x;
    const int warp = tid >> 5;
    const int lane = tid & 31;
    const int q    = lane >> 2;
    const int tq   = lane & 3;

    const uint32_t* Qg32 = g_Qh + ((size_t)bh * Lc + qt * 128 + warp * 16 + q) * 32;
    uint32_t qf[4][4];
    #pragma unroll
    for (int s = 0; s < 4; s++) {
        qf[s][0] = Qg32[8*s + tq];
        qf[s][1] = Qg32[256 + 8*s + tq];
        qf[s][2] = Qg32[8*s + tq + 4];
        qf[s][3] = Qg32[256 + 8*s + tq + 4];
    }

    float O[8][4];
    #pragma unroll
    for (int nt = 0; nt < 8; nt++)
        #pragma unroll
        for (int e = 0; e < 4; e++) O[nt][e] = 0.f;
    float m0r = -1e30f, m1r = -1e30f, l0r = 0.f, l1r = 0.f;
    const float Cs = 0.18033688011112158f;   // 0.125 * log2(e)

    const int* maskb = g_mask + b * Lc;

    auto issue = [&](int kt) {
        int buf = kt & 1;
        uint32_t sK = (uint32_t)__cvta_generic_to_shared(&Ks[buf][0]);
        uint32_t sV = (uint32_t)__cvta_generic_to_shared(&Vs[buf][0]);
        const uint4* Kg4 = (const uint4*)(g_Kh + ((size_t)bh * Lc + kt * 64) * 32);
        const uint4* Vg4 = (const uint4*)g_Vth + ((size_t)(bh * 32 + kt)) * 512;
        #pragma unroll
        for (int i = 0; i < 2; i++) {
            int f = tid + i * 256;
            int n = f >> 3, u = f & 7;
            cpa16(sK + (n * 36 + u * 4) * 4, Kg4 + n * 8 + u);
            cpa16(sV + (n * 36 + u * 4) * 4, Vg4 + n * 8 + u);
        }
        if (tid < 64) mk[buf][tid] = maskb[kt * 64 + tid] ? -1e30f : 0.f;
    };

    issue(0); CPA_COMMIT();
    issue(1); CPA_COMMIT();

    for (int kt = 0; kt < 32; kt++) {
        CPA_WAIT1();
        __syncthreads();
        int buf = kt & 1;

        float S[8][4];
        #pragma unroll
        for (int nt = 0; nt < 8; nt++)
            #pragma unroll
            for (int e = 0; e < 4; e++) S[nt][e] = 0.f;
        #pragma unroll
        for (int nt = 0; nt < 8; nt++) {
            const uint32_t* kr = &Ks[buf][(nt * 8 + q) * 36 + tq * 8];
            uint4 B1 = *(const uint4*)kr;
            uint4 B2 = *(const uint4*)(kr + 4);
            mma_f16(S[nt], qf[0][0], qf[0][1], qf[0][2], qf[0][3], B1.x, B1.y);
            mma_f16(S[nt], qf[1][0], qf[1][1], qf[1][2], qf[1][3], B1.z, B1.w);
            mma_f16(S[nt], qf[2][0], qf[2][1], qf[2][2], qf[2][3], B2.x, B2.y);
            mma_f16(S[nt], qf[3][0], qf[3][1], qf[3][2], qf[3][3], B2.z, B2.w);
        }

        #pragma unroll
        for (int nt = 0; nt < 8; nt++) {
            float mq0 = mk[buf][nt * 8 + tq * 2];
            float mq1 = mk[buf][nt * 8 + tq * 2 + 1];
            S[nt][0] = fmaf(S[nt][0], Cs, mq0);
            S[nt][1] = fmaf(S[nt][1], Cs, mq1);
            S[nt][2] = fmaf(S[nt][2], Cs, mq0);
            S[nt][3] = fmaf(S[nt][3], Cs, mq1);
        }

        float rm0 = -1e30f, rm1 = -1e30f;
        #pragma unroll
        for (int nt = 0; nt < 8; nt++) {
            rm0 = fmaxf(rm0, fmaxf(S[nt][0], S[nt][1]));
            rm1 = fmaxf(rm1, fmaxf(S[nt][2], S[nt][3]));
        }
        rm0 = fmaxf(rm0, __shfl_xor_sync(0xffffffffu, rm0, 1));
        rm0 = fmaxf(rm0, __shfl_xor_sync(0xffffffffu, rm0, 2));
        rm1 = fmaxf(rm1, __shfl_xor_sync(0xffffffffu, rm1, 1));
        rm1 = fmaxf(rm1, __shfl_xor_sync(0xffffffffu, rm1, 2));
        float mn0 = fmaxf(m0r, rm0);
        float mn1 = fmaxf(m1r, rm1);

        float rs0 = 0.f, rs1 = 0.f;
        #pragma unroll
        for (int nt = 0; nt < 8; nt++) {
            float p0 = ex2f(S[nt][0] - mn0);
            float p1 = ex2f(S[nt][1] - mn0);
            float p2 = ex2f(S[nt][2] - mn1);
            float p3 = ex2f(S[nt][3] - mn1);
            S[nt][0] = p0; S[nt][1] = p1; S[nt][2] = p2; S[nt][3] = p3;
            rs0 += p0 + p1; rs1 += p2 + p3;
        }
        rs0 += __shfl_xor_sync(0xffffffffu, rs0, 1);
        rs0 += __shfl_xor_sync(0xffffffffu, rs0, 2);
        rs1 += __shfl_xor_sync(0xffffffffu, rs1, 1);
        rs1 += __shfl_xor_sync(0xffffffffu, rs1, 2);

        float alpha0 = ex2f(m0r - mn0);
        float alpha1 = ex2f(m1r - mn1);
        l0r = l0r * alpha0 + rs0;  m0r = mn0;
        l1r = l1r * alpha1 + rs1;  m1r = mn1;

        uint32_t pp[8][2];
        #pragma unroll
        for (int nt = 0; nt < 8; nt++) {
            pp[nt][0] = packh2(S[nt][0], S[nt][1]);
            pp[nt][1] = packh2(S[nt][2], S[nt][3]);
            O[nt][0] *= alpha0; O[nt][1] *= alpha0;
            O[nt][2] *= alpha1; O[nt][3] *= alpha1;
        }

        #pragma unroll
        for (int nt = 0; nt < 8; nt++) {
            const uint32_t* vr = &Vs[buf][(nt * 8 + q) * 36 + tq * 8];
            uint4 V1 = *(const uint4*)vr;
            uint4 V2 = *(const uint4*)(vr + 4);
            mma_f16(O[nt], pp[0][0], pp[0][1], pp[1][0], pp[1][1], V1.x, V1.y);
            mma_f16(O[nt], pp[2][0], pp[2][1], pp[3][0], pp[3][1], V1.z, V1.w);
            mma_f16(O[nt], pp[4][0], pp[4][1], pp[5][0], pp[5][1], V2.x, V2.y);
            mma_f16(O[nt], pp[6][0], pp[6][1], pp[7][0], pp[7][1], V2.z, V2.w);
        }

        __syncthreads();
        if (kt + 2 < 32) issue(kt + 2);
        CPA_COMMIT();
    }

    float inv0 = (l0r > 0.f) ? (1.f / l0r) : 0.f;
    float inv1 = (l1r > 0.f) ? (1.f / l1r) : 0.f;
    int r0 = qt * 128 + warp * 16 + q;
    size_t tok0 = (size_t)b * Lc + r0;
    size_t tok1 = tok0 + 8;
    #pragma unroll
    for (int nt = 0; nt < 8; nt++) {
        int n = h * 64 + nt * 8 + tq * 2;
        float o0 = O[nt][0] * inv0 * g_G[tok0 * Dc + n];
        float o1 = O[nt][1] * inv0 * g_G[tok0 * Dc + n + 1];
        float o2 = O[nt][2] * inv1 * g_G[tok1 * Dc + n];
        float o3 = O[nt][3] * inv1 * g_G[tok1 * Dc + n + 1];
        int J = n >> 1, chnk = J >> 4, jj = J & 15;
        int pos = (jj >> 2) + (jj & 1) * 4 + ((jj >> 1) & 1) * 8;
        g_AOh[tok0 * 512 + chnk * 16 + pos] = packh2(o0, o1);
        g_AOh[tok1 * 512 + chnk * 16 + pos] = packh2(o2, o3);
    }
}

// ---- FP16 output projection GEMM, cp.async double-buffered -----------------
__global__ __launch_bounds__(256) void out_gemm_tc(
    const float* __restrict__ bo, float* __restrict__ out)
{
    const uint32_t* Ag  = g_AOh;
    const uint32_t* Wgp = g_H + SEGW + (size_t)4 * WS;

    const int m0 = blockIdx.y * 128;
    const int n0 = blockIdx.x * 64;

    __shared__ uint32_t As[2][128 * 16];
    __shared__ uint32_t Bs[2][64 * 16];

    const int tid  = threadIdx.x;
    const int warp = tid >> 5;
    const int lane = tid & 31;
    const int q    = lane >> 2;
    const int tq   = lane & 3;
    const int warpM0 = (warp >> 1) * 32;
    const int warpN0 = (warp & 1) * 32;

    float acc[2][4][4];
    #pragma unroll
    for (int mt = 0; mt < 2; mt++)
        #pragma unroll
        for (int nt = 0; nt < 4; nt++)
            #pragma unroll
            for (int e = 0; e < 4; e++) acc[mt][nt][e] = 0.f;

    auto copyt = [&](int kc, int buf) {
        uint32_t sA = (uint32_t)__cvta_generic_to_shared(&As[buf][0]);
        uint32_t sB = (uint32_t)__cvta_generic_to_shared(&Bs[buf][0]);
        #pragma unroll
        for (int i = 0; i < 2; i++) {
            int idx = tid + i * 256;
            int m = idx >> 2, u = idx & 3;
            cpa16(sA + (m * 16 + u * 4) * 4,
                  (const uint4*)(Ag + (size_t)(m0 + m) * 512 + kc * 16) + u);
        }
        {
            int n = tid >> 2, u = tid & 3;
            cpa16(sB + (n * 16 + u * 4) * 4,
                  (const uint4*)(Wgp + (size_t)(n0 + n) * 512 + kc * 16) + u);
        }
    };

    copyt(0, 0); CPA_COMMIT();
    copyt(1, 1); CPA_COMMIT();

    for (int it = 0; it < 32; it++) {
        CPA_WAIT1();
        __syncthreads();
        int buf = it & 1;

        uint4 Ar[2], Ar8[2];
        #pragma unroll
        for (int mt = 0; mt < 2; mt++) {
            int r = warpM0 + mt * 16 + q;
            Ar[mt]  = *(const uint4*)&As[buf][r * 16 + tq * 4];
            Ar8[mt] = *(const uint4*)&As[buf][(r + 8) * 16 + tq * 4];
        }
        #pragma unroll
        for (int nt = 0; nt < 4; nt++) {
            int n = warpN0 + nt * 8 + q;
            uint4 Bv = *(const uint4*)&Bs[buf][n * 16 + tq * 4];
            #pragma unroll
            for (int mt = 0; mt < 2; mt++) {
                mma_f16(acc[mt][nt], Ar[mt].x, Ar8[mt].x, Ar[mt].y, Ar8[mt].y, Bv.x, Bv.y);
                mma_f16(acc[mt][nt], Ar[mt].z, Ar8[mt].z, Ar[mt].w, Ar8[mt].w, Bv.z, Bv.w);
            }
        }
        __syncthreads();
        if (it + 2 < 32) copyt(it + 2, buf);
        CPA_COMMIT();
    }

    #pragma unroll
    for (int mt = 0; mt < 2; mt++)
        #pragma unroll
        for (int nt = 0; nt < 4; nt++)
            #pragma unroll
            for (int e = 0; e < 4; e++) {
                int row = m0 + warpM0 + mt * 16 + q + ((e >> 1) ? 8 : 0);
                int col = n0 + warpN0 + nt * 8 + tq * 2 + (e & 1);
                out[(size_t)row * Dc + col] = acc[mt][nt][e] + bo[col];
            }
}

// ---- launch -----------------------------------------------------------------
extern "C" void kernel_launch(void* const* d_in, const int* in_sizes, int n_in,
                              void* d_out, int out_size)
{
    const float* query   = (const float*)d_in[0];
    const float* key_in  = (const float*)d_in[1];
    const float* value   = (const float*)d_in[2];
    const unsigned char* maskraw = (const unsigned char*)d_in[3];
    const float* rope_cos = (const float*)d_in[4];
    const float* rope_sin = (const float*)d_in[5];
    const float* Wq = (const float*)d_in[6];
    const float* bq = (const float*)d_in[7];
    const float* Wk = (const float*)d_in[8];
    const float* bk = (const float*)d_in[9];
    const float* Wv = (const float*)d_in[10];
    const float* bv = (const float*)d_in[11];
    const float* Wg = (const float*)d_in[12];
    const float* bg = (const float*)d_in[13];
    const float* Wo = (const float*)d_in[14];
    const float* bo = (const float*)d_in[15];
    float* out = (float*)d_out;

    (void)in_sizes; (void)n_in; (void)out_size;

    mask_decode_kernel<<<1, 1024>>>(maskraw);
    prep_half<<<dim3(4096, 1, 8), 256>>>(query, key_in, value, Wq, Wk, Wv, Wg, Wo);
    proj_gemm_tc<<<dim3(16, 32, 4), 256>>>(bq, bk, bv, bg, rope_cos, rope_sin);
    attn_tc_kernel<<<dim3(16, 32), 256>>>();
    out_gemm_tc<<<dim3(16, 32), 256>>>(bo, out);
}

// round 12
// speedup vs baseline: 2.2779x; 1.0816x over previous
#include <cuda_runtime.h>
#include <cuda_fp16.h>
#include <stdint.h>
#include <math.h>

#define Bc   2
#define Lc   2048
#define Dc   1024
#define Hc   16
#define NT   4096
#define BHc  32

#define SEG1 (4096*512)
#define SEGW (3*4096*512)
#define WS   (1024*512)
__device__ uint32_t g_H[(size_t)(3*4096 + 5*1024)*512];
__device__ uint32_t g_Qh[(size_t)BHc*Lc*32];     // plain half-pair rows of 32 (pre-scaled by Cs)
__device__ uint32_t g_Kh[(size_t)BHc*Lc*32];     // attn-permuted rows of 32
__device__ __half   g_Vth[(size_t)BHc*32*64*64]; // attn-smem-image half V
__device__ float    g_G [(size_t)NT*Dc];
__device__ uint32_t g_AOh[(size_t)NT*512];       // chunk-permuted half
__device__ int      g_mask[NT];
__device__ uint32_t g_mkh[NT/2];                 // half2 additive mask (-4 live / -3e4 masked)

__device__ __forceinline__ uint32_t packh2(float a, float b) {
    __half2 h = __floats2half2_rn(a, b);
    return *reinterpret_cast<uint32_t*>(&h);
}
__device__ __forceinline__ uint32_t hadd2u(uint32_t a, uint32_t b) {
    uint32_t r;
    asm("add.f16x2 %0, %1, %2;" : "=r"(r) : "r"(a), "r"(b));
    return r;
}
__device__ __forceinline__ uint32_t ex2h2(uint32_t a) {
    uint32_t r;
    asm("ex2.approx.f16x2 %0, %1;" : "=r"(r) : "r"(a));
    return r;
}
__device__ __forceinline__ void mma_f16(
    float* d, uint32_t a0, uint32_t a1, uint32_t a2, uint32_t a3,
    uint32_t b0, uint32_t b1)
{
    asm volatile(
        "mma.sync.aligned.m16n8k16.row.col.f32.f16.f16.f32 "
        "{%0,%1,%2,%3}, {%4,%5,%6,%7}, {%8,%9}, {%0,%1,%2,%3};\n"
        : "+f"(d[0]), "+f"(d[1]), "+f"(d[2]), "+f"(d[3])
        : "r"(a0), "r"(a1), "r"(a2), "r"(a3), "r"(b0), "r"(b1));
}
__device__ __forceinline__ void cpa16(uint32_t dst, const void* src) {
    asm volatile("cp.async.ca.shared.global [%0], [%1], 16;"
                 :: "r"(dst), "l"(src) : "memory");
}
#define CPA_COMMIT() asm volatile("cp.async.commit_group;" ::: "memory")
#define CPA_WAIT1()  asm volatile("cp.async.wait_group 1;" ::: "memory")

__global__ void mask_decode_kernel(const unsigned char* __restrict__ raw) {
    __shared__ int cnt[4];
    int tid = threadIdx.x;
    if (tid < 4) cnt[tid] = 0;
    __syncthreads();
    for (int i = tid; i < NT; i += blockDim.x)
        if (raw[i]) atomicAdd(&cnt[i & 3], 1);
    __syncthreads();
    int c0 = cnt[0], c1 = cnt[1], c2 = cnt[2], c3 = cnt[3];
    int mode;
    if (c0 > 0 && c1 == 0 && c2 == 0 && c3 == 0)       mode = 1;
    else if ((c2 > 0 || c3 > 0) && c0 == 0 && c1 == 0) mode = 2;
    else                                               mode = 0;
    for (int i = tid; i < NT; i += blockDim.x) {
        int v;
        if (mode == 0)      v = (raw[i] != 0);
        else if (mode == 1) v = (((const int*)raw)[i] != 0);
        else                v = (((const float*)raw)[i] != 0.0f);
        g_mask[i] = v;
    }
    __syncthreads();
    // half2 additive mask with the fixed softmax shift folded in
    for (int i = tid; i < NT / 2; i += blockDim.x) {
        float m0 = g_mask[2*i]     ? -30000.f : -4.0f;
        float m1 = g_mask[2*i + 1] ? -30000.f : -4.0f;
        g_mkh[i] = packh2(m0, m1);
    }
}

__global__ void prep_half(
    const float* __restrict__ q, const float* __restrict__ k,
    const float* __restrict__ v,
    const float* __restrict__ wq, const float* __restrict__ wk,
    const float* __restrict__ wv, const float* __restrict__ wg,
    const float* __restrict__ wo)
{
    int z = blockIdx.z, row = blockIdx.x, t = threadIdx.x;
    const float* src; size_t off;
    if (z < 3) {
        src = (z == 0) ? q : ((z == 1) ? k : v);
        off = (size_t)z * SEG1;
    } else {
        if (row >= 1024) return;
        src = (z == 3) ? wq : ((z == 4) ? wk : ((z == 5) ? wv : ((z == 6) ? wg : wo)));
        off = (size_t)SEGW + (size_t)(z - 3) * WS;
    }
    float4 val = ((const float4*)src)[(size_t)row * 256 + t];
    int ch = t >> 3, c = t & 7;
    uint32_t* dst = g_H + off + (size_t)row * 512 + ch * 16 + (c & 1) * 8 + (c >> 1);
    dst[0] = packh2(val.x, val.y);
    dst[4] = packh2(val.z, val.w);
}

// ---- FP16 projection GEMM, cp.async double-buffered, fused RoPE ------------
__global__ __launch_bounds__(256) void proj_gemm_tc(
    const float* __restrict__ bq, const float* __restrict__ bk,
    const float* __restrict__ bv, const float* __restrict__ bg,
    const float* __restrict__ cosb, const float* __restrict__ sinb)
{
    const int z = blockIdx.z;
    const uint32_t* Ag  = g_H + ((z == 3) ? 0 : (size_t)z * SEG1);
    const uint32_t* Wgp = g_H + SEGW + (size_t)z * WS;
    const float* bias = (z == 0) ? bq : ((z == 1) ? bk : ((z == 2) ? bv : bg));

    const int m0 = blockIdx.y * 128;
    const int n0 = blockIdx.x * 64;

    __shared__ uint32_t As[2][128 * 16];
    __shared__ uint32_t Bs[2][64 * 16];

    const int tid  = threadIdx.x;
    const int warp = tid >> 5;
    const int lane = tid & 31;
    const int q    = lane >> 2;
    const int tq   = lane & 3;
    const int warpM0 = (warp >> 1) * 32;
    const int colbase = (warp & 1) * 16;

    float acc[2][4][4];
    #pragma unroll
    for (int mt = 0; mt < 2; mt++)
        #pragma unroll
        for (int nt = 0; nt < 4; nt++)
            #pragma unroll
            for (int e = 0; e < 4; e++) acc[mt][nt][e] = 0.f;

    auto copyt = [&](int kc, int buf) {
        uint32_t sA = (uint32_t)__cvta_generic_to_shared(&As[buf][0]);
        uint32_t sB = (uint32_t)__cvta_generic_to_shared(&Bs[buf][0]);
        #pragma unroll
        for (int i = 0; i < 2; i++) {
            int idx = tid + i * 256;
            int m = idx >> 2, u = idx & 3;
            cpa16(sA + (m * 16 + u * 4) * 4,
                  (const uint4*)(Ag + (size_t)(m0 + m) * 512 + kc * 16) + u);
        }
        {
            int n = tid >> 2, u = tid & 3;
            cpa16(sB + (n * 16 + u * 4) * 4,
                  (const uint4*)(Wgp + (size_t)(n0 + n) * 512 + kc * 16) + u);
        }
    };

    copyt(0, 0); CPA_COMMIT();
    copyt(1, 1); CPA_COMMIT();

    for (int it = 0; it < 32; it++) {
        CPA_WAIT1();
        __syncthreads();
        int buf = it & 1;

        uint4 Ar[2], Ar8[2];
        #pragma unroll
        for (int mt = 0; mt < 2; mt++) {
            int r = warpM0 + mt * 16 + q;
            Ar[mt]  = *(const uint4*)&As[buf][r * 16 + tq * 4];
            Ar8[mt] = *(const uint4*)&As[buf][(r + 8) * 16 + tq * 4];
        }
        #pragma unroll
        for (int nt = 0; nt < 4; nt++) {
            int n = colbase + (nt & 1) * 8 + (nt >> 1) * 32 + q;
            uint4 Bv = *(const uint4*)&Bs[buf][n * 16 + tq * 4];
            #pragma unroll
            for (int mt = 0; mt < 2; mt++) {
                mma_f16(acc[mt][nt], Ar[mt].x, Ar8[mt].x, Ar[mt].y, Ar8[mt].y, Bv.x, Bv.y);
                mma_f16(acc[mt][nt], Ar[mt].z, Ar8[mt].z, Ar[mt].w, Ar8[mt].w, Bv.z, Bv.w);
            }
        }
        __syncthreads();
        if (it + 2 < 32) copyt(it + 2, buf);
        CPA_COMMIT();
    }

    const int h = n0 >> 6;
    const float CsQ = 0.18033688011112158f;   // 0.125 * log2(e), folded into Q
    #pragma unroll
    for (int mt = 0; mt < 2; mt++)
        #pragma unroll
        for (int nt = 0; nt < 2; nt++) {
            int cl0 = colbase + nt * 8 + tq * 2;
            float y1[4], y2[4];
            #pragma unroll
            for (int e = 0; e < 4; e++) {
                int row = m0 + warpM0 + mt * 16 + q + ((e >> 1) ? 8 : 0);
                int l = row & (Lc - 1);
                int cl = cl0 + (e & 1);
                float x1 = acc[mt][nt][e]     + bias[n0 + cl];
                float x2 = acc[mt][nt + 2][e] + bias[n0 + cl + 32];
                if (z <= 1) {
                    float c1 = cosb[l * 64 + cl],      s1 = sinb[l * 64 + cl];
                    float c2 = cosb[l * 64 + cl + 32], s2 = sinb[l * 64 + cl + 32];
                    y1[e] = x1 * c1 - x2 * s1;
                    y2[e] = x2 * c2 + x1 * s2;
                    if (z == 0) { y1[e] *= CsQ; y2[e] *= CsQ; }
                } else { y1[e] = x1; y2[e] = x2; }
            }
            #pragma unroll
            for (int h2 = 0; h2 < 2; h2++) {
                int row = m0 + warpM0 + mt * 16 + q + h2 * 8;
                int b = row >> 11, l = row & (Lc - 1);
                if (z == 3) {
                    size_t rb = (size_t)row * Dc + n0;
                    g_G[rb + cl0]      = 1.f / (1.f + __expf(-y1[2*h2]));
                    g_G[rb + cl0 + 1]  = 1.f / (1.f + __expf(-y1[2*h2+1]));
                    g_G[rb + cl0 + 32] = 1.f / (1.f + __expf(-y2[2*h2]));
                    g_G[rb + cl0 + 33] = 1.f / (1.f + __expf(-y2[2*h2+1]));
                } else if (z == 2) {
                    int kt2 = l >> 6, tk = l & 63, jp = tk >> 1;
                    int hoff = ((jp & 3) * 8 + (jp >> 2)) * 2 + (tk & 1);
                    __half* vrow = g_Vth + (((size_t)(b * Hc + h) * 32 + kt2) * 64) * 64;
                    vrow[(size_t)(cl0)      * 64 + hoff] = __float2half(y1[2*h2]);
                    vrow[(size_t)(cl0 + 1)  * 64 + hoff] = __float2half(y1[2*h2+1]);
                    vrow[(size_t)(cl0 + 32) * 64 + hoff] = __float2half(y2[2*h2]);
                    vrow[(size_t)(cl0 + 33) * 64 + hoff] = __float2half(y2[2*h2+1]);
                } else {
                    size_t drow = ((size_t)(b * Hc + h) * Lc + l) * 32;
                    uint32_t p1 = packh2(y1[2*h2], y1[2*h2+1]);
                    uint32_t p2 = packh2(y2[2*h2], y2[2*h2+1]);
                    int j1 = cl0 >> 1;
                    if (z == 0) {
                        g_Qh[drow + j1]      = p1;
                        g_Qh[drow + j1 + 16] = p2;
                    } else {
                        int pos = (j1 & 3) * 8 + (j1 >> 2);
                        g_Kh[drow + pos]     = p1;
                        g_Kh[drow + pos + 4] = p2;
                    }
                }
            }
        }
}

// ---- FP16 flash attention: fixed-shift softmax, half2 exp, l via MMA -------
__global__ __launch_bounds__(256, 2) void attn_tc_kernel()
{
    __shared__ uint32_t Ks[2][64 * 36];
    __shared__ uint32_t Vs[2][64 * 36];
    __shared__ uint32_t mk[2][32];

    const int qt  = blockIdx.x;
    const int bh  = blockIdx.y;
    const int b   = bh >> 4;
    const int h   = bh & 15;
    const int tid = threadIdx.x;
    const int warp = tid >> 5;
    const int lane = tid & 31;
    const int q    = lane >> 2;
    const int tq   = lane & 3;

    const uint32_t* Qg32 = g_Qh + ((size_t)bh * Lc + qt * 128 + warp * 16 + q) * 32;
    uint32_t qf[4][4];
    #pragma unroll
    for (int s = 0; s < 4; s++) {
        qf[s][0] = Qg32[8*s + tq];
        qf[s][1] = Qg32[256 + 8*s + tq];
        qf[s][2] = Qg32[8*s + tq + 4];
        qf[s][3] = Qg32[256 + 8*s + tq + 4];
    }

    float O[8][4];
    #pragma unroll
    for (int nt = 0; nt < 8; nt++)
        #pragma unroll
        for (int e = 0; e < 4; e++) O[nt][e] = 0.f;
    float lacc[4] = {0.f, 0.f, 0.f, 0.f};
    const uint32_t ONES = 0x3C003C00u;   // half2(1, 1)

    auto issue = [&](int kt) {
        int buf = kt & 1;
        uint32_t sK = (uint32_t)__cvta_generic_to_shared(&Ks[buf][0]);
        uint32_t sV = (uint32_t)__cvta_generic_to_shared(&Vs[buf][0]);
        const uint4* Kg4 = (const uint4*)(g_Kh + ((size_t)bh * Lc + kt * 64) * 32);
        const uint4* Vg4 = (const uint4*)g_Vth + ((size_t)(bh * 32 + kt)) * 512;
        #pragma unroll
        for (int i = 0; i < 2; i++) {
            int f = tid + i * 256;
            int n = f >> 3, u = f & 7;
            cpa16(sK + (n * 36 + u * 4) * 4, Kg4 + n * 8 + u);
            cpa16(sV + (n * 36 + u * 4) * 4, Vg4 + n * 8 + u);
        }
        if (tid < 8) {
            uint32_t sM = (uint32_t)__cvta_generic_to_shared(&mk[buf][0]);
            cpa16(sM + tid * 16, g_mkh + b * 1024 + kt * 32 + tid * 4);
        }
    };

    issue(0); CPA_COMMIT();
    issue(1); CPA_COMMIT();

    for (int kt = 0; kt < 32; kt++) {
        CPA_WAIT1();
        __syncthreads();
        int buf = kt & 1;

        // S = Q.K^T (S already in log2 units; Cs folded into Q)
        float S[8][4];
        #pragma unroll
        for (int nt = 0; nt < 8; nt++)
            #pragma unroll
            for (int e = 0; e < 4; e++) S[nt][e] = 0.f;
        #pragma unroll
        for (int nt = 0; nt < 8; nt++) {
            const uint32_t* kr = &Ks[buf][(nt * 8 + q) * 36 + tq * 8];
            uint4 B1 = *(const uint4*)kr;
            uint4 B2 = *(const uint4*)(kr + 4);
            mma_f16(S[nt], qf[0][0], qf[0][1], qf[0][2], qf[0][3], B1.x, B1.y);
            mma_f16(S[nt], qf[1][0], qf[1][1], qf[1][2], qf[1][3], B1.z, B1.w);
            mma_f16(S[nt], qf[2][0], qf[2][1], qf[2][2], qf[2][3], B2.x, B2.y);
            mma_f16(S[nt], qf[3][0], qf[3][1], qf[3][2], qf[3][3], B2.z, B2.w);
        }

        // P = 2^(S + mask_shift), computed entirely in half2
        uint32_t pp[8][2];
        #pragma unroll
        for (int nt = 0; nt < 8; nt++) {
            uint32_t mq = mk[buf][nt * 4 + tq];
            pp[nt][0] = ex2h2(hadd2u(packh2(S[nt][0], S[nt][1]), mq));
            pp[nt][1] = ex2h2(hadd2u(packh2(S[nt][2], S[nt][3]), mq));
        }

        // l += P . ones   (row-sum replicated across all fragment columns)
        mma_f16(lacc, pp[0][0], pp[0][1], pp[1][0], pp[1][1], ONES, ONES);
        mma_f16(lacc, pp[2][0], pp[2][1], pp[3][0], pp[3][1], ONES, ONES);
        mma_f16(lacc, pp[4][0], pp[4][1], pp[5][0], pp[5][1], ONES, ONES);
        mma_f16(lacc, pp[6][0], pp[6][1], pp[7][0], pp[7][1], ONES, ONES);

        // O += P . V
        #pragma unroll
        for (int nt = 0; nt < 8; nt++) {
            const uint32_t* vr = &Vs[buf][(nt * 8 + q) * 36 + tq * 8];
            uint4 V1 = *(const uint4*)vr;
            uint4 V2 = *(const uint4*)(vr + 4);
            mma_f16(O[nt], pp[0][0], pp[0][1], pp[1][0], pp[1][1], V1.x, V1.y);
            mma_f16(O[nt], pp[2][0], pp[2][1], pp[3][0], pp[3][1], V1.z, V1.w);
            mma_f16(O[nt], pp[4][0], pp[4][1], pp[5][0], pp[5][1], V2.x, V2.y);
            mma_f16(O[nt], pp[6][0], pp[6][1], pp[7][0], pp[7][1], V2.z, V2.w);
        }

        __syncthreads();
        if (kt + 2 < 32) issue(kt + 2);
        CPA_COMMIT();
    }

    float l0r = lacc[0], l1r = lacc[2];
    float inv0 = (l0r > 0.f) ? (1.f / l0r) : 0.f;
    float inv1 = (l1r > 0.f) ? (1.f / l1r) : 0.f;
    int r0 = qt * 128 + warp * 16 + q;
    size_t tok0 = (size_t)b * Lc + r0;
    size_t tok1 = tok0 + 8;
    #pragma unroll
    for (int nt = 0; nt < 8; nt++) {
        int n = h * 64 + nt * 8 + tq * 2;
        float o0 = O[nt][0] * inv0 * g_G[tok0 * Dc + n];
        float o1 = O[nt][1] * inv0 * g_G[tok0 * Dc + n + 1];
        float o2 = O[nt][2] * inv1 * g_G[tok1 * Dc + n];
        float o3 = O[nt][3] * inv1 * g_G[tok1 * Dc + n + 1];
        int J = n >> 1, chnk = J >> 4, jj = J & 15;
        int pos = (jj >> 2) + (jj & 1) * 4 + ((jj >> 1) & 1) * 8;
        g_AOh[tok0 * 512 + chnk * 16 + pos] = packh2(o0, o1);
        g_AOh[tok1 * 512 + chnk * 16 + pos] = packh2(o2, o3);
    }
}

// ---- FP16 output projection GEMM, cp.async double-buffered -----------------
__global__ __launch_bounds__(256) void out_gemm_tc(
    const float* __restrict__ bo, float* __restrict__ out)
{
    const uint32_t* Ag  = g_AOh;
    const uint32_t* Wgp = g_H + SEGW + (size_t)4 * WS;

    const int m0 = blockIdx.y * 128;
    const int n0 = blockIdx.x * 64;

    __shared__ uint32_t As[2][128 * 16];
    __shared__ uint32_t Bs[2][64 * 16];

    const int tid  = threadIdx.x;
    const int warp = tid >> 5;
    const int lane = tid & 31;
    const int q    = lane >> 2;
    const int tq   = lane & 3;
    const int warpM0 = (warp >> 1) * 32;
    const int warpN0 = (warp & 1) * 32;

    float acc[2][4][4];
    #pragma unroll
    for (int mt = 0; mt < 2; mt++)
        #pragma unroll
        for (int nt = 0; nt < 4; nt++)
            #pragma unroll
            for (int e = 0; e < 4; e++) acc[mt][nt][e] = 0.f;

    auto copyt = [&](int kc, int buf) {
        uint32_t sA = (uint32_t)__cvta_generic_to_shared(&As[buf][0]);
        uint32_t sB = (uint32_t)__cvta_generic_to_shared(&Bs[buf][0]);
        #pragma unroll
        for (int i = 0; i < 2; i++) {
            int idx = tid + i * 256;
            int m = idx >> 2, u = idx & 3;
            cpa16(sA + (m * 16 + u * 4) * 4,
                  (const uint4*)(Ag + (size_t)(m0 + m) * 512 + kc * 16) + u);
        }
        {
            int n = tid >> 2, u = tid & 3;
            cpa16(sB + (n * 16 + u * 4) * 4,
                  (const uint4*)(Wgp + (size_t)(n0 + n) * 512 + kc * 16) + u);
        }
    };

    copyt(0, 0); CPA_COMMIT();
    copyt(1, 1); CPA_COMMIT();

    for (int it = 0; it < 32; it++) {
        CPA_WAIT1();
        __syncthreads();
        int buf = it & 1;

        uint4 Ar[2], Ar8[2];
        #pragma unroll
        for (int mt = 0; mt < 2; mt++) {
            int r = warpM0 + mt * 16 + q;
            Ar[mt]  = *(const uint4*)&As[buf][r * 16 + tq * 4];
            Ar8[mt] = *(const uint4*)&As[buf][(r + 8) * 16 + tq * 4];
        }
        #pragma unroll
        for (int nt = 0; nt < 4; nt++) {
            int n = warpN0 + nt * 8 + q;
            uint4 Bv = *(const uint4*)&Bs[buf][n * 16 + tq * 4];
            #pragma unroll
            for (int mt = 0; mt < 2; mt++) {
                mma_f16(acc[mt][nt], Ar[mt].x, Ar8[mt].x, Ar[mt].y, Ar8[mt].y, Bv.x, Bv.y);
                mma_f16(acc[mt][nt], Ar[mt].z, Ar8[mt].z, Ar[mt].w, Ar8[mt].w, Bv.z, Bv.w);
            }
        }
        __syncthreads();
        if (it + 2 < 32) copyt(it + 2, buf);
        CPA_COMMIT();
    }

    #pragma unroll
    for (int mt = 0; mt < 2; mt++)
        #pragma unroll
        for (int nt = 0; nt < 4; nt++)
            #pragma unroll
            for (int e = 0; e < 4; e++) {
                int row = m0 + warpM0 + mt * 16 + q + ((e >> 1) ? 8 : 0);
                int col = n0 + warpN0 + nt * 8 + tq * 2 + (e & 1);
                out[(size_t)row * Dc + col] = acc[mt][nt][e] + bo[col];
            }
}

// ---- launch -----------------------------------------------------------------
extern "C" void kernel_launch(void* const* d_in, const int* in_sizes, int n_in,
                              void* d_out, int out_size)
{
    const float* query   = (const float*)d_in[0];
    const float* key_in  = (const float*)d_in[1];
    const float* value   = (const float*)d_in[2];
    const unsigned char* maskraw = (const unsigned char*)d_in[3];
    const float* rope_cos = (const float*)d_in[4];
    const float* rope_sin = (const float*)d_in[5];
    const float* Wq = (const float*)d_in[6];
    const float* bq = (const float*)d_in[7];
    const float* Wk = (const float*)d_in[8];
    const float* bk = (const float*)d_in[9];
    const float* Wv = (const float*)d_in[10];
    const float* bv = (const float*)d_in[11];
    const float* Wg = (const float*)d_in[12];
    const float* bg = (const float*)d_in[13];
    const float* Wo = (const float*)d_in[14];
    const float* bo = (const float*)d_in[15];
    float* out = (float*)d_out;

    (void)in_sizes; (void)n_in; (void)out_size;

    mask_decode_kernel<<<1, 1024>>>(maskraw);
    prep_half<<<dim3(4096, 1, 8), 256>>>(query, key_in, value, Wq, Wk, Wv, Wg, Wo);
    proj_gemm_tc<<<dim3(16, 32, 4), 256>>>(bq, bk, bv, bg, rope_cos, rope_sin);
    attn_tc_kernel<<<dim3(16, 32), 256>>>();
    out_gemm_tc<<<dim3(16, 32), 256>>>(bo, out);
}

// round 13
// speedup vs baseline: 2.4112x; 1.0585x over previous
#include <cuda_runtime.h>
#include <cuda_fp16.h>
#include <stdint.h>
#include <math.h>

#define Bc   2
#define Lc   2048
#define Dc   1024
#define Hc   16
#define NT   4096
#define BHc  32

#define SEG1 (4096*512)
#define SEGW (3*4096*512)
#define WS   (1024*512)
__device__ uint32_t g_H[(size_t)(3*4096 + 5*1024)*512];
__device__ uint32_t g_Qh[(size_t)BHc*Lc*32];     // plain half-pair rows of 32 (pre-scaled by Cs)
__device__ uint32_t g_Kh[(size_t)BHc*Lc*32];     // attn-permuted rows of 32
__device__ __half   g_Vth[(size_t)BHc*32*64*64]; // attn-smem-image half V
__device__ float    g_G [(size_t)NT*Dc];
__device__ uint32_t g_AOh[(size_t)NT*512];       // chunk-permuted half
__device__ int      g_mask[NT];
__device__ uint32_t g_mkh[NT/2];                 // half2 additive mask (-4 live / -3e4 masked)

__device__ __forceinline__ uint32_t packh2(float a, float b) {
    __half2 h = __floats2half2_rn(a, b);
    return *reinterpret_cast<uint32_t*>(&h);
}
__device__ __forceinline__ uint32_t hadd2u(uint32_t a, uint32_t b) {
    uint32_t r;
    asm("add.f16x2 %0, %1, %2;" : "=r"(r) : "r"(a), "r"(b));
    return r;
}
__device__ __forceinline__ uint32_t ex2h2(uint32_t a) {
    uint32_t r;
    asm("ex2.approx.f16x2 %0, %1;" : "=r"(r) : "r"(a));
    return r;
}
__device__ __forceinline__ void mma_f16(
    float* d, uint32_t a0, uint32_t a1, uint32_t a2, uint32_t a3,
    uint32_t b0, uint32_t b1)
{
    asm volatile(
        "mma.sync.aligned.m16n8k16.row.col.f32.f16.f16.f32 "
        "{%0,%1,%2,%3}, {%4,%5,%6,%7}, {%8,%9}, {%0,%1,%2,%3};\n"
        : "+f"(d[0]), "+f"(d[1]), "+f"(d[2]), "+f"(d[3])
        : "r"(a0), "r"(a1), "r"(a2), "r"(a3), "r"(b0), "r"(b1));
}
__device__ __forceinline__ void cpa16(uint32_t dst, const void* src) {
    asm volatile("cp.async.ca.shared.global [%0], [%1], 16;"
                 :: "r"(dst), "l"(src) : "memory");
}
#define CPA_COMMIT() asm volatile("cp.async.commit_group;" ::: "memory")
#define CPA_WAIT1()  asm volatile("cp.async.wait_group 1;" ::: "memory")

__global__ void mask_decode_kernel(const unsigned char* __restrict__ raw) {
    __shared__ int cnt[4];
    int tid = threadIdx.x;
    if (tid < 4) cnt[tid] = 0;
    __syncthreads();
    for (int i = tid; i < NT; i += blockDim.x)
        if (raw[i]) atomicAdd(&cnt[i & 3], 1);
    __syncthreads();
    int c0 = cnt[0], c1 = cnt[1], c2 = cnt[2], c3 = cnt[3];
    int mode;
    if (c0 > 0 && c1 == 0 && c2 == 0 && c3 == 0)       mode = 1;
    else if ((c2 > 0 || c3 > 0) && c0 == 0 && c1 == 0) mode = 2;
    else                                               mode = 0;
    for (int i = tid; i < NT; i += blockDim.x) {
        int v;
        if (mode == 0)      v = (raw[i] != 0);
        else if (mode == 1) v = (((const int*)raw)[i] != 0);
        else                v = (((const float*)raw)[i] != 0.0f);
        g_mask[i] = v;
    }
    __syncthreads();
    for (int i = tid; i < NT / 2; i += blockDim.x) {
        float m0 = g_mask[2*i]     ? -30000.f : -4.0f;
        float m1 = g_mask[2*i + 1] ? -30000.f : -4.0f;
        g_mkh[i] = packh2(m0, m1);
    }
}

__global__ void prep_half(
    const float* __restrict__ q, const float* __restrict__ k,
    const float* __restrict__ v,
    const float* __restrict__ wq, const float* __restrict__ wk,
    const float* __restrict__ wv, const float* __restrict__ wg,
    const float* __restrict__ wo)
{
    int z = blockIdx.z, row = blockIdx.x, t = threadIdx.x;
    const float* src; size_t off;
    if (z < 3) {
        src = (z == 0) ? q : ((z == 1) ? k : v);
        off = (size_t)z * SEG1;
    } else {
        if (row >= 1024) return;
        src = (z == 3) ? wq : ((z == 4) ? wk : ((z == 5) ? wv : ((z == 6) ? wg : wo)));
        off = (size_t)SEGW + (size_t)(z - 3) * WS;
    }
    float4 val = ((const float4*)src)[(size_t)row * 256 + t];
    int ch = t >> 3, c = t & 7;
    uint32_t* dst = g_H + off + (size_t)row * 512 + ch * 16 + (c & 1) * 8 + (c >> 1);
    dst[0] = packh2(val.x, val.y);
    dst[4] = packh2(val.z, val.w);
}

// ---- FP16 projection GEMM, 128x128 tile, cp.async, fused RoPE --------------
// 8 warps as 4(m) x 2(n); each warp 32 rows x 64 cols (one full head).
// RoPE pair (c, c+32) = acc nt and nt+4 in the same thread.
__global__ __launch_bounds__(256) void proj_gemm_tc(
    const float* __restrict__ bq, const float* __restrict__ bk,
    const float* __restrict__ bv, const float* __restrict__ bg,
    const float* __restrict__ cosb, const float* __restrict__ sinb)
{
    const int z = blockIdx.z;
    const uint32_t* Ag  = g_H + ((z == 3) ? 0 : (size_t)z * SEG1);
    const uint32_t* Wgp = g_H + SEGW + (size_t)z * WS;
    const float* bias = (z == 0) ? bq : ((z == 1) ? bk : ((z == 2) ? bv : bg));

    const int m0 = blockIdx.y * 128;
    const int n0 = blockIdx.x * 128;

    __shared__ uint32_t As[2][128 * 16];
    __shared__ uint32_t Bs[2][128 * 16];

    const int tid  = threadIdx.x;
    const int warp = tid >> 5;
    const int lane = tid & 31;
    const int q    = lane >> 2;
    const int tq   = lane & 3;
    const int warpM0 = (warp >> 1) * 32;
    const int warpN0 = (warp & 1) * 64;

    float acc[2][8][4];
    #pragma unroll
    for (int mt = 0; mt < 2; mt++)
        #pragma unroll
        for (int nt = 0; nt < 8; nt++)
            #pragma unroll
            for (int e = 0; e < 4; e++) acc[mt][nt][e] = 0.f;

    auto copyt = [&](int kc, int buf) {
        uint32_t sA = (uint32_t)__cvta_generic_to_shared(&As[buf][0]);
        uint32_t sB = (uint32_t)__cvta_generic_to_shared(&Bs[buf][0]);
        #pragma unroll
        for (int i = 0; i < 2; i++) {
            int idx = tid + i * 256;
            int m = idx >> 2, u = idx & 3;
            cpa16(sA + (m * 16 + u * 4) * 4,
                  (const uint4*)(Ag + (size_t)(m0 + m) * 512 + kc * 16) + u);
            cpa16(sB + (m * 16 + u * 4) * 4,
                  (const uint4*)(Wgp + (size_t)(n0 + m) * 512 + kc * 16) + u);
        }
    };

    copyt(0, 0); CPA_COMMIT();
    copyt(1, 1); CPA_COMMIT();

    for (int it = 0; it < 32; it++) {
        CPA_WAIT1();
        __syncthreads();
        int buf = it & 1;

        uint4 Ar[2], Ar8[2];
        #pragma unroll
        for (int mt = 0; mt < 2; mt++) {
            int r = warpM0 + mt * 16 + q;
            Ar[mt]  = *(const uint4*)&As[buf][r * 16 + tq * 4];
            Ar8[mt] = *(const uint4*)&As[buf][(r + 8) * 16 + tq * 4];
        }
        #pragma unroll
        for (int nt = 0; nt < 8; nt++) {
            int n = warpN0 + nt * 8 + q;
            uint4 Bv = *(const uint4*)&Bs[buf][n * 16 + tq * 4];
            #pragma unroll
            for (int mt = 0; mt < 2; mt++) {
                mma_f16(acc[mt][nt], Ar[mt].x, Ar8[mt].x, Ar[mt].y, Ar8[mt].y, Bv.x, Bv.y);
                mma_f16(acc[mt][nt], Ar[mt].z, Ar8[mt].z, Ar[mt].w, Ar8[mt].w, Bv.z, Bv.w);
            }
        }
        __syncthreads();
        if (it + 2 < 32) copyt(it + 2, buf);
        CPA_COMMIT();
    }

    const int h = (n0 + warpN0) >> 6;
    const int nb = n0 + warpN0;
    const float CsQ = 0.18033688011112158f;   // 0.125 * log2(e), folded into Q
    #pragma unroll
    for (int mt = 0; mt < 2; mt++)
        #pragma unroll
        for (int nt = 0; nt < 4; nt++) {
            int cl0 = nt * 8 + tq * 2;   // 0..31 within head
            float y1[4], y2[4];
            #pragma unroll
            for (int e = 0; e < 4; e++) {
                int row = m0 + warpM0 + mt * 16 + q + ((e >> 1) ? 8 : 0);
                int l = row & (Lc - 1);
                int cl = cl0 + (e & 1);
                float x1 = acc[mt][nt][e]     + bias[nb + cl];
                float x2 = acc[mt][nt + 4][e] + bias[nb + cl + 32];
                if (z <= 1) {
                    float c1 = cosb[l * 64 + cl],      s1 = sinb[l * 64 + cl];
                    float c2 = cosb[l * 64 + cl + 32], s2 = sinb[l * 64 + cl + 32];
                    y1[e] = x1 * c1 - x2 * s1;
                    y2[e] = x2 * c2 + x1 * s2;
                    if (z == 0) { y1[e] *= CsQ; y2[e] *= CsQ; }
                } else { y1[e] = x1; y2[e] = x2; }
            }
            #pragma unroll
            for (int h2 = 0; h2 < 2; h2++) {
                int row = m0 + warpM0 + mt * 16 + q + h2 * 8;
                int b = row >> 11, l = row & (Lc - 1);
                if (z == 3) {
                    size_t rb = (size_t)row * Dc + nb;
                    g_G[rb + cl0]      = 1.f / (1.f + __expf(-y1[2*h2]));
                    g_G[rb + cl0 + 1]  = 1.f / (1.f + __expf(-y1[2*h2+1]));
                    g_G[rb + cl0 + 32] = 1.f / (1.f + __expf(-y2[2*h2]));
                    g_G[rb + cl0 + 33] = 1.f / (1.f + __expf(-y2[2*h2+1]));
                } else if (z == 2) {
                    int kt2 = l >> 6, tk = l & 63, jp = tk >> 1;
                    int hoff = ((jp & 3) * 8 + (jp >> 2)) * 2 + (tk & 1);
                    __half* vrow = g_Vth + (((size_t)(b * Hc + h) * 32 + kt2) * 64) * 64;
                    vrow[(size_t)(cl0)      * 64 + hoff] = __float2half(y1[2*h2]);
                    vrow[(size_t)(cl0 + 1)  * 64 + hoff] = __float2half(y1[2*h2+1]);
                    vrow[(size_t)(cl0 + 32) * 64 + hoff] = __float2half(y2[2*h2]);
                    vrow[(size_t)(cl0 + 33) * 64 + hoff] = __float2half(y2[2*h2+1]);
                } else {
                    size_t drow = ((size_t)(b * Hc + h) * Lc + l) * 32;
                    uint32_t p1 = packh2(y1[2*h2], y1[2*h2+1]);
                    uint32_t p2 = packh2(y2[2*h2], y2[2*h2+1]);
                    int j1 = cl0 >> 1;
                    if (z == 0) {
                        g_Qh[drow + j1]      = p1;
                        g_Qh[drow + j1 + 16] = p2;
                    } else {
                        int pos = (j1 & 3) * 8 + (j1 >> 2);
                        g_Kh[drow + pos]     = p1;
                        g_Kh[drow + pos + 4] = p2;
                    }
                }
            }
        }
}

// ---- FP16 flash attention: fixed-shift softmax, half2 exp, l via MMA -------
__global__ __launch_bounds__(256, 2) void attn_tc_kernel()
{
    __shared__ uint32_t Ks[2][64 * 36];
    __shared__ uint32_t Vs[2][64 * 36];
    __shared__ uint32_t mk[2][32];

    const int qt  = blockIdx.x;
    const int bh  = blockIdx.y;
    const int b   = bh >> 4;
    const int h   = bh & 15;
    const int tid = threadIdx.x;
    const int warp = tid >> 5;
    const int lane = tid & 31;
    const int q    = lane >> 2;
    const int tq   = lane & 3;

    const uint32_t* Qg32 = g_Qh + ((size_t)bh * Lc + qt * 128 + warp * 16 + q) * 32;
    uint32_t qf[4][4];
    #pragma unroll
    for (int s = 0; s < 4; s++) {
        qf[s][0] = Qg32[8*s + tq];
        qf[s][1] = Qg32[256 + 8*s + tq];
        qf[s][2] = Qg32[8*s + tq + 4];
        qf[s][3] = Qg32[256 + 8*s + tq + 4];
    }

    float O[8][4];
    #pragma unroll
    for (int nt = 0; nt < 8; nt++)
        #pragma unroll
        for (int e = 0; e < 4; e++) O[nt][e] = 0.f;
    float lacc[4] = {0.f, 0.f, 0.f, 0.f};
    const uint32_t ONES = 0x3C003C00u;   // half2(1, 1)

    auto issue = [&](int kt) {
        int buf = kt & 1;
        uint32_t sK = (uint32_t)__cvta_generic_to_shared(&Ks[buf][0]);
        uint32_t sV = (uint32_t)__cvta_generic_to_shared(&Vs[buf][0]);
        const uint4* Kg4 = (const uint4*)(g_Kh + ((size_t)bh * Lc + kt * 64) * 32);
        const uint4* Vg4 = (const uint4*)g_Vth + ((size_t)(bh * 32 + kt)) * 512;
        #pragma unroll
        for (int i = 0; i < 2; i++) {
            int f = tid + i * 256;
            int n = f >> 3, u = f & 7;
            cpa16(sK + (n * 36 + u * 4) * 4, Kg4 + n * 8 + u);
            cpa16(sV + (n * 36 + u * 4) * 4, Vg4 + n * 8 + u);
        }
        if (tid < 8) {
            uint32_t sM = (uint32_t)__cvta_generic_to_shared(&mk[buf][0]);
            cpa16(sM + tid * 16, g_mkh + b * 1024 + kt * 32 + tid * 4);
        }
    };

    issue(0); CPA_COMMIT();
    issue(1); CPA_COMMIT();

    for (int kt = 0; kt < 32; kt++) {
        CPA_WAIT1();
        __syncthreads();
        int buf = kt & 1;

        float S[8][4];
        #pragma unroll
        for (int nt = 0; nt < 8; nt++)
            #pragma unroll
            for (int e = 0; e < 4; e++) S[nt][e] = 0.f;
        #pragma unroll
        for (int nt = 0; nt < 8; nt++) {
            const uint32_t* kr = &Ks[buf][(nt * 8 + q) * 36 + tq * 8];
            uint4 B1 = *(const uint4*)kr;
            uint4 B2 = *(const uint4*)(kr + 4);
            mma_f16(S[nt], qf[0][0], qf[0][1], qf[0][2], qf[0][3], B1.x, B1.y);
            mma_f16(S[nt], qf[1][0], qf[1][1], qf[1][2], qf[1][3], B1.z, B1.w);
            mma_f16(S[nt], qf[2][0], qf[2][1], qf[2][2], qf[2][3], B2.x, B2.y);
            mma_f16(S[nt], qf[3][0], qf[3][1], qf[3][2], qf[3][3], B2.z, B2.w);
        }

        uint32_t pp[8][2];
        #pragma unroll
        for (int nt = 0; nt < 8; nt++) {
            uint32_t mq = mk[buf][nt * 4 + tq];
            pp[nt][0] = ex2h2(hadd2u(packh2(S[nt][0], S[nt][1]), mq));
            pp[nt][1] = ex2h2(hadd2u(packh2(S[nt][2], S[nt][3]), mq));
        }

        mma_f16(lacc, pp[0][0], pp[0][1], pp[1][0], pp[1][1], ONES, ONES);
        mma_f16(lacc, pp[2][0], pp[2][1], pp[3][0], pp[3][1], ONES, ONES);
        mma_f16(lacc, pp[4][0], pp[4][1], pp[5][0], pp[5][1], ONES, ONES);
        mma_f16(lacc, pp[6][0], pp[6][1], pp[7][0], pp[7][1], ONES, ONES);

        #pragma unroll
        for (int nt = 0; nt < 8; nt++) {
            const uint32_t* vr = &Vs[buf][(nt * 8 + q) * 36 + tq * 8];
            uint4 V1 = *(const uint4*)vr;
            uint4 V2 = *(const uint4*)(vr + 4);
            mma_f16(O[nt], pp[0][0], pp[0][1], pp[1][0], pp[1][1], V1.x, V1.y);
            mma_f16(O[nt], pp[2][0], pp[2][1], pp[3][0], pp[3][1], V1.z, V1.w);
            mma_f16(O[nt], pp[4][0], pp[4][1], pp[5][0], pp[5][1], V2.x, V2.y);
            mma_f16(O[nt], pp[6][0], pp[6][1], pp[7][0], pp[7][1], V2.z, V2.w);
        }

        __syncthreads();
        if (kt + 2 < 32) issue(kt + 2);
        CPA_COMMIT();
    }

    float l0r = lacc[0], l1r = lacc[2];
    float inv0 = (l0r > 0.f) ? (1.f / l0r) : 0.f;
    float inv1 = (l1r > 0.f) ? (1.f / l1r) : 0.f;
    int r0 = qt * 128 + warp * 16 + q;
    size_t tok0 = (size_t)b * Lc + r0;
    size_t tok1 = tok0 + 8;
    #pragma unroll
    for (int nt = 0; nt < 8; nt++) {
        int n = h * 64 + nt * 8 + tq * 2;
        float o0 = O[nt][0] * inv0 * g_G[tok0 * Dc + n];
        float o1 = O[nt][1] * inv0 * g_G[tok0 * Dc + n + 1];
        float o2 = O[nt][2] * inv1 * g_G[tok1 * Dc + n];
        float o3 = O[nt][3] * inv1 * g_G[tok1 * Dc + n + 1];
        int J = n >> 1, chnk = J >> 4, jj = J & 15;
        int pos = (jj >> 2) + (jj & 1) * 4 + ((jj >> 1) & 1) * 8;
        g_AOh[tok0 * 512 + chnk * 16 + pos] = packh2(o0, o1);
        g_AOh[tok1 * 512 + chnk * 16 + pos] = packh2(o2, o3);
    }
}

// ---- FP16 output projection GEMM, 128x128 tile, cp.async -------------------
__global__ __launch_bounds__(256) void out_gemm_tc(
    const float* __restrict__ bo, float* __restrict__ out)
{
    const uint32_t* Ag  = g_AOh;
    const uint32_t* Wgp = g_H + SEGW + (size_t)4 * WS;

    const int m0 = blockIdx.y * 128;
    const int n0 = blockIdx.x * 128;

    __shared__ uint32_t As[2][128 * 16];
    __shared__ uint32_t Bs[2][128 * 16];

    const int tid  = threadIdx.x;
    const int warp = tid >> 5;
    const int lane = tid & 31;
    const int q    = lane >> 2;
    const int tq   = lane & 3;
    const int warpM0 = (warp >> 1) * 32;
    const int warpN0 = (warp & 1) * 64;

    float acc[2][8][4];
    #pragma unroll
    for (int mt = 0; mt < 2; mt++)
        #pragma unroll
        for (int nt = 0; nt < 8; nt++)
            #pragma unroll
            for (int e = 0; e < 4; e++) acc[mt][nt][e] = 0.f;

    auto copyt = [&](int kc, int buf) {
        uint32_t sA = (uint32_t)__cvta_generic_to_shared(&As[buf][0]);
        uint32_t sB = (uint32_t)__cvta_generic_to_shared(&Bs[buf][0]);
        #pragma unroll
        for (int i = 0; i < 2; i++) {
            int idx = tid + i * 256;
            int m = idx >> 2, u = idx & 3;
            cpa16(sA + (m * 16 + u * 4) * 4,
                  (const uint4*)(Ag + (size_t)(m0 + m) * 512 + kc * 16) + u);
            cpa16(sB + (m * 16 + u * 4) * 4,
                  (const uint4*)(Wgp + (size_t)(n0 + m) * 512 + kc * 16) + u);
        }
    };

    copyt(0, 0); CPA_COMMIT();
    copyt(1, 1); CPA_COMMIT();

    for (int it = 0; it < 32; it++) {
        CPA_WAIT1();
        __syncthreads();
        int buf = it & 1;

        uint4 Ar[2], Ar8[2];
        #pragma unroll
        for (int mt = 0; mt < 2; mt++) {
            int r = warpM0 + mt * 16 + q;
            Ar[mt]  = *(const uint4*)&As[buf][r * 16 + tq * 4];
            Ar8[mt] = *(const uint4*)&As[buf][(r + 8) * 16 + tq * 4];
        }
        #pragma unroll
        for (int nt = 0; nt < 8; nt++) {
            int n = warpN0 + nt * 8 + q;
            uint4 Bv = *(const uint4*)&Bs[buf][n * 16 + tq * 4];
            #pragma unroll
            for (int mt = 0; mt < 2; mt++) {
                mma_f16(acc[mt][nt], Ar[mt].x, Ar8[mt].x, Ar[mt].y, Ar8[mt].y, Bv.x, Bv.y);
                mma_f16(acc[mt][nt], Ar[mt].z, Ar8[mt].z, Ar[mt].w, Ar8[mt].w, Bv.z, Bv.w);
            }
        }
        __syncthreads();
        if (it + 2 < 32) copyt(it + 2, buf);
        CPA_COMMIT();
    }

    #pragma unroll
    for (int mt = 0; mt < 2; mt++)
        #pragma unroll
        for (int nt = 0; nt < 8; nt++)
            #pragma unroll
            for (int e = 0; e < 4; e++) {
                int row = m0 + warpM0 + mt * 16 + q + ((e >> 1) ? 8 : 0);
                int col = n0 + warpN0 + nt * 8 + tq * 2 + (e & 1);
                out[(size_t)row * Dc + col] = acc[mt][nt][e] + bo[col];
            }
}

// ---- launch -----------------------------------------------------------------
extern "C" void kernel_launch(void* const* d_in, const int* in_sizes, int n_in,
                              void* d_out, int out_size)
{
    const float* query   = (const float*)d_in[0];
    const float* key_in  = (const float*)d_in[1];
    const float* value   = (const float*)d_in[2];
    const unsigned char* maskraw = (const unsigned char*)d_in[3];
    const float* rope_cos = (const float*)d_in[4];
    const float* rope_sin = (const float*)d_in[5];
    const float* Wq = (const float*)d_in[6];
    const float* bq = (const float*)d_in[7];
    const float* Wk = (const float*)d_in[8];
    const float* bk = (const float*)d_in[9];
    const float* Wv = (const float*)d_in[10];
    const float* bv = (const float*)d_in[11];
    const float* Wg = (const float*)d_in[12];
    const float* bg = (const float*)d_in[13];
    const float* Wo = (const float*)d_in[14];
    const float* bo = (const float*)d_in[15];
    float* out = (float*)d_out;

    (void)in_sizes; (void)n_in; (void)out_size;

    mask_decode_kernel<<<1, 1024>>>(maskraw);
    prep_half<<<dim3(4096, 1, 8), 256>>>(query, key_in, value, Wq, Wk, Wv, Wg, Wo);
    proj_gemm_tc<<<dim3(8, 32, 4), 256>>>(bq, bk, bv, bg, rope_cos, rope_sin);
    attn_tc_kernel<<<dim3(16, 32), 256>>>();
    out_gemm_tc<<<dim3(8, 32), 256>>>(bo, out);
}

// round 14
// speedup vs baseline: 2.4862x; 1.0311x over previous
#include <cuda_runtime.h>
#include <cuda_fp16.h>
#include <stdint.h>
#include <math.h>

#define Bc   2
#define Lc   2048
#define Dc   1024
#define Hc   16
#define NT   4096
#define BHc  32

#define SEG1 (4096*512)
#define SEGW (3*4096*512)
#define WS   (1024*512)
__device__ uint32_t g_H[(size_t)(3*4096 + 5*1024)*512];
__device__ uint32_t g_Qh[(size_t)BHc*Lc*32];     // plain half-pair rows of 32 (pre-scaled by Cs)
__device__ uint32_t g_Kh[(size_t)BHc*Lc*32];     // attn-permuted rows of 32
__device__ __half   g_Vth[(size_t)BHc*32*64*64]; // attn-smem-image half V
__device__ float    g_G [(size_t)NT*Dc];
__device__ uint32_t g_AOh[(size_t)NT*512];       // chunk-permuted half
__device__ int      g_mask[NT];
__device__ uint32_t g_mkh[NT/2];                 // half2 additive mask (-4 live / -3e4 masked)

__device__ __forceinline__ uint32_t packh2(float a, float b) {
    __half2 h = __floats2half2_rn(a, b);
    return *reinterpret_cast<uint32_t*>(&h);
}
__device__ __forceinline__ uint32_t hadd2u(uint32_t a, uint32_t b) {
    uint32_t r;
    asm("add.f16x2 %0, %1, %2;" : "=r"(r) : "r"(a), "r"(b));
    return r;
}
__device__ __forceinline__ uint32_t ex2h2(uint32_t a) {
    uint32_t r;
    asm("ex2.approx.f16x2 %0, %1;" : "=r"(r) : "r"(a));
    return r;
}
__device__ __forceinline__ void mma_f16(
    float* d, uint32_t a0, uint32_t a1, uint32_t a2, uint32_t a3,
    uint32_t b0, uint32_t b1)
{
    asm volatile(
        "mma.sync.aligned.m16n8k16.row.col.f32.f16.f16.f32 "
        "{%0,%1,%2,%3}, {%4,%5,%6,%7}, {%8,%9}, {%0,%1,%2,%3};\n"
        : "+f"(d[0]), "+f"(d[1]), "+f"(d[2]), "+f"(d[3])
        : "r"(a0), "r"(a1), "r"(a2), "r"(a3), "r"(b0), "r"(b1));
}
__device__ __forceinline__ void cpa16(uint32_t dst, const void* src) {
    asm volatile("cp.async.ca.shared.global [%0], [%1], 16;"
                 :: "r"(dst), "l"(src) : "memory");
}
#define CPA_COMMIT() asm volatile("cp.async.commit_group;" ::: "memory")
#define CPA_WAIT1()  asm volatile("cp.async.wait_group 1;" ::: "memory")

__global__ void mask_decode_kernel(const unsigned char* __restrict__ raw) {
    __shared__ int cnt[4];
    int tid = threadIdx.x;
    if (tid < 4) cnt[tid] = 0;
    __syncthreads();
    for (int i = tid; i < NT; i += blockDim.x)
        if (raw[i]) atomicAdd(&cnt[i & 3], 1);
    __syncthreads();
    int c0 = cnt[0], c1 = cnt[1], c2 = cnt[2], c3 = cnt[3];
    int mode;
    if (c0 > 0 && c1 == 0 && c2 == 0 && c3 == 0)       mode = 1;
    else if ((c2 > 0 || c3 > 0) && c0 == 0 && c1 == 0) mode = 2;
    else                                               mode = 0;
    for (int i = tid; i < NT; i += blockDim.x) {
        int v;
        if (mode == 0)      v = (raw[i] != 0);
        else if (mode == 1) v = (((const int*)raw)[i] != 0);
        else                v = (((const float*)raw)[i] != 0.0f);
        g_mask[i] = v;
    }
    __syncthreads();
    for (int i = tid; i < NT / 2; i += blockDim.x) {
        float m0 = g_mask[2*i]     ? -30000.f : -4.0f;
        float m1 = g_mask[2*i + 1] ? -30000.f : -4.0f;
        g_mkh[i] = packh2(m0, m1);
    }
}

__global__ void prep_half(
    const float* __restrict__ q, const float* __restrict__ k,
    const float* __restrict__ v,
    const float* __restrict__ wq, const float* __restrict__ wk,
    const float* __restrict__ wv, const float* __restrict__ wg,
    const float* __restrict__ wo)
{
    int z = blockIdx.z, row = blockIdx.x, t = threadIdx.x;
    const float* src; size_t off;
    if (z < 3) {
        src = (z == 0) ? q : ((z == 1) ? k : v);
        off = (size_t)z * SEG1;
    } else {
        if (row >= 1024) return;
        src = (z == 3) ? wq : ((z == 4) ? wk : ((z == 5) ? wv : ((z == 6) ? wg : wo)));
        off = (size_t)SEGW + (size_t)(z - 3) * WS;
    }
    float4 val = ((const float4*)src)[(size_t)row * 256 + t];
    int ch = t >> 3, c = t & 7;
    uint32_t* dst = g_H + off + (size_t)row * 512 + ch * 16 + (c & 1) * 8 + (c >> 1);
    dst[0] = packh2(val.x, val.y);
    dst[4] = packh2(val.z, val.w);
}

// ---- FP16 projection GEMM, 128x128 tile, 3-stage pipeline, fused RoPE ------
// dynamic smem: 3 stages x (As 2048 + Bs 2048) u32 = 49152 B
__global__ __launch_bounds__(256) void proj_gemm_tc(
    const float* __restrict__ bq, const float* __restrict__ bk,
    const float* __restrict__ bv, const float* __restrict__ bg,
    const float* __restrict__ cosb, const float* __restrict__ sinb)
{
    extern __shared__ uint32_t dsm[];
    const int z = blockIdx.z;
    const uint32_t* Ag  = g_H + ((z == 3) ? 0 : (size_t)z * SEG1);
    const uint32_t* Wgp = g_H + SEGW + (size_t)z * WS;
    const float* bias = (z == 0) ? bq : ((z == 1) ? bk : ((z == 2) ? bv : bg));

    const int m0 = blockIdx.y * 128;
    const int n0 = blockIdx.x * 128;

    const int tid  = threadIdx.x;
    const int warp = tid >> 5;
    const int lane = tid & 31;
    const int q    = lane >> 2;
    const int tq   = lane & 3;
    const int warpM0 = (warp >> 1) * 32;
    const int warpN0 = (warp & 1) * 64;

    float acc[2][8][4];
    #pragma unroll
    for (int mt = 0; mt < 2; mt++)
        #pragma unroll
        for (int nt = 0; nt < 8; nt++)
            #pragma unroll
            for (int e = 0; e < 4; e++) acc[mt][nt][e] = 0.f;

    auto copyt = [&](int kc, int s) {
        uint32_t sA = (uint32_t)__cvta_generic_to_shared(dsm + s * 4096);
        uint32_t sB = sA + 2048 * 4;
        #pragma unroll
        for (int i = 0; i < 2; i++) {
            int idx = tid + i * 256;
            int m = idx >> 2, u = idx & 3;
            cpa16(sA + (m * 16 + u * 4) * 4,
                  (const uint4*)(Ag + (size_t)(m0 + m) * 512 + kc * 16) + u);
            cpa16(sB + (m * 16 + u * 4) * 4,
                  (const uint4*)(Wgp + (size_t)(n0 + m) * 512 + kc * 16) + u);
        }
    };

    copyt(0, 0); CPA_COMMIT();
    copyt(1, 1); CPA_COMMIT();

    int buf = 0;
    for (int it = 0; it < 32; it++) {
        CPA_WAIT1();
        __syncthreads();                  // all warps done with it-1; tile it visible
        if (it + 2 < 32) {
            int s = buf + 2; if (s >= 3) s -= 3;
            copyt(it + 2, s);
        }
        CPA_COMMIT();

        const uint32_t* As = dsm + buf * 4096;
        const uint32_t* Bs = As + 2048;

        uint4 Ar[2], Ar8[2];
        #pragma unroll
        for (int mt = 0; mt < 2; mt++) {
            int r = warpM0 + mt * 16 + q;
            Ar[mt]  = *(const uint4*)&As[r * 16 + tq * 4];
            Ar8[mt] = *(const uint4*)&As[(r + 8) * 16 + tq * 4];
        }
        #pragma unroll
        for (int nt = 0; nt < 8; nt++) {
            int n = warpN0 + nt * 8 + q;
            uint4 Bv = *(const uint4*)&Bs[n * 16 + tq * 4];
            #pragma unroll
            for (int mt = 0; mt < 2; mt++) {
                mma_f16(acc[mt][nt], Ar[mt].x, Ar8[mt].x, Ar[mt].y, Ar8[mt].y, Bv.x, Bv.y);
                mma_f16(acc[mt][nt], Ar[mt].z, Ar8[mt].z, Ar[mt].w, Ar8[mt].w, Bv.z, Bv.w);
            }
        }
        if (++buf == 3) buf = 0;
    }

    const int h = (n0 + warpN0) >> 6;
    const int nb = n0 + warpN0;
    const float CsQ = 0.18033688011112158f;   // 0.125 * log2(e), folded into Q
    #pragma unroll
    for (int mt = 0; mt < 2; mt++)
        #pragma unroll
        for (int nt = 0; nt < 4; nt++) {
            int cl0 = nt * 8 + tq * 2;   // 0..31 within head
            float y1[4], y2[4];
            #pragma unroll
            for (int e = 0; e < 4; e++) {
                int row = m0 + warpM0 + mt * 16 + q + ((e >> 1) ? 8 : 0);
                int l = row & (Lc - 1);
                int cl = cl0 + (e & 1);
                float x1 = acc[mt][nt][e]     + bias[nb + cl];
                float x2 = acc[mt][nt + 4][e] + bias[nb + cl + 32];
                if (z <= 1) {
                    float c1 = cosb[l * 64 + cl],      s1 = sinb[l * 64 + cl];
                    float c2 = cosb[l * 64 + cl + 32], s2 = sinb[l * 64 + cl + 32];
                    y1[e] = x1 * c1 - x2 * s1;
                    y2[e] = x2 * c2 + x1 * s2;
                    if (z == 0) { y1[e] *= CsQ; y2[e] *= CsQ; }
                } else { y1[e] = x1; y2[e] = x2; }
            }
            #pragma unroll
            for (int h2 = 0; h2 < 2; h2++) {
                int row = m0 + warpM0 + mt * 16 + q + h2 * 8;
                int b = row >> 11, l = row & (Lc - 1);
                if (z == 3) {
                    size_t rb = (size_t)row * Dc + nb;
                    g_G[rb + cl0]      = 1.f / (1.f + __expf(-y1[2*h2]));
                    g_G[rb + cl0 + 1]  = 1.f / (1.f + __expf(-y1[2*h2+1]));
                    g_G[rb + cl0 + 32] = 1.f / (1.f + __expf(-y2[2*h2]));
                    g_G[rb + cl0 + 33] = 1.f / (1.f + __expf(-y2[2*h2+1]));
                } else if (z == 2) {
                    int kt2 = l >> 6, tk = l & 63, jp = tk >> 1;
                    int hoff = ((jp & 3) * 8 + (jp >> 2)) * 2 + (tk & 1);
                    __half* vrow = g_Vth + (((size_t)(b * Hc + h) * 32 + kt2) * 64) * 64;
                    vrow[(size_t)(cl0)      * 64 + hoff] = __float2half(y1[2*h2]);
                    vrow[(size_t)(cl0 + 1)  * 64 + hoff] = __float2half(y1[2*h2+1]);
                    vrow[(size_t)(cl0 + 32) * 64 + hoff] = __float2half(y2[2*h2]);
                    vrow[(size_t)(cl0 + 33) * 64 + hoff] = __float2half(y2[2*h2+1]);
                } else {
                    size_t drow = ((size_t)(b * Hc + h) * Lc + l) * 32;
                    uint32_t p1 = packh2(y1[2*h2], y1[2*h2+1]);
                    uint32_t p2 = packh2(y2[2*h2], y2[2*h2+1]);
                    int j1 = cl0 >> 1;
                    if (z == 0) {
                        g_Qh[drow + j1]      = p1;
                        g_Qh[drow + j1 + 16] = p2;
                    } else {
                        int pos = (j1 & 3) * 8 + (j1 >> 2);
                        g_Kh[drow + pos]     = p1;
                        g_Kh[drow + pos + 4] = p2;
                    }
                }
            }
        }
}

// ---- FP16 flash attention: 3-stage pipeline, fixed-shift softmax -----------
// dynamic smem: 3 stages x (Ks 2304 + Vs 2304 + mk 32) u32 = 55680 B
__global__ __launch_bounds__(256, 2) void attn_tc_kernel()
{
    extern __shared__ uint32_t dsm[];
    const int qt  = blockIdx.x;
    const int bh  = blockIdx.y;
    const int b   = bh >> 4;
    const int h   = bh & 15;
    const int tid = threadIdx.x;
    const int warp = tid >> 5;
    const int lane = tid & 31;
    const int q    = lane >> 2;
    const int tq   = lane & 3;

    const uint32_t* Qg32 = g_Qh + ((size_t)bh * Lc + qt * 128 + warp * 16 + q) * 32;
    uint32_t qf[4][4];
    #pragma unroll
    for (int s = 0; s < 4; s++) {
        qf[s][0] = Qg32[8*s + tq];
        qf[s][1] = Qg32[256 + 8*s + tq];
        qf[s][2] = Qg32[8*s + tq + 4];
        qf[s][3] = Qg32[256 + 8*s + tq + 4];
    }

    float O[8][4];
    #pragma unroll
    for (int nt = 0; nt < 8; nt++)
        #pragma unroll
        for (int e = 0; e < 4; e++) O[nt][e] = 0.f;
    float lacc[4] = {0.f, 0.f, 0.f, 0.f};
    const uint32_t ONES = 0x3C003C00u;   // half2(1, 1)

    auto issue = [&](int kt, int s) {
        uint32_t base = (uint32_t)__cvta_generic_to_shared(dsm + s * 4640);
        uint32_t sK = base;
        uint32_t sV = base + 2304 * 4;
        const uint4* Kg4 = (const uint4*)(g_Kh + ((size_t)bh * Lc + kt * 64) * 32);
        const uint4* Vg4 = (const uint4*)g_Vth + ((size_t)(bh * 32 + kt)) * 512;
        #pragma unroll
        for (int i = 0; i < 2; i++) {
            int f = tid + i * 256;
            int n = f >> 3, u = f & 7;
            cpa16(sK + (n * 36 + u * 4) * 4, Kg4 + n * 8 + u);
            cpa16(sV + (n * 36 + u * 4) * 4, Vg4 + n * 8 + u);
        }
        if (tid < 8)
            cpa16(base + 4608 * 4 + tid * 16, g_mkh + b * 1024 + kt * 32 + tid * 4);
    };

    issue(0, 0); CPA_COMMIT();
    issue(1, 1); CPA_COMMIT();

    int buf = 0;
    for (int kt = 0; kt < 32; kt++) {
        CPA_WAIT1();
        __syncthreads();
        if (kt + 2 < 32) {
            int s = buf + 2; if (s >= 3) s -= 3;
            issue(kt + 2, s);
        }
        CPA_COMMIT();

        const uint32_t* Ks = dsm + buf * 4640;
        const uint32_t* Vs = Ks + 2304;
        const uint32_t* mk = Ks + 4608;

        float S[8][4];
        #pragma unroll
        for (int nt = 0; nt < 8; nt++)
            #pragma unroll
            for (int e = 0; e < 4; e++) S[nt][e] = 0.f;
        #pragma unroll
        for (int nt = 0; nt < 8; nt++) {
            const uint32_t* kr = &Ks[(nt * 8 + q) * 36 + tq * 8];
            uint4 B1 = *(const uint4*)kr;
            uint4 B2 = *(const uint4*)(kr + 4);
            mma_f16(S[nt], qf[0][0], qf[0][1], qf[0][2], qf[0][3], B1.x, B1.y);
            mma_f16(S[nt], qf[1][0], qf[1][1], qf[1][2], qf[1][3], B1.z, B1.w);
            mma_f16(S[nt], qf[2][0], qf[2][1], qf[2][2], qf[2][3], B2.x, B2.y);
            mma_f16(S[nt], qf[3][0], qf[3][1], qf[3][2], qf[3][3], B2.z, B2.w);
        }

        uint32_t pp[8][2];
        #pragma unroll
        for (int nt = 0; nt < 8; nt++) {
            uint32_t mq = mk[nt * 4 + tq];
            pp[nt][0] = ex2h2(hadd2u(packh2(S[nt][0], S[nt][1]), mq));
            pp[nt][1] = ex2h2(hadd2u(packh2(S[nt][2], S[nt][3]), mq));
        }

        mma_f16(lacc, pp[0][0], pp[0][1], pp[1][0], pp[1][1], ONES, ONES);
        mma_f16(lacc, pp[2][0], pp[2][1], pp[3][0], pp[3][1], ONES, ONES);
        mma_f16(lacc, pp[4][0], pp[4][1], pp[5][0], pp[5][1], ONES, ONES);
        mma_f16(lacc, pp[6][0], pp[6][1], pp[7][0], pp[7][1], ONES, ONES);

        #pragma unroll
        for (int nt = 0; nt < 8; nt++) {
            const uint32_t* vr = &Vs[(nt * 8 + q) * 36 + tq * 8];
            uint4 V1 = *(const uint4*)vr;
            uint4 V2 = *(const uint4*)(vr + 4);
            mma_f16(O[nt], pp[0][0], pp[0][1], pp[1][0], pp[1][1], V1.x, V1.y);
            mma_f16(O[nt], pp[2][0], pp[2][1], pp[3][0], pp[3][1], V1.z, V1.w);
            mma_f16(O[nt], pp[4][0], pp[4][1], pp[5][0], pp[5][1], V2.x, V2.y);
            mma_f16(O[nt], pp[6][0], pp[6][1], pp[7][0], pp[7][1], V2.z, V2.w);
        }
        if (++buf == 3) buf = 0;
    }

    float l0r = lacc[0], l1r = lacc[2];
    float inv0 = (l0r > 0.f) ? (1.f / l0r) : 0.f;
    float inv1 = (l1r > 0.f) ? (1.f / l1r) : 0.f;
    int r0 = qt * 128 + warp * 16 + q;
    size_t tok0 = (size_t)b * Lc + r0;
    size_t tok1 = tok0 + 8;
    #pragma unroll
    for (int nt = 0; nt < 8; nt++) {
        int n = h * 64 + nt * 8 + tq * 2;
        float o0 = O[nt][0] * inv0 * g_G[tok0 * Dc + n];
        float o1 = O[nt][1] * inv0 * g_G[tok0 * Dc + n + 1];
        float o2 = O[nt][2] * inv1 * g_G[tok1 * Dc + n];
        float o3 = O[nt][3] * inv1 * g_G[tok1 * Dc + n + 1];
        int J = n >> 1, chnk = J >> 4, jj = J & 15;
        int pos = (jj >> 2) + (jj & 1) * 4 + ((jj >> 1) & 1) * 8;
        g_AOh[tok0 * 512 + chnk * 16 + pos] = packh2(o0, o1);
        g_AOh[tok1 * 512 + chnk * 16 + pos] = packh2(o2, o3);
    }
}

// ---- FP16 output projection GEMM, 128x128 tile, 3-stage pipeline -----------
__global__ __launch_bounds__(256) void out_gemm_tc(
    const float* __restrict__ bo, float* __restrict__ out)
{
    extern __shared__ uint32_t dsm[];
    const uint32_t* Ag  = g_AOh;
    const uint32_t* Wgp = g_H + SEGW + (size_t)4 * WS;

    const int m0 = blockIdx.y * 128;
    const int n0 = blockIdx.x * 128;

    const int tid  = threadIdx.x;
    const int warp = tid >> 5;
    const int lane = tid & 31;
    const int q    = lane >> 2;
    const int tq   = lane & 3;
    const int warpM0 = (warp >> 1) * 32;
    const int warpN0 = (warp & 1) * 64;

    float acc[2][8][4];
    #pragma unroll
    for (int mt = 0; mt < 2; mt++)
        #pragma unroll
        for (int nt = 0; nt < 8; nt++)
            #pragma unroll
            for (int e = 0; e < 4; e++) acc[mt][nt][e] = 0.f;

    auto copyt = [&](int kc, int s) {
        uint32_t sA = (uint32_t)__cvta_generic_to_shared(dsm + s * 4096);
        uint32_t sB = sA + 2048 * 4;
        #pragma unroll
        for (int i = 0; i < 2; i++) {
            int idx = tid + i * 256;
            int m = idx >> 2, u = idx & 3;
            cpa16(sA + (m * 16 + u * 4) * 4,
                  (const uint4*)(Ag + (size_t)(m0 + m) * 512 + kc * 16) + u);
            cpa16(sB + (m * 16 + u * 4) * 4,
                  (const uint4*)(Wgp + (size_t)(n0 + m) * 512 + kc * 16) + u);
        }
    };

    copyt(0, 0); CPA_COMMIT();
    copyt(1, 1); CPA_COMMIT();

    int buf = 0;
    for (int it = 0; it < 32; it++) {
        CPA_WAIT1();
        __syncthreads();
        if (it + 2 < 32) {
            int s = buf + 2; if (s >= 3) s -= 3;
            copyt(it + 2, s);
        }
        CPA_COMMIT();

        const uint32_t* As = dsm + buf * 4096;
        const uint32_t* Bs = As + 2048;

        uint4 Ar[2], Ar8[2];
        #pragma unroll
        for (int mt = 0; mt < 2; mt++) {
            int r = warpM0 + mt * 16 + q;
            Ar[mt]  = *(const uint4*)&As[r * 16 + tq * 4];
            Ar8[mt] = *(const uint4*)&As[(r + 8) * 16 + tq * 4];
        }
        #pragma unroll
        for (int nt = 0; nt < 8; nt++) {
            int n = warpN0 + nt * 8 + q;
            uint4 Bv = *(const uint4*)&Bs[n * 16 + tq * 4];
            #pragma unroll
            for (int mt = 0; mt < 2; mt++) {
                mma_f16(acc[mt][nt], Ar[mt].x, Ar8[mt].x, Ar[mt].y, Ar8[mt].y, Bv.x, Bv.y);
                mma_f16(acc[mt][nt], Ar[mt].z, Ar8[mt].z, Ar[mt].w, Ar8[mt].w, Bv.z, Bv.w);
            }
        }
        if (++buf == 3) buf = 0;
    }

    #pragma unroll
    for (int mt = 0; mt < 2; mt++)
        #pragma unroll
        for (int nt = 0; nt < 8; nt++)
            #pragma unroll
            for (int e = 0; e < 4; e++) {
                int row = m0 + warpM0 + mt * 16 + q + ((e >> 1) ? 8 : 0);
                int col = n0 + warpN0 + nt * 8 + tq * 2 + (e & 1);
                out[(size_t)row * Dc + col] = acc[mt][nt][e] + bo[col];
            }
}

// ---- launch -----------------------------------------------------------------
#define GEMM_SMEM 49152
#define ATTN_SMEM 55680

extern "C" void kernel_launch(void* const* d_in, const int* in_sizes, int n_in,
                              void* d_out, int out_size)
{
    const float* query   = (const float*)d_in[0];
    const float* key_in  = (const float*)d_in[1];
    const float* value   = (const float*)d_in[2];
    const unsigned char* maskraw = (const unsigned char*)d_in[3];
    const float* rope_cos = (const float*)d_in[4];
    const float* rope_sin = (const float*)d_in[5];
    const float* Wq = (const float*)d_in[6];
    const float* bq = (const float*)d_in[7];
    const float* Wk = (const float*)d_in[8];
    const float* bk = (const float*)d_in[9];
    const float* Wv = (const float*)d_in[10];
    const float* bv = (const float*)d_in[11];
    const float* Wg = (const float*)d_in[12];
    const float* bg = (const float*)d_in[13];
    const float* Wo = (const float*)d_in[14];
    const float* bo = (const float*)d_in[15];
    float* out = (float*)d_out;

    (void)in_sizes; (void)n_in; (void)out_size;

    cudaFuncSetAttribute(proj_gemm_tc,
                         cudaFuncAttributeMaxDynamicSharedMemorySize, GEMM_SMEM);
    cudaFuncSetAttribute(attn_tc_kernel,
                         cudaFuncAttributeMaxDynamicSharedMemorySize, ATTN_SMEM);
    cudaFuncSetAttribute(out_gemm_tc,
                         cudaFuncAttributeMaxDynamicSharedMemorySize, GEMM_SMEM);

    mask_decode_kernel<<<1, 1024>>>(maskraw);
    prep_half<<<dim3(4096, 1, 8), 256>>>(query, key_in, value, Wq, Wk, Wv, Wg, Wo);
    proj_gemm_tc<<<dim3(8, 32, 4), 256, GEMM_SMEM>>>(bq, bk, bv, bg, rope_cos, rope_sin);
    attn_tc_kernel<<<dim3(16, 32), 256, ATTN_SMEM>>>();
    out_gemm_tc<<<dim3(8, 32), 256, GEMM_SMEM>>>(bo, out);
}

// round 16
// speedup vs baseline: 2.5166x; 1.0122x over previous
#include <cuda_runtime.h>
#include <cuda_fp16.h>
#include <stdint.h>
#include <math.h>

#define Bc   2
#define Lc   2048
#define Dc   1024
#define Hc   16
#define NT   4096
#define BHc  32

#define SEG1 (4096*512)
#define SEGW (3*4096*512)
#define WS   (1024*512)
__device__ uint32_t g_H[(size_t)(3*4096 + 5*1024)*512];
__device__ uint32_t g_Qh[(size_t)BHc*Lc*32];     // plain half-pair rows of 32 (pre-scaled by Cs)
__device__ uint32_t g_Kh[(size_t)BHc*Lc*32];     // attn-permuted rows of 32
__device__ __half   g_Vth[(size_t)BHc*32*64*64]; // attn-smem-image half V
__device__ float    g_G [(size_t)NT*Dc];
__device__ uint32_t g_AOh[(size_t)NT*512];       // chunk-permuted half
__device__ int      g_mask[NT];
__device__ uint32_t g_mkh[NT/2];                 // half2 additive mask (-4 live / -3e4 masked)

__device__ __forceinline__ uint32_t packh2(float a, float b) {
    __half2 h = __floats2half2_rn(a, b);
    return *reinterpret_cast<uint32_t*>(&h);
}
__device__ __forceinline__ uint32_t hadd2u(uint32_t a, uint32_t b) {
    uint32_t r;
    asm("add.f16x2 %0, %1, %2;" : "=r"(r) : "r"(a), "r"(b));
    return r;
}
__device__ __forceinline__ uint32_t ex2h2(uint32_t a) {
    uint32_t r;
    asm("ex2.approx.f16x2 %0, %1;" : "=r"(r) : "r"(a));
    return r;
}
__device__ __forceinline__ void mma_f16(
    float* d, uint32_t a0, uint32_t a1, uint32_t a2, uint32_t a3,
    uint32_t b0, uint32_t b1)
{
    asm volatile(
        "mma.sync.aligned.m16n8k16.row.col.f32.f16.f16.f32 "
        "{%0,%1,%2,%3}, {%4,%5,%6,%7}, {%8,%9}, {%0,%1,%2,%3};\n"
        : "+f"(d[0]), "+f"(d[1]), "+f"(d[2]), "+f"(d[3])
        : "r"(a0), "r"(a1), "r"(a2), "r"(a3), "r"(b0), "r"(b1));
}
__device__ __forceinline__ void cpa16(uint32_t dst, const void* src) {
    asm volatile("cp.async.ca.shared.global [%0], [%1], 16;"
                 :: "r"(dst), "l"(src) : "memory");
}
#define CPA_COMMIT() asm volatile("cp.async.commit_group;" ::: "memory")
#define CPA_WAIT1()  asm volatile("cp.async.wait_group 1;" ::: "memory")

__global__ void mask_decode_kernel(const unsigned char* __restrict__ raw) {
    __shared__ int cnt[4];
    int tid = threadIdx.x;
    if (tid < 4) cnt[tid] = 0;
    __syncthreads();
    for (int i = tid; i < NT; i += blockDim.x)
        if (raw[i]) atomicAdd(&cnt[i & 3], 1);
    __syncthreads();
    int c0 = cnt[0], c1 = cnt[1], c2 = cnt[2], c3 = cnt[3];
    int mode;
    if (c0 > 0 && c1 == 0 && c2 == 0 && c3 == 0)       mode = 1;
    else if ((c2 > 0 || c3 > 0) && c0 == 0 && c1 == 0) mode = 2;
    else                                               mode = 0;
    for (int i = tid; i < NT; i += blockDim.x) {
        int v;
        if (mode == 0)      v = (raw[i] != 0);
        else if (mode == 1) v = (((const int*)raw)[i] != 0);
        else                v = (((const float*)raw)[i] != 0.0f);
        g_mask[i] = v;
    }
    __syncthreads();
    for (int i = tid; i < NT / 2; i += blockDim.x) {
        float m0 = g_mask[2*i]     ? -30000.f : -4.0f;
        float m1 = g_mask[2*i + 1] ? -30000.f : -4.0f;
        g_mkh[i] = packh2(m0, m1);
    }
}

__global__ void prep_half(
    const float* __restrict__ q, const float* __restrict__ k,
    const float* __restrict__ v,
    const float* __restrict__ wq, const float* __restrict__ wk,
    const float* __restrict__ wv, const float* __restrict__ wg,
    const float* __restrict__ wo)
{
    int z = blockIdx.z, row = blockIdx.x, t = threadIdx.x;
    const float* src; size_t off;
    if (z < 3) {
        src = (z == 0) ? q : ((z == 1) ? k : v);
        off = (size_t)z * SEG1;
    } else {
        if (row >= 1024) return;
        src = (z == 3) ? wq : ((z == 4) ? wk : ((z == 5) ? wv : ((z == 6) ? wg : wo)));
        off = (size_t)SEGW + (size_t)(z - 3) * WS;
    }
    float4 val = ((const float4*)src)[(size_t)row * 256 + t];
    int ch = t >> 3, c = t & 7;
    uint32_t* dst = g_H + off + (size_t)row * 512 + ch * 16 + (c & 1) * 8 + (c >> 1);
    dst[0] = packh2(val.x, val.y);
    dst[4] = packh2(val.z, val.w);
}

// ---- FP16 projection GEMM, 128x128 tile, 3-stage pipeline, k-chunk 64 ------
// stage = A(128x32 u32) + B(128x32 u32) = 8192 u32 = 32 KB; 3 stages = 96 KB.
// Layout per stage: [A chunk0 | B chunk0 | A chunk1 | B chunk1] (4 x 2048 u32).
__global__ __launch_bounds__(256) void proj_gemm_tc(
    const float* __restrict__ bq, const float* __restrict__ bk,
    const float* __restrict__ bv, const float* __restrict__ bg,
    const float* __restrict__ cosb, const float* __restrict__ sinb)
{
    extern __shared__ uint32_t dsm[];
    const int z = blockIdx.z;
    const uint32_t* Ag  = g_H + ((z == 3) ? 0 : (size_t)z * SEG1);
    const uint32_t* Wgp = g_H + SEGW + (size_t)z * WS;
    const float* bias = (z == 0) ? bq : ((z == 1) ? bk : ((z == 2) ? bv : bg));

    const int m0 = blockIdx.y * 128;
    const int n0 = blockIdx.x * 128;

    const int tid  = threadIdx.x;
    const int warp = tid >> 5;
    const int lane = tid & 31;
    const int q    = lane >> 2;
    const int tq   = lane & 3;
    const int warpM0 = (warp >> 1) * 32;
    const int warpN0 = (warp & 1) * 64;

    float acc[2][8][4];
    #pragma unroll
    for (int mt = 0; mt < 2; mt++)
        #pragma unroll
        for (int nt = 0; nt < 8; nt++)
            #pragma unroll
            for (int e = 0; e < 4; e++) acc[mt][nt][e] = 0.f;

    // stage it copies k-chunks 2*it and 2*it+1
    auto copyt = [&](int it, int s) {
        uint32_t base = (uint32_t)__cvta_generic_to_shared(dsm + s * 8192);
        #pragma unroll
        for (int c = 0; c < 2; c++) {
            int kc = it * 2 + c;
            uint32_t sA = base + c * 16384;
            uint32_t sB = sA + 8192;
            #pragma unroll
            for (int i = 0; i < 2; i++) {
                int idx = tid + i * 256;
                int m = idx >> 2, u = idx & 3;
                cpa16(sA + (m * 16 + u * 4) * 4,
                      (const uint4*)(Ag + (size_t)(m0 + m) * 512 + kc * 16) + u);
                cpa16(sB + (m * 16 + u * 4) * 4,
                      (const uint4*)(Wgp + (size_t)(n0 + m) * 512 + kc * 16) + u);
            }
        }
    };

    copyt(0, 0); CPA_COMMIT();
    copyt(1, 1); CPA_COMMIT();

    int buf = 0;
    for (int it = 0; it < 16; it++) {
        CPA_WAIT1();
        __syncthreads();
        if (it + 2 < 16) {
            int s = buf + 2; if (s >= 3) s -= 3;
            copyt(it + 2, s);
        }
        CPA_COMMIT();

        #pragma unroll
        for (int c = 0; c < 2; c++) {
            const uint32_t* As = dsm + buf * 8192 + c * 4096;
            const uint32_t* Bs = As + 2048;

            uint4 Ar[2], Ar8[2];
            #pragma unroll
            for (int mt = 0; mt < 2; mt++) {
                int r = warpM0 + mt * 16 + q;
                Ar[mt]  = *(const uint4*)&As[r * 16 + tq * 4];
                Ar8[mt] = *(const uint4*)&As[(r + 8) * 16 + tq * 4];
            }
            #pragma unroll
            for (int nt = 0; nt < 8; nt++) {
                int n = warpN0 + nt * 8 + q;
                uint4 Bv = *(const uint4*)&Bs[n * 16 + tq * 4];
                #pragma unroll
                for (int mt = 0; mt < 2; mt++) {
                    mma_f16(acc[mt][nt], Ar[mt].x, Ar8[mt].x, Ar[mt].y, Ar8[mt].y, Bv.x, Bv.y);
                    mma_f16(acc[mt][nt], Ar[mt].z, Ar8[mt].z, Ar[mt].w, Ar8[mt].w, Bv.z, Bv.w);
                }
            }
        }
        if (++buf == 3) buf = 0;
    }

    const int h = (n0 + warpN0) >> 6;
    const int nb = n0 + warpN0;
    const float CsQ = 0.18033688011112158f;   // 0.125 * log2(e), folded into Q
    #pragma unroll
    for (int mt = 0; mt < 2; mt++)
        #pragma unroll
        for (int nt = 0; nt < 4; nt++) {
            int cl0 = nt * 8 + tq * 2;   // 0..31 within head
            float y1[4], y2[4];
            #pragma unroll
            for (int e = 0; e < 4; e++) {
                int row = m0 + warpM0 + mt * 16 + q + ((e >> 1) ? 8 : 0);
                int l = row & (Lc - 1);
                int cl = cl0 + (e & 1);
                float x1 = acc[mt][nt][e]     + bias[nb + cl];
                float x2 = acc[mt][nt + 4][e] + bias[nb + cl + 32];
                if (z <= 1) {
                    float c1 = cosb[l * 64 + cl],      s1 = sinb[l * 64 + cl];
                    float c2 = cosb[l * 64 + cl + 32], s2 = sinb[l * 64 + cl + 32];
                    y1[e] = x1 * c1 - x2 * s1;
                    y2[e] = x2 * c2 + x1 * s2;
                    if (z == 0) { y1[e] *= CsQ; y2[e] *= CsQ; }
                } else { y1[e] = x1; y2[e] = x2; }
            }
            #pragma unroll
            for (int h2 = 0; h2 < 2; h2++) {
                int row = m0 + warpM0 + mt * 16 + q + h2 * 8;
                int b = row >> 11, l = row & (Lc - 1);
                if (z == 3) {
                    size_t rb = (size_t)row * Dc + nb;
                    g_G[rb + cl0]      = 1.f / (1.f + __expf(-y1[2*h2]));
                    g_G[rb + cl0 + 1]  = 1.f / (1.f + __expf(-y1[2*h2+1]));
                    g_G[rb + cl0 + 32] = 1.f / (1.f + __expf(-y2[2*h2]));
                    g_G[rb + cl0 + 33] = 1.f / (1.f + __expf(-y2[2*h2+1]));
                } else if (z == 2) {
                    int kt2 = l >> 6, tk = l & 63, jp = tk >> 1;
                    int hoff = ((jp & 3) * 8 + (jp >> 2)) * 2 + (tk & 1);
                    __half* vrow = g_Vth + (((size_t)(b * Hc + h) * 32 + kt2) * 64) * 64;
                    vrow[(size_t)(cl0)      * 64 + hoff] = __float2half(y1[2*h2]);
                    vrow[(size_t)(cl0 + 1)  * 64 + hoff] = __float2half(y1[2*h2+1]);
                    vrow[(size_t)(cl0 + 32) * 64 + hoff] = __float2half(y2[2*h2]);
                    vrow[(size_t)(cl0 + 33) * 64 + hoff] = __float2half(y2[2*h2+1]);
                } else {
                    size_t drow = ((size_t)(b * Hc + h) * Lc + l) * 32;
                    uint32_t p1 = packh2(y1[2*h2], y1[2*h2+1]);
                    uint32_t p2 = packh2(y2[2*h2], y2[2*h2+1]);
                    int j1 = cl0 >> 1;
                    if (z == 0) {
                        g_Qh[drow + j1]      = p1;
                        g_Qh[drow + j1 + 16] = p2;
                    } else {
                        int pos = (j1 & 3) * 8 + (j1 >> 2);
                        g_Kh[drow + pos]     = p1;
                        g_Kh[drow + pos + 4] = p2;
                    }
                }
            }
        }
}

// ---- FP16 flash attention: 3-stage pipeline, fixed-shift softmax (R14) -----
__global__ __launch_bounds__(256, 2) void attn_tc_kernel()
{
    extern __shared__ uint32_t dsm[];
    const int qt  = blockIdx.x;
    const int bh  = blockIdx.y;
    const int b   = bh >> 4;
    const int h   = bh & 15;
    const int tid = threadIdx.x;
    const int warp = tid >> 5;
    const int lane = tid & 31;
    const int q    = lane >> 2;
    const int tq   = lane & 3;

    const uint32_t* Qg32 = g_Qh + ((size_t)bh * Lc + qt * 128 + warp * 16 + q) * 32;
    uint32_t qf[4][4];
    #pragma unroll
    for (int s = 0; s < 4; s++) {
        qf[s][0] = Qg32[8*s + tq];
        qf[s][1] = Qg32[256 + 8*s + tq];
        qf[s][2] = Qg32[8*s + tq + 4];
        qf[s][3] = Qg32[256 + 8*s + tq + 4];
    }

    float O[8][4];
    #pragma unroll
    for (int nt = 0; nt < 8; nt++)
        #pragma unroll
        for (int e = 0; e < 4; e++) O[nt][e] = 0.f;
    float lacc[4] = {0.f, 0.f, 0.f, 0.f};
    const uint32_t ONES = 0x3C003C00u;

    auto issue = [&](int kt, int s) {
        uint32_t base = (uint32_t)__cvta_generic_to_shared(dsm + s * 4640);
        const uint4* Kg4 = (const uint4*)(g_Kh + ((size_t)bh * Lc + kt * 64) * 32);
        const uint4* Vg4 = (const uint4*)g_Vth + ((size_t)(bh * 32 + kt)) * 512;
        #pragma unroll
        for (int i = 0; i < 2; i++) {
            int f = tid + i * 256;
            int n = f >> 3, u = f & 7;
            cpa16(base + (n * 36 + u * 4) * 4, Kg4 + n * 8 + u);
            cpa16(base + (2304 + n * 36 + u * 4) * 4, Vg4 + n * 8 + u);
        }
        if (tid < 8)
            cpa16(base + 4608 * 4 + tid * 16, g_mkh + b * 1024 + kt * 32 + tid * 4);
    };

    issue(0, 0); CPA_COMMIT();
    issue(1, 1); CPA_COMMIT();

    int buf = 0;
    for (int kt = 0; kt < 32; kt++) {
        CPA_WAIT1();
        __syncthreads();
        if (kt + 2 < 32) {
            int s = buf + 2; if (s >= 3) s -= 3;
            issue(kt + 2, s);
        }
        CPA_COMMIT();

        const uint32_t* Ks = dsm + buf * 4640;
        const uint32_t* Vs = Ks + 2304;
        const uint32_t* mk = Ks + 4608;

        float S[8][4];
        #pragma unroll
        for (int nt = 0; nt < 8; nt++)
            #pragma unroll
            for (int e = 0; e < 4; e++) S[nt][e] = 0.f;
        #pragma unroll
        for (int nt = 0; nt < 8; nt++) {
            const uint32_t* kr = &Ks[(nt * 8 + q) * 36 + tq * 8];
            uint4 B1 = *(const uint4*)kr;
            uint4 B2 = *(const uint4*)(kr + 4);
            mma_f16(S[nt], qf[0][0], qf[0][1], qf[0][2], qf[0][3], B1.x, B1.y);
            mma_f16(S[nt], qf[1][0], qf[1][1], qf[1][2], qf[1][3], B1.z, B1.w);
            mma_f16(S[nt], qf[2][0], qf[2][1], qf[2][2], qf[2][3], B2.x, B2.y);
            mma_f16(S[nt], qf[3][0], qf[3][1], qf[3][2], qf[3][3], B2.z, B2.w);
        }

        uint32_t pp[8][2];
        #pragma unroll
        for (int nt = 0; nt < 8; nt++) {
            uint32_t mq = mk[nt * 4 + tq];
            pp[nt][0] = ex2h2(hadd2u(packh2(S[nt][0], S[nt][1]), mq));
            pp[nt][1] = ex2h2(hadd2u(packh2(S[nt][2], S[nt][3]), mq));
        }

        mma_f16(lacc, pp[0][0], pp[0][1], pp[1][0], pp[1][1], ONES, ONES);
        mma_f16(lacc, pp[2][0], pp[2][1], pp[3][0], pp[3][1], ONES, ONES);
        mma_f16(lacc, pp[4][0], pp[4][1], pp[5][0], pp[5][1], ONES, ONES);
        mma_f16(lacc, pp[6][0], pp[6][1], pp[7][0], pp[7][1], ONES, ONES);

        #pragma unroll
        for (int nt = 0; nt < 8; nt++) {
            const uint32_t* vr = &Vs[(nt * 8 + q) * 36 + tq * 8];
            uint4 V1 = *(const uint4*)vr;
            uint4 V2 = *(const uint4*)(vr + 4);
            mma_f16(O[nt], pp[0][0], pp[0][1], pp[1][0], pp[1][1], V1.x, V1.y);
            mma_f16(O[nt], pp[2][0], pp[2][1], pp[3][0], pp[3][1], V1.z, V1.w);
            mma_f16(O[nt], pp[4][0], pp[4][1], pp[5][0], pp[5][1], V2.x, V2.y);
            mma_f16(O[nt], pp[6][0], pp[6][1], pp[7][0], pp[7][1], V2.z, V2.w);
        }
        if (++buf == 3) buf = 0;
    }

    float l0r = lacc[0], l1r = lacc[2];
    float inv0 = (l0r > 0.f) ? (1.f / l0r) : 0.f;
    float inv1 = (l1r > 0.f) ? (1.f / l1r) : 0.f;
    int r0 = qt * 128 + warp * 16 + q;
    size_t tok0 = (size_t)b * Lc + r0;
    size_t tok1 = tok0 + 8;
    #pragma unroll
    for (int nt = 0; nt < 8; nt++) {
        int n = h * 64 + nt * 8 + tq * 2;
        float o0 = O[nt][0] * inv0 * g_G[tok0 * Dc + n];
        float o1 = O[nt][1] * inv0 * g_G[tok0 * Dc + n + 1];
        float o2 = O[nt][2] * inv1 * g_G[tok1 * Dc + n];
        float o3 = O[nt][3] * inv1 * g_G[tok1 * Dc + n + 1];
        int J = n >> 1, chnk = J >> 4, jj = J & 15;
        int pos = (jj >> 2) + (jj & 1) * 4 + ((jj >> 1) & 1) * 8;
        g_AOh[tok0 * 512 + chnk * 16 + pos] = packh2(o0, o1);
        g_AOh[tok1 * 512 + chnk * 16 + pos] = packh2(o2, o3);
    }
}

// ---- FP16 output projection GEMM, 128x128 tile, k-chunk 64 -----------------
__global__ __launch_bounds__(256) void out_gemm_tc(
    const float* __restrict__ bo, float* __restrict__ out)
{
    extern __shared__ uint32_t dsm[];
    const uint32_t* Ag  = g_AOh;
    const uint32_t* Wgp = g_H + SEGW + (size_t)4 * WS;

    const int m0 = blockIdx.y * 128;
    const int n0 = blockIdx.x * 128;

    const int tid  = threadIdx.x;
    const int warp = tid >> 5;
    const int lane = tid & 31;
    const int q    = lane >> 2;
    const int tq   = lane & 3;
    const int warpM0 = (warp >> 1) * 32;
    const int warpN0 = (warp & 1) * 64;

    float acc[2][8][4];
    #pragma unroll
    for (int mt = 0; mt < 2; mt++)
        #pragma unroll
        for (int nt = 0; nt < 8; nt++)
            #pragma unroll
            for (int e = 0; e < 4; e++) acc[mt][nt][e] = 0.f;

    auto copyt = [&](int it, int s) {
        uint32_t base = (uint32_t)__cvta_generic_to_shared(dsm + s * 8192);
        #pragma unroll
        for (int c = 0; c < 2; c++) {
            int kc = it * 2 + c;
            uint32_t sA = base + c * 16384;
            uint32_t sB = sA + 8192;
            #pragma unroll
            for (int i = 0; i < 2; i++) {
                int idx = tid + i * 256;
                int m = idx >> 2, u = idx & 3;
                cpa16(sA + (m * 16 + u * 4) * 4,
                      (const uint4*)(Ag + (size_t)(m0 + m) * 512 + kc * 16) + u);
                cpa16(sB + (m * 16 + u * 4) * 4,
                      (const uint4*)(Wgp + (size_t)(n0 + m) * 512 + kc * 16) + u);
            }
        }
    };

    copyt(0, 0); CPA_COMMIT();
    copyt(1, 1); CPA_COMMIT();

    int buf = 0;
    for (int it = 0; it < 16; it++) {
        CPA_WAIT1();
        __syncthreads();
        if (it + 2 < 16) {
            int s = buf + 2; if (s >= 3) s -= 3;
            copyt(it + 2, s);
        }
        CPA_COMMIT();

        #pragma unroll
        for (int c = 0; c < 2; c++) {
            const uint32_t* As = dsm + buf * 8192 + c * 4096;
            const uint32_t* Bs = As + 2048;

            uint4 Ar[2], Ar8[2];
            #pragma unroll
            for (int mt = 0; mt < 2; mt++) {
                int r = warpM0 + mt * 16 + q;
                Ar[mt]  = *(const uint4*)&As[r * 16 + tq * 4];
                Ar8[mt] = *(const uint4*)&As[(r + 8) * 16 + tq * 4];
            }
            #pragma unroll
            for (int nt = 0; nt < 8; nt++) {
                int n = warpN0 + nt * 8 + q;
                uint4 Bv = *(const uint4*)&Bs[n * 16 + tq * 4];
                #pragma unroll
                for (int mt = 0; mt < 2; mt++) {
                    mma_f16(acc[mt][nt], Ar[mt].x, Ar8[mt].x, Ar[mt].y, Ar8[mt].y, Bv.x, Bv.y);
                    mma_f16(acc[mt][nt], Ar[mt].z, Ar8[mt].z, Ar[mt].w, Ar8[mt].w, Bv.z, Bv.w);
                }
            }
        }
        if (++buf == 3) buf = 0;
    }

    #pragma unroll
    for (int mt = 0; mt < 2; mt++)
        #pragma unroll
        for (int nt = 0; nt < 8; nt++)
            #pragma unroll
            for (int e = 0; e < 4; e++) {
                int row = m0 + warpM0 + mt * 16 + q + ((e >> 1) ? 8 : 0);
                int col = n0 + warpN0 + nt * 8 + tq * 2 + (e & 1);
                out[(size_t)row * Dc + col] = acc[mt][nt][e] + bo[col];
            }
}

// ---- launch -----------------------------------------------------------------
#define GEMM_SMEM 98304
#define ATTN_SMEM 55680

extern "C" void kernel_launch(void* const* d_in, const int* in_sizes, int n_in,
                              void* d_out, int out_size)
{
    const float* query   = (const float*)d_in[0];
    const float* key_in  = (const float*)d_in[1];
    const float* value   = (const float*)d_in[2];
    const unsigned char* maskraw = (const unsigned char*)d_in[3];
    const float* rope_cos = (const float*)d_in[4];
    const float* rope_sin = (const float*)d_in[5];
    const float* Wq = (const float*)d_in[6];
    const float* bq = (const float*)d_in[7];
    const float* Wk = (const float*)d_in[8];
    const float* bk = (const float*)d_in[9];
    const float* Wv = (const float*)d_in[10];
    const float* bv = (const float*)d_in[11];
    const float* Wg = (const float*)d_in[12];
    const float* bg = (const float*)d_in[13];
    const float* Wo = (const float*)d_in[14];
    const float* bo = (const float*)d_in[15];
    float* out = (float*)d_out;

    (void)in_sizes; (void)n_in; (void)out_size;

    cudaFuncSetAttribute(proj_gemm_tc,
                         cudaFuncAttributeMaxDynamicSharedMemorySize, GEMM_SMEM);
    cudaFuncSetAttribute(attn_tc_kernel,
                         cudaFuncAttributeMaxDynamicSharedMemorySize, ATTN_SMEM);
    cudaFuncSetAttribute(out_gemm_tc,
                         cudaFuncAttributeMaxDynamicSharedMemorySize, GEMM_SMEM);

    mask_decode_kernel<<<1, 1024>>>(maskraw);
    prep_half<<<dim3(4096, 1, 8), 256>>>(query, key_in, value, Wq, Wk, Wv, Wg, Wo);
    proj_gemm_tc<<<dim3(8, 32, 4), 256, GEMM_SMEM>>>(bq, bk, bv, bg, rope_cos, rope_sin);
    attn_tc_kernel<<<dim3(16, 32), 256, ATTN_SMEM>>>();
    out_gemm_tc<<<dim3(8, 32), 256, GEMM_SMEM>>>(bo, out);
}

// round 17
// speedup vs baseline: 2.5170x; 1.0002x over previous
#include <cuda_runtime.h>
#include <cuda_fp16.h>
#include <stdint.h>
#include <math.h>

#define Bc   2
#define Lc   2048
#define Dc   1024
#define Hc   16
#define NT   4096
#define BHc  32

#define SEG1 (4096*512)
#define SEGW (3*4096*512)
#define WS   (1024*512)
__device__ uint32_t g_H[(size_t)(3*4096 + 5*1024)*512];
__device__ uint32_t g_Qh[(size_t)BHc*Lc*32];     // plain half-pair rows of 32 (pre-scaled by Cs)
__device__ uint32_t g_Kh[(size_t)BHc*Lc*32];     // attn-permuted rows of 32
__device__ __half   g_Vth[(size_t)BHc*32*64*64]; // attn-smem-image half V
__device__ float    g_G [(size_t)NT*Dc];
__device__ uint32_t g_AOh[(size_t)NT*512];       // chunk-permuted half
__device__ int      g_mask[NT];
__device__ uint32_t g_mkh[NT/2];                 // half2 additive mask (-4 live / -3e4 masked)

__device__ __forceinline__ uint32_t packh2(float a, float b) {
    __half2 h = __floats2half2_rn(a, b);
    return *reinterpret_cast<uint32_t*>(&h);
}
__device__ __forceinline__ uint32_t hadd2u(uint32_t a, uint32_t b) {
    uint32_t r;
    asm("add.f16x2 %0, %1, %2;" : "=r"(r) : "r"(a), "r"(b));
    return r;
}
__device__ __forceinline__ uint32_t ex2h2(uint32_t a) {
    uint32_t r;
    asm("ex2.approx.f16x2 %0, %1;" : "=r"(r) : "r"(a));
    return r;
}
__device__ __forceinline__ void mma_f16(
    float* d, uint32_t a0, uint32_t a1, uint32_t a2, uint32_t a3,
    uint32_t b0, uint32_t b1)
{
    asm volatile(
        "mma.sync.aligned.m16n8k16.row.col.f32.f16.f16.f32 "
        "{%0,%1,%2,%3}, {%4,%5,%6,%7}, {%8,%9}, {%0,%1,%2,%3};\n"
        : "+f"(d[0]), "+f"(d[1]), "+f"(d[2]), "+f"(d[3])
        : "r"(a0), "r"(a1), "r"(a2), "r"(a3), "r"(b0), "r"(b1));
}
__device__ __forceinline__ void cpa16(uint32_t dst, const void* src) {
    asm volatile("cp.async.ca.shared.global [%0], [%1], 16;"
                 :: "r"(dst), "l"(src) : "memory");
}
#define CPA_COMMIT() asm volatile("cp.async.commit_group;" ::: "memory")
#define CPA_WAIT1()  asm volatile("cp.async.wait_group 1;" ::: "memory")

// ---- prep: fp32 -> chunk-permuted half; mask decode folded into one block --
__global__ void prep_half(
    const float* __restrict__ q, const float* __restrict__ k,
    const float* __restrict__ v,
    const float* __restrict__ wq, const float* __restrict__ wk,
    const float* __restrict__ wv, const float* __restrict__ wg,
    const float* __restrict__ wo,
    const unsigned char* __restrict__ maskraw)
{
    int z = blockIdx.z, row = blockIdx.x, t = threadIdx.x;
    const float* src; size_t off;
    if (z < 3) {
        src = (z == 0) ? q : ((z == 1) ? k : v);
        off = (size_t)z * SEG1;
    } else {
        if (row >= 1024) {
            // mask decode rides in one otherwise-idle block
            if (z == 3 && row == 1100) {
                __shared__ int cnt[4];
                if (t < 4) cnt[t] = 0;
                __syncthreads();
                for (int i = t; i < NT; i += 256)
                    if (maskraw[i]) atomicAdd(&cnt[i & 3], 1);
                __syncthreads();
                int c0 = cnt[0], c1 = cnt[1], c2 = cnt[2], c3 = cnt[3];
                int mode;
                if (c0 > 0 && c1 == 0 && c2 == 0 && c3 == 0)       mode = 1;
                else if ((c2 > 0 || c3 > 0) && c0 == 0 && c1 == 0) mode = 2;
                else                                               mode = 0;
                for (int i = t; i < NT; i += 256) {
                    int mv;
                    if (mode == 0)      mv = (maskraw[i] != 0);
                    else if (mode == 1) mv = (((const int*)maskraw)[i] != 0);
                    else                mv = (((const float*)maskraw)[i] != 0.0f);
                    g_mask[i] = mv;
                }
                __syncthreads();
                for (int i = t; i < NT / 2; i += 256) {
                    float m0 = g_mask[2*i]     ? -30000.f : -4.0f;
                    float m1 = g_mask[2*i + 1] ? -30000.f : -4.0f;
                    g_mkh[i] = packh2(m0, m1);
                }
            }
            return;
        }
        src = (z == 3) ? wq : ((z == 4) ? wk : ((z == 5) ? wv : ((z == 6) ? wg : wo)));
        off = (size_t)SEGW + (size_t)(z - 3) * WS;
    }
    float4 val = ((const float4*)src)[(size_t)row * 256 + t];
    int ch = t >> 3, c = t & 7;
    uint32_t* dst = g_H + off + (size_t)row * 512 + ch * 16 + (c & 1) * 8 + (c >> 1);
    dst[0] = packh2(val.x, val.y);
    dst[4] = packh2(val.z, val.w);
}

// ---- FP16 projection GEMM, 128x128 tile, 3-stage pipeline, k-chunk 64 ------
__global__ __launch_bounds__(256) void proj_gemm_tc(
    const float* __restrict__ bq, const float* __restrict__ bk,
    const float* __restrict__ bv, const float* __restrict__ bg,
    const float* __restrict__ cosb, const float* __restrict__ sinb)
{
    extern __shared__ uint32_t dsm[];
    const int z = blockIdx.z;
    const uint32_t* Ag  = g_H + ((z == 3) ? 0 : (size_t)z * SEG1);
    const uint32_t* Wgp = g_H + SEGW + (size_t)z * WS;
    const float* bias = (z == 0) ? bq : ((z == 1) ? bk : ((z == 2) ? bv : bg));

    const int m0 = blockIdx.y * 128;
    const int n0 = blockIdx.x * 128;

    const int tid  = threadIdx.x;
    const int warp = tid >> 5;
    const int lane = tid & 31;
    const int q    = lane >> 2;
    const int tq   = lane & 3;
    const int warpM0 = (warp >> 1) * 32;
    const int warpN0 = (warp & 1) * 64;

    float acc[2][8][4];
    #pragma unroll
    for (int mt = 0; mt < 2; mt++)
        #pragma unroll
        for (int nt = 0; nt < 8; nt++)
            #pragma unroll
            for (int e = 0; e < 4; e++) acc[mt][nt][e] = 0.f;

    auto copyt = [&](int it, int s) {
        uint32_t base = (uint32_t)__cvta_generic_to_shared(dsm + s * 8192);
        #pragma unroll
        for (int c = 0; c < 2; c++) {
            int kc = it * 2 + c;
            uint32_t sA = base + c * 16384;
            uint32_t sB = sA + 8192;
            #pragma unroll
            for (int i = 0; i < 2; i++) {
                int idx = tid + i * 256;
                int m = idx >> 2, u = idx & 3;
                cpa16(sA + (m * 16 + u * 4) * 4,
                      (const uint4*)(Ag + (size_t)(m0 + m) * 512 + kc * 16) + u);
                cpa16(sB + (m * 16 + u * 4) * 4,
                      (const uint4*)(Wgp + (size_t)(n0 + m) * 512 + kc * 16) + u);
            }
        }
    };

    copyt(0, 0); CPA_COMMIT();
    copyt(1, 1); CPA_COMMIT();

    int buf = 0;
    for (int it = 0; it < 16; it++) {
        CPA_WAIT1();
        __syncthreads();
        if (it + 2 < 16) {
            int s = buf + 2; if (s >= 3) s -= 3;
            copyt(it + 2, s);
        }
        CPA_COMMIT();

        #pragma unroll
        for (int c = 0; c < 2; c++) {
            const uint32_t* As = dsm + buf * 8192 + c * 4096;
            const uint32_t* Bs = As + 2048;

            uint4 Ar[2], Ar8[2];
            #pragma unroll
            for (int mt = 0; mt < 2; mt++) {
                int r = warpM0 + mt * 16 + q;
                Ar[mt]  = *(const uint4*)&As[r * 16 + tq * 4];
                Ar8[mt] = *(const uint4*)&As[(r + 8) * 16 + tq * 4];
            }
            #pragma unroll
            for (int nt = 0; nt < 8; nt++) {
                int n = warpN0 + nt * 8 + q;
                uint4 Bv = *(const uint4*)&Bs[n * 16 + tq * 4];
                #pragma unroll
                for (int mt = 0; mt < 2; mt++) {
                    mma_f16(acc[mt][nt], Ar[mt].x, Ar8[mt].x, Ar[mt].y, Ar8[mt].y, Bv.x, Bv.y);
                    mma_f16(acc[mt][nt], Ar[mt].z, Ar8[mt].z, Ar[mt].w, Ar8[mt].w, Bv.z, Bv.w);
                }
            }
        }
        if (++buf == 3) buf = 0;
    }

    const int h = (n0 + warpN0) >> 6;
    const int nb = n0 + warpN0;
    const float CsQ = 0.18033688011112158f;   // 0.125 * log2(e), folded into Q
    #pragma unroll
    for (int mt = 0; mt < 2; mt++)
        #pragma unroll
        for (int nt = 0; nt < 4; nt++) {
            int cl0 = nt * 8 + tq * 2;   // 0..31 within head
            float y1[4], y2[4];
            #pragma unroll
            for (int e = 0; e < 4; e++) {
                int row = m0 + warpM0 + mt * 16 + q + ((e >> 1) ? 8 : 0);
                int l = row & (Lc - 1);
                int cl = cl0 + (e & 1);
                float x1 = acc[mt][nt][e]     + bias[nb + cl];
                float x2 = acc[mt][nt + 4][e] + bias[nb + cl + 32];
                if (z <= 1) {
                    float c1 = cosb[l * 64 + cl],      s1 = sinb[l * 64 + cl];
                    float c2 = cosb[l * 64 + cl + 32], s2 = sinb[l * 64 + cl + 32];
                    y1[e] = x1 * c1 - x2 * s1;
                    y2[e] = x2 * c2 + x1 * s2;
                    if (z == 0) { y1[e] *= CsQ; y2[e] *= CsQ; }
                } else { y1[e] = x1; y2[e] = x2; }
            }
            #pragma unroll
            for (int h2 = 0; h2 < 2; h2++) {
                int row = m0 + warpM0 + mt * 16 + q + h2 * 8;
                int b = row >> 11, l = row & (Lc - 1);
                if (z == 3) {
                    size_t rb = (size_t)row * Dc + nb;
                    float2 ga = make_float2(1.f / (1.f + __expf(-y1[2*h2])),
                                            1.f / (1.f + __expf(-y1[2*h2+1])));
                    float2 gb = make_float2(1.f / (1.f + __expf(-y2[2*h2])),
                                            1.f / (1.f + __expf(-y2[2*h2+1])));
                    *(float2*)&g_G[rb + cl0]      = ga;
                    *(float2*)&g_G[rb + cl0 + 32] = gb;
                } else if (z == 2) {
                    int kt2 = l >> 6, tk = l & 63, jp = tk >> 1;
                    int hoff = ((jp & 3) * 8 + (jp >> 2)) * 2 + (tk & 1);
                    __half* vrow = g_Vth + (((size_t)(b * Hc + h) * 32 + kt2) * 64) * 64;
                    vrow[(size_t)(cl0)      * 64 + hoff] = __float2half(y1[2*h2]);
                    vrow[(size_t)(cl0 + 1)  * 64 + hoff] = __float2half(y1[2*h2+1]);
                    vrow[(size_t)(cl0 + 32) * 64 + hoff] = __float2half(y2[2*h2]);
                    vrow[(size_t)(cl0 + 33) * 64 + hoff] = __float2half(y2[2*h2+1]);
                } else {
                    size_t drow = ((size_t)(b * Hc + h) * Lc + l) * 32;
                    uint32_t p1 = packh2(y1[2*h2], y1[2*h2+1]);
                    uint32_t p2 = packh2(y2[2*h2], y2[2*h2+1]);
                    int j1 = cl0 >> 1;
                    if (z == 0) {
                        g_Qh[drow + j1]      = p1;
                        g_Qh[drow + j1 + 16] = p2;
                    } else {
                        int pos = (j1 & 3) * 8 + (j1 >> 2);
                        g_Kh[drow + pos]     = p1;
                        g_Kh[drow + pos + 4] = p2;
                    }
                }
            }
        }
}

// ---- FP16 flash attention: 3-stage pipeline, fixed-shift softmax -----------
__global__ __launch_bounds__(256, 2) void attn_tc_kernel()
{
    extern __shared__ uint32_t dsm[];
    const int qt  = blockIdx.x;
    const int bh  = blockIdx.y;
    const int b   = bh >> 4;
    const int h   = bh & 15;
    const int tid = threadIdx.x;
    const int warp = tid >> 5;
    const int lane = tid & 31;
    const int q    = lane >> 2;
    const int tq   = lane & 3;

    const uint32_t* Qg32 = g_Qh + ((size_t)bh * Lc + qt * 128 + warp * 16 + q) * 32;
    uint32_t qf[4][4];
    #pragma unroll
    for (int s = 0; s < 4; s++) {
        qf[s][0] = Qg32[8*s + tq];
        qf[s][1] = Qg32[256 + 8*s + tq];
        qf[s][2] = Qg32[8*s + tq + 4];
        qf[s][3] = Qg32[256 + 8*s + tq + 4];
    }

    float O[8][4];
    #pragma unroll
    for (int nt = 0; nt < 8; nt++)
        #pragma unroll
        for (int e = 0; e < 4; e++) O[nt][e] = 0.f;
    float lacc[4] = {0.f, 0.f, 0.f, 0.f};
    const uint32_t ONES = 0x3C003C00u;

    auto issue = [&](int kt, int s) {
        uint32_t base = (uint32_t)__cvta_generic_to_shared(dsm + s * 4640);
        const uint4* Kg4 = (const uint4*)(g_Kh + ((size_t)bh * Lc + kt * 64) * 32);
        const uint4* Vg4 = (const uint4*)g_Vth + ((size_t)(bh * 32 + kt)) * 512;
        #pragma unroll
        for (int i = 0; i < 2; i++) {
            int f = tid + i * 256;
            int n = f >> 3, u = f & 7;
            cpa16(base + (n * 36 + u * 4) * 4, Kg4 + n * 8 + u);
            cpa16(base + (2304 + n * 36 + u * 4) * 4, Vg4 + n * 8 + u);
        }
        if (tid < 8)
            cpa16(base + 4608 * 4 + tid * 16, g_mkh + b * 1024 + kt * 32 + tid * 4);
    };

    issue(0, 0); CPA_COMMIT();
    issue(1, 1); CPA_COMMIT();

    int buf = 0;
    for (int kt = 0; kt < 32; kt++) {
        CPA_WAIT1();
        __syncthreads();
        if (kt + 2 < 32) {
            int s = buf + 2; if (s >= 3) s -= 3;
            issue(kt + 2, s);
        }
        CPA_COMMIT();

        const uint32_t* Ks = dsm + buf * 4640;
        const uint32_t* Vs = Ks + 2304;
        const uint32_t* mk = Ks + 4608;

        float S[8][4];
        #pragma unroll
        for (int nt = 0; nt < 8; nt++)
            #pragma unroll
            for (int e = 0; e < 4; e++) S[nt][e] = 0.f;
        #pragma unroll
        for (int nt = 0; nt < 8; nt++) {
            const uint32_t* kr = &Ks[(nt * 8 + q) * 36 + tq * 8];
            uint4 B1 = *(const uint4*)kr;
            uint4 B2 = *(const uint4*)(kr + 4);
            mma_f16(S[nt], qf[0][0], qf[0][1], qf[0][2], qf[0][3], B1.x, B1.y);
            mma_f16(S[nt], qf[1][0], qf[1][1], qf[1][2], qf[1][3], B1.z, B1.w);
            mma_f16(S[nt], qf[2][0], qf[2][1], qf[2][2], qf[2][3], B2.x, B2.y);
            mma_f16(S[nt], qf[3][0], qf[3][1], qf[3][2], qf[3][3], B2.z, B2.w);
        }

        uint32_t pp[8][2];
        #pragma unroll
        for (int nt = 0; nt < 8; nt++) {
            uint32_t mq = mk[nt * 4 + tq];
            pp[nt][0] = ex2h2(hadd2u(packh2(S[nt][0], S[nt][1]), mq));
            pp[nt][1] = ex2h2(hadd2u(packh2(S[nt][2], S[nt][3]), mq));
        }

        mma_f16(lacc, pp[0][0], pp[0][1], pp[1][0], pp[1][1], ONES, ONES);
        mma_f16(lacc, pp[2][0], pp[2][1], pp[3][0], pp[3][1], ONES, ONES);
        mma_f16(lacc, pp[4][0], pp[4][1], pp[5][0], pp[5][1], ONES, ONES);
        mma_f16(lacc, pp[6][0], pp[6][1], pp[7][0], pp[7][1], ONES, ONES);

        #pragma unroll
        for (int nt = 0; nt < 8; nt++) {
            const uint32_t* vr = &Vs[(nt * 8 + q) * 36 + tq * 8];
            uint4 V1 = *(const uint4*)vr;
            uint4 V2 = *(const uint4*)(vr + 4);
            mma_f16(O[nt], pp[0][0], pp[0][1], pp[1][0], pp[1][1], V1.x, V1.y);
            mma_f16(O[nt], pp[2][0], pp[2][1], pp[3][0], pp[3][1], V1.z, V1.w);
            mma_f16(O[nt], pp[4][0], pp[4][1], pp[5][0], pp[5][1], V2.x, V2.y);
            mma_f16(O[nt], pp[6][0], pp[6][1], pp[7][0], pp[7][1], V2.z, V2.w);
        }
        if (++buf == 3) buf = 0;
    }

    float l0r = lacc[0], l1r = lacc[2];
    float inv0 = (l0r > 0.f) ? (1.f / l0r) : 0.f;
    float inv1 = (l1r > 0.f) ? (1.f / l1r) : 0.f;
    int r0 = qt * 128 + warp * 16 + q;
    size_t tok0 = (size_t)b * Lc + r0;
    size_t tok1 = tok0 + 8;
    #pragma unroll
    for (int nt = 0; nt < 8; nt++) {
        int n = h * 64 + nt * 8 + tq * 2;
        float2 ga = *(const float2*)&g_G[tok0 * Dc + n];
        float2 gb = *(const float2*)&g_G[tok1 * Dc + n];
        float o0 = O[nt][0] * inv0 * ga.x;
        float o1 = O[nt][1] * inv0 * ga.y;
        float o2 = O[nt][2] * inv1 * gb.x;
        float o3 = O[nt][3] * inv1 * gb.y;
        int J = n >> 1, chnk = J >> 4, jj = J & 15;
        int pos = (jj >> 2) + (jj & 1) * 4 + ((jj >> 1) & 1) * 8;
        g_AOh[tok0 * 512 + chnk * 16 + pos] = packh2(o0, o1);
        g_AOh[tok1 * 512 + chnk * 16 + pos] = packh2(o2, o3);
    }
}

// ---- FP16 output projection GEMM, 128x128 tile, k-chunk 64 -----------------
__global__ __launch_bounds__(256) void out_gemm_tc(
    const float* __restrict__ bo, float* __restrict__ out)
{
    extern __shared__ uint32_t dsm[];
    const uint32_t* Ag  = g_AOh;
    const uint32_t* Wgp = g_H + SEGW + (size_t)4 * WS;

    const int m0 = blockIdx.y * 128;
    const int n0 = blockIdx.x * 128;

    const int tid  = threadIdx.x;
    const int warp = tid >> 5;
    const int lane = tid & 31;
    const int q    = lane >> 2;
    const int tq   = lane & 3;
    const int warpM0 = (warp >> 1) * 32;
    const int warpN0 = (warp & 1) * 64;

    float acc[2][8][4];
    #pragma unroll
    for (int mt = 0; mt < 2; mt++)
        #pragma unroll
        for (int nt = 0; nt < 8; nt++)
            #pragma unroll
            for (int e = 0; e < 4; e++) acc[mt][nt][e] = 0.f;

    auto copyt = [&](int it, int s) {
        uint32_t base = (uint32_t)__cvta_generic_to_shared(dsm + s * 8192);
        #pragma unroll
        for (int c = 0; c < 2; c++) {
            int kc = it * 2 + c;
            uint32_t sA = base + c * 16384;
            uint32_t sB = sA + 8192;
            #pragma unroll
            for (int i = 0; i < 2; i++) {
                int idx = tid + i * 256;
                int m = idx >> 2, u = idx & 3;
                cpa16(sA + (m * 16 + u * 4) * 4,
                      (const uint4*)(Ag + (size_t)(m0 + m) * 512 + kc * 16) + u);
                cpa16(sB + (m * 16 + u * 4) * 4,
                      (const uint4*)(Wgp + (size_t)(n0 + m) * 512 + kc * 16) + u);
            }
        }
    };

    copyt(0, 0); CPA_COMMIT();
    copyt(1, 1); CPA_COMMIT();

    int buf = 0;
    for (int it = 0; it < 16; it++) {
        CPA_WAIT1();
        __syncthreads();
        if (it + 2 < 16) {
            int s = buf + 2; if (s >= 3) s -= 3;
            copyt(it + 2, s);
        }
        CPA_COMMIT();

        #pragma unroll
        for (int c = 0; c < 2; c++) {
            const uint32_t* As = dsm + buf * 8192 + c * 4096;
            const uint32_t* Bs = As + 2048;

            uint4 Ar[2], Ar8[2];
            #pragma unroll
            for (int mt = 0; mt < 2; mt++) {
                int r = warpM0 + mt * 16 + q;
                Ar[mt]  = *(const uint4*)&As[r * 16 + tq * 4];
                Ar8[mt] = *(const uint4*)&As[(r + 8) * 16 + tq * 4];
            }
            #pragma unroll
            for (int nt = 0; nt < 8; nt++) {
                int n = warpN0 + nt * 8 + q;
                uint4 Bv = *(const uint4*)&Bs[n * 16 + tq * 4];
                #pragma unroll
                for (int mt = 0; mt < 2; mt++) {
                    mma_f16(acc[mt][nt], Ar[mt].x, Ar8[mt].x, Ar[mt].y, Ar8[mt].y, Bv.x, Bv.y);
                    mma_f16(acc[mt][nt], Ar[mt].z, Ar8[mt].z, Ar[mt].w, Ar8[mt].w, Bv.z, Bv.w);
                }
            }
        }
        if (++buf == 3) buf = 0;
    }

    #pragma unroll
    for (int mt = 0; mt < 2; mt++)
        #pragma unroll
        for (int nt = 0; nt < 8; nt++)
            #pragma unroll
            for (int e = 0; e < 4; e++) {
                int row = m0 + warpM0 + mt * 16 + q + ((e >> 1) ? 8 : 0);
                int col = n0 + warpN0 + nt * 8 + tq * 2 + (e & 1);
                out[(size_t)row * Dc + col] = acc[mt][nt][e] + bo[col];
            }
}

// ---- launch -----------------------------------------------------------------
#define GEMM_SMEM 98304
#define ATTN_SMEM 55680

extern "C" void kernel_launch(void* const* d_in, const int* in_sizes, int n_in,
                              void* d_out, int out_size)
{
    const float* query   = (const float*)d_in[0];
    const float* key_in  = (const float*)d_in[1];
    const float* value   = (const float*)d_in[2];
    const unsigned char* maskraw = (const unsigned char*)d_in[3];
    const float* rope_cos = (const float*)d_in[4];
    const float* rope_sin = (const float*)d_in[5];
    const float* Wq = (const float*)d_in[6];
    const float* bq = (const float*)d_in[7];
    const float* Wk = (const float*)d_in[8];
    const float* bk = (const float*)d_in[9];
    const float* Wv = (const float*)d_in[10];
    const float* bv = (const float*)d_in[11];
    const float* Wg = (const float*)d_in[12];
    const float* bg = (const float*)d_in[13];
    const float* Wo = (const float*)d_in[14];
    const float* bo = (const float*)d_in[15];
    float* out = (float*)d_out;

    (void)in_sizes; (void)n_in; (void)out_size;

    cudaFuncSetAttribute(proj_gemm_tc,
                         cudaFuncAttributeMaxDynamicSharedMemorySize, GEMM_SMEM);
    cudaFuncSetAttribute(attn_tc_kernel,
                         cudaFuncAttributeMaxDynamicSharedMemorySize, ATTN_SMEM);
    cudaFuncSetAttribute(out_gemm_tc,
                         cudaFuncAttributeMaxDynamicSharedMemorySize, GEMM_SMEM);

    prep_half<<<dim3(4096, 1, 8), 256>>>(query, key_in, value,
                                         Wq, Wk, Wv, Wg, Wo, maskraw);
    proj_gemm_tc<<<dim3(8, 32, 4), 256, GEMM_SMEM>>>(bq, bk, bv, bg, rope_cos, rope_sin);
    attn_tc_kernel<<<dim3(16, 32), 256, ATTN_SMEM>>>();
    out_gemm_tc<<<dim3(8, 32), 256, GEMM_SMEM>>>(bo, out);
}